// round 12
// baseline (speedup 1.0000x reference)
#include <cuda_runtime.h>
#include <cuda_fp16.h>
#include <math.h>
#include <stdint.h>

#define BB 256
#define HS 512
#define INSZ 512
#define NC 38
#define TT 26
#define CH 512
#define PP 256   /* 8*32 */

// ---------------- scratch (device globals; no allocation allowed) ----------
__device__ __align__(16) __half g_ahT[(size_t)3*BB*320*CH]; // padded input, [kw][b][pos320][ic]
__device__ __align__(16) __half g_bhT[9*CH*CH];             // conv weights [khw][oc][ic]
__device__ __align__(16) __half g_fmh[(size_t)BB*CH*PP];    // conv output fp16, 67MB
__device__ float g_meanH[BB*INSZ];
__device__ float g_bhproj[BB*HS];
__device__ float g_Wq[HS*HS];
__device__ float g_qb[BB*HS];
__device__ float g_badd[4*HS];                         // w2ih @ hlin_b
// fp16 packed loop weights
__device__ __align__(16) __half g_Wq16[HS*HS];
__device__ __align__(16) __half g_hlinT16[HS*HS];      // hlin^T fp16
__device__ __align__(16) __half g_w2ihraw16[4*HS*HS];  // w2ih plain fp16
__device__ __align__(16) __half g_W2pp16[4*HS*HS];     // (w2ih@hlin) plain fp16
__device__ __align__(16) __half g_w1ih16[4*HS*INSZ];   // row 4j+g
__device__ __align__(16) __half g_w1hh16[4*HS*HS];
__device__ __align__(16) __half g_w2ih16[4*HS*HS];     // folded, gate-interleaved
__device__ __align__(16) __half g_w2hh16[4*HS*HS];
__device__ float g_bias1p[4*HS], g_bias2p[4*HS];
__device__ float g_wgp[4*HS*NC];                       // onehot gather, packed rows
// states
__device__ __align__(16) __half g_h1a16[BB*HS], g_h1b16[BB*HS], g_h2a16[BB*HS];
__device__ float g_c1a[BB*HS], g_c1b[BB*HS], g_c2a[BB*HS], g_c2b[BB*HS];
__device__ __align__(16) __half g_hist16[(size_t)TT*BB*HS];
__device__ __align__(16) __half g_ctx16[BB*HS];

// ---------------- fast math ------------------------------------------------
__device__ __forceinline__ float fexp(float x){
    float y; asm("ex2.approx.f32 %0, %1;" : "=f"(y) : "f"(x*1.4426950408889634f)); return y;
}
__device__ __forceinline__ float frcp(float x){
    float y; asm("rcp.approx.f32 %0, %1;" : "=f"(y) : "f"(x)); return y;
}
__device__ __forceinline__ float ftanh(float x){
    float xc = fminf(fmaxf(x, -15.f), 15.f);
    float t = fexp(2.f*xc);
    return (t - 1.f) * frcp(t + 1.f);
}
__device__ __forceinline__ float ftanh_hw(float x){
    float y; asm("tanh.approx.f32 %0, %1;" : "=f"(y) : "f"(x)); return y;
}
__device__ __forceinline__ float fsigm(float x){
    return frcp(1.f + fexp(-x));
}
__device__ __forceinline__ void mma_fp16(float* d, const uint32_t* a, const uint32_t* b){
    asm volatile(
      "mma.sync.aligned.m16n8k16.row.col.f32.f16.f16.f32 "
      "{%0,%1,%2,%3},{%4,%5,%6,%7},{%8,%9},{%0,%1,%2,%3};"
      : "+f"(d[0]),"+f"(d[1]),"+f"(d[2]),"+f"(d[3])
      : "r"(a[0]),"r"(a[1]),"r"(a[2]),"r"(a[3]), "r"(b[0]),"r"(b[1]));
}

// ---------------- prep kernels ------------------------------------------------
__global__ void padT_kernel(const float* __restrict__ in, __half* __restrict__ oh)
{
    __shared__ float s[32][33];
    int blk = blockIdx.x;
    int icb = blk & 15;
    int rr  = (blk >> 4) % 10;
    int b   = blk >> 4; b /= 10;
    int t = threadIdx.x;
    int r = rr - 1;

    if ((unsigned)r < 8u){
        int c = t & 31, icq = t >> 5;
        #pragma unroll
        for (int j=0;j<4;j++){
            int ic = icq + j*8;
            s[ic][c] = in[((size_t)b*CH + icb*32 + ic)*PP + r*32 + c];
        }
    }
    __syncthreads();

    int icl = t & 31, cq = t >> 5;
    #pragma unroll
    for (int j=0;j<4;j++){
        int c = cq + j*8;
        #pragma unroll
        for (int kw=0; kw<3; kw++){
            int cc = c + kw - 1;
            float v = 0.f;
            if ((unsigned)r < 8u && (unsigned)cc < 32u) v = s[icl][cc];
            size_t off = (((size_t)kw*BB + b)*320 + rr*32 + c)*CH + icb*32 + icl;
            oh[off] = __float2half(v);
        }
    }
}

__global__ void wT_kernel(const float* __restrict__ w, __half* __restrict__ oh)
{
    int idx = blockIdx.x*256 + threadIdx.x;
    if (idx >= 9*CH*CH) return;
    int ic = idx & 511;
    int oc = (idx >> 9) & 511;
    int khw = idx >> 18;
    oh[((size_t)khw*CH + oc)*CH + ic] = __float2half(w[((size_t)oc*CH + ic)*9 + khw]);
}

__global__ void cast16_kernel(const float* __restrict__ in, __half* __restrict__ out, int n)
{
    int idx = blockIdx.x*256 + threadIdx.x;
    if (idx < n) out[idx] = __float2half(in[idx]);
}

// out[k][n] = fp16(in[n][k]), 512x512, smem tile transpose
__global__ void transposeT16_kernel(const float* __restrict__ in, __half* __restrict__ out)
{
    __shared__ float s[32][33];
    int bx = blockIdx.x & 15, by = blockIdx.x >> 4;
    int tx = threadIdx.x & 31, ty = threadIdx.x >> 5;
    #pragma unroll
    for (int i=0;i<4;i++){
        int n = bx*32 + ty + i*8;
        s[ty+i*8][tx] = in[(size_t)n*HS + by*32 + tx];
    }
    __syncthreads();
    #pragma unroll
    for (int i=0;i<4;i++){
        int k = by*32 + ty + i*8;
        out[(size_t)k*HS + bx*32 + tx] = __float2half(s[tx][ty+i*8]);
    }
}

// interleave-pack gate weights (fp32 src): out[(4j+g)*512 + k] = w[(g*512+j)*ldw + k]
__global__ void wpack16_kernel(const float* __restrict__ w, int ldw, __half* __restrict__ out)
{
    int idx = blockIdx.x*256 + threadIdx.x;
    if (idx >= 4*HS*512) return;
    int k = idx & 511;
    int row = idx >> 9;
    int j = row >> 2, g = row & 3;
    out[idx] = __float2half(w[(size_t)(g*HS + j)*ldw + k]);
}

// interleave-pack gate weights (fp16 src, ld=512)
__global__ void wpack16h_kernel(const __half* __restrict__ w, __half* __restrict__ out)
{
    int idx = blockIdx.x*256 + threadIdx.x;
    if (idx >= 4*HS*512) return;
    int k = idx & 511;
    int row = idx >> 9;
    int j = row >> 2, g = row & 3;
    out[idx] = w[(size_t)(g*HS + j)*512 + k];
}

__global__ void bpack_kernel(const float* __restrict__ bih, const float* __restrict__ bhh,
                             const float* __restrict__ badd, float* __restrict__ out)
{
    int row = blockIdx.x*256 + threadIdx.x;
    if (row >= 4*HS) return;
    int j = row >> 2, g = row & 3;
    float v = bih[g*HS + j] + bhh[g*HS + j];
    if (badd) v += badd[g*HS + j];
    out[row] = v;
}

__global__ void wgpack_kernel(const float* __restrict__ w, float* __restrict__ out)
{
    int idx = blockIdx.x*256 + threadIdx.x;
    if (idx >= 4*HS*NC) return;
    int c = idx % NC;
    int row = idx / NC;
    int j = row >> 2, g = row & 3;
    out[idx] = w[(size_t)(g*HS + j)*(INSZ+NC) + INSZ + c];
}

// badd[m] = sum_k w2ih[m,k] * hlin_b[k]
__global__ void badd_kernel(const float* __restrict__ w2ih, const float* __restrict__ hlinb,
                            float* __restrict__ out)
{
    int m = blockIdx.x*256 + threadIdx.x;
    if (m >= 4*HS) return;
    const float* wr = w2ih + (size_t)m*HS;
    float s = 0.f;
    #pragma unroll 8
    for (int k=0;k<HS;k++) s += wr[k]*hlinb[k];
    out[m] = s;
}

// ---------------- conv 3x3 SAME via fp16 mma, 4-stage cp.async ---------------
#define CPITCH 20
#define CSTAGE_W (128*CPITCH)

__global__ void __launch_bounds__(256, 2) conv_fp16_kernel(
    const __half* __restrict__ Ag, const __half* __restrict__ Bg,
    const float* __restrict__ bias, __half* __restrict__ out)
{
    extern __shared__ __align__(16) uint32_t sm[];
    uint32_t* Asm = sm;
    uint32_t* Bsm = sm + 4*CSTAGE_W;
    const int b  = blockIdx.z;
    const int m0 = blockIdx.y * 128;
    const int n0 = blockIdx.x * 128;
    const int tid = threadIdx.x;
    const int lane = tid & 31, warp = tid >> 5;
    const int wm = (warp >> 2) * 64;
    const int wn = (warp & 3) * 32;
    const int gid = lane >> 2, tig = lane & 3;

    const int lrow = tid >> 1;
    const int lch  = tid & 1;

    float acc[4][4][4];
    #pragma unroll
    for (int i=0;i<4;i++)
      #pragma unroll
      for (int j=0;j<4;j++)
        #pragma unroll
        for (int k=0;k<4;k++) acc[i][j][k]=0.f;

    uint32_t sAb = (uint32_t)__cvta_generic_to_shared(Asm);
    uint32_t sBb = (uint32_t)__cvta_generic_to_shared(Bsm);

#define CLOAD(s) do { \
        int st_  = (s) & 3; \
        int khw_ = (s) >> 4; \
        int ic0_ = ((s) & 15) << 5; \
        int kh_ = khw_ / 3, kw_ = khw_ - kh_*3; \
        const __half* ap_ = Ag + (((size_t)kw_*BB + b)*320 + m0 + kh_*32 + lrow)*CH + ic0_ + lch*8; \
        const __half* bp_ = Bg + ((size_t)khw_*CH + n0 + lrow)*CH + ic0_ + lch*8; \
        uint32_t da_ = sAb + (uint32_t)(((st_*128 + lrow)*CPITCH + lch*4)*4); \
        uint32_t db_ = sBb + (uint32_t)(((st_*128 + lrow)*CPITCH + lch*4)*4); \
        asm volatile("cp.async.cg.shared.global [%0], [%1], 16;" :: "r"(da_),      "l"(ap_)); \
        asm volatile("cp.async.cg.shared.global [%0], [%1], 16;" :: "r"(da_ + 32), "l"(ap_ + 16)); \
        asm volatile("cp.async.cg.shared.global [%0], [%1], 16;" :: "r"(db_),      "l"(bp_)); \
        asm volatile("cp.async.cg.shared.global [%0], [%1], 16;" :: "r"(db_ + 32), "l"(bp_ + 16)); \
        asm volatile("cp.async.commit_group;"); \
    } while(0)

    CLOAD(0); CLOAD(1); CLOAD(2);

    for (int s = 0; s < 144; ++s){
        asm volatile("cp.async.wait_group 2;");
        __syncthreads();
        if (s + 3 < 144) CLOAD(s + 3);

        const uint32_t* A_ = Asm + (s & 3) * CSTAGE_W;
        const uint32_t* B_ = Bsm + (s & 3) * CSTAGE_W;

        #pragma unroll
        for (int h = 0; h < 2; ++h){
            const int kb = h*8 + tig;
            uint32_t afr[4][4], bfr[4][2];
            #pragma unroll
            for (int mi=0; mi<4; ++mi){
                int rowb = wm + mi*16 + gid;
                afr[mi][0] = A_[rowb*CPITCH + kb];
                afr[mi][1] = A_[(rowb+8)*CPITCH + kb];
                afr[mi][2] = A_[rowb*CPITCH + kb + 4];
                afr[mi][3] = A_[(rowb+8)*CPITCH + kb + 4];
            }
            #pragma unroll
            for (int ni=0; ni<4; ++ni){
                int colb = wn + ni*8 + gid;
                bfr[ni][0] = B_[colb*CPITCH + kb];
                bfr[ni][1] = B_[colb*CPITCH + kb + 4];
            }
            #pragma unroll
            for (int mi=0; mi<4; ++mi)
                #pragma unroll
                for (int ni=0; ni<4; ++ni)
                    mma_fp16(acc[mi][ni], afr[mi], bfr[ni]);
        }
    }
#undef CLOAD

    #pragma unroll
    for (int mi=0; mi<4; ++mi){
        int prow = m0 + wm + mi*16 + gid;
        #pragma unroll
        for (int ni=0; ni<4; ++ni){
            int oc = n0 + wn + ni*8 + tig*2;
            float bz0 = bias[oc], bz1 = bias[oc+1];
            __half* o0 = out + ((size_t)b*CH + oc)*PP;
            o0[prow]          = __float2half(acc[mi][ni][0] + bz0);
            o0[PP + prow]     = __float2half(acc[mi][ni][1] + bz1);
            o0[prow + 8]      = __float2half(acc[mi][ni][2] + bz0);
            o0[PP + prow + 8] = __float2half(acc[mi][ni][3] + bz1);
        }
    }
}

// ---------------- fp16 step GEMM (+optional fused LSTM epilogue) -------------
#define GPITCH 20
#define GA_WORDS (64*GPITCH)
#define GB_WORDS (128*GPITCH)

__global__ void __launch_bounds__(256, 2) gemm16_kernel(
    __half* __restrict__ C16, int ldc,
    const __half* __restrict__ A1, const __half* __restrict__ W1, int K1,
    const __half* __restrict__ A2, const __half* __restrict__ W2, int K2,
    const float* __restrict__ bias, const float* __restrict__ Cadd, int ldadd,
    const float* __restrict__ Wgp, const int* __restrict__ textcol, int textstride,
    const float* __restrict__ cin, float* __restrict__ cout, __half* __restrict__ hout)
{
    extern __shared__ __align__(16) uint32_t sm[];
    uint32_t* Asm = sm;                  // [4][64][20]
    uint32_t* Bsm = sm + 4*GA_WORDS;     // [4][128][20]
    const int m0 = blockIdx.y * 64;
    const int n0 = blockIdx.x * 128;
    const int tid = threadIdx.x;
    const int lane = tid & 31, warp = tid >> 5;
    const int wm = (warp >> 2) * 32;
    const int wn = (warp & 3) * 32;
    const int gid = lane >> 2, tig = lane & 3;

    const int S1 = K1 >> 5;
    const int S2 = (A2 != nullptr) ? (K2 >> 5) : 0;
    const int S  = S1 + S2;

    float acc[2][4][4];
    #pragma unroll
    for (int i=0;i<2;i++)
      #pragma unroll
      for (int j=0;j<4;j++)
        #pragma unroll
        for (int k=0;k<4;k++) acc[i][j][k]=0.f;

    uint32_t sAb = (uint32_t)__cvta_generic_to_shared(Asm);
    uint32_t sBb = (uint32_t)__cvta_generic_to_shared(Bsm);

#define GLOAD(s) do { \
        int st_ = (s) & 3; int s_ = (s); \
        const __half* A_; const __half* W_; int k0_; \
        if (s_ < S1){ A_ = A1; W_ = W1; k0_ = s_ << 5; } \
        else        { A_ = A2; W_ = W2; k0_ = (s_ - S1) << 5; } \
        const __half* ap_ = A_ + (size_t)(m0 + (tid>>2))*512 + k0_ + (tid&3)*8; \
        uint32_t da_ = sAb + (uint32_t)(((st_*64 + (tid>>2))*GPITCH + (tid&3)*4)*4); \
        asm volatile("cp.async.cg.shared.global [%0], [%1], 16;" :: "r"(da_), "l"(ap_)); \
        const __half* bp_ = W_ + (size_t)(n0 + (tid>>1))*512 + k0_ + (tid&1)*16; \
        uint32_t db_ = sBb + (uint32_t)(((st_*128 + (tid>>1))*GPITCH + (tid&1)*8)*4); \
        asm volatile("cp.async.cg.shared.global [%0], [%1], 16;" :: "r"(db_),      "l"(bp_)); \
        asm volatile("cp.async.cg.shared.global [%0], [%1], 16;" :: "r"(db_ + 16), "l"(bp_ + 8)); \
        asm volatile("cp.async.commit_group;"); \
    } while(0)

    GLOAD(0); GLOAD(1); GLOAD(2);

    for (int s = 0; s < S; ++s){
        asm volatile("cp.async.wait_group 2;");
        __syncthreads();
        if (s + 3 < S) GLOAD(s + 3);

        const uint32_t* A_ = Asm + (s & 3) * GA_WORDS;
        const uint32_t* B_ = Bsm + (s & 3) * GB_WORDS;

        #pragma unroll
        for (int h = 0; h < 2; ++h){
            const int kb = h*8 + tig;
            uint32_t afr[2][4], bfr[4][2];
            #pragma unroll
            for (int mi=0; mi<2; ++mi){
                int rowb = wm + mi*16 + gid;
                afr[mi][0] = A_[rowb*GPITCH + kb];
                afr[mi][1] = A_[(rowb+8)*GPITCH + kb];
                afr[mi][2] = A_[rowb*GPITCH + kb + 4];
                afr[mi][3] = A_[(rowb+8)*GPITCH + kb + 4];
            }
            #pragma unroll
            for (int ni=0; ni<4; ++ni){
                int colb = wn + ni*8 + gid;
                bfr[ni][0] = B_[colb*GPITCH + kb];
                bfr[ni][1] = B_[colb*GPITCH + kb + 4];
            }
            #pragma unroll
            for (int mi=0; mi<2; ++mi)
                #pragma unroll
                for (int ni=0; ni<4; ++ni)
                    mma_fp16(acc[mi][ni], afr[mi], bfr[ni]);
        }
    }
#undef GLOAD

    #pragma unroll
    for (int mi=0; mi<2; ++mi){
        int m = m0 + wm + mi*16 + gid;
        int tc0 = 0, tc1 = 0;
        if (Wgp){ tc0 = textcol[m*textstride]; tc1 = textcol[(m+8)*textstride]; }
        #pragma unroll
        for (int ni=0; ni<4; ++ni){
            int n = n0 + wn + ni*8 + tig*2;
            float b0 = 0.f, b1 = 0.f;
            if (bias){ b0 = bias[n]; b1 = bias[n+1]; }
            float v00 = acc[mi][ni][0] + b0;
            float v01 = acc[mi][ni][1] + b1;
            float v10 = acc[mi][ni][2] + b0;
            float v11 = acc[mi][ni][3] + b1;
            if (Cadd){
                v00 += Cadd[(size_t)m*ldadd + n];     v01 += Cadd[(size_t)m*ldadd + n+1];
                v10 += Cadd[(size_t)(m+8)*ldadd + n]; v11 += Cadd[(size_t)(m+8)*ldadd + n+1];
            }
            if (Wgp){
                v00 += Wgp[n*NC + tc0];     v01 += Wgp[(n+1)*NC + tc0];
                v10 += Wgp[n*NC + tc1];     v11 += Wgp[(n+1)*NC + tc1];
            }
            if (cout){
                float p00 = __shfl_xor_sync(0xffffffffu, v00, 1);
                float p01 = __shfl_xor_sync(0xffffffffu, v01, 1);
                float p10 = __shfl_xor_sync(0xffffffffu, v10, 1);
                float p11 = __shfl_xor_sync(0xffffffffu, v11, 1);
                if ((tig & 1) == 0){
                    int j = n >> 2;
                    float c2a = fsigm(v01)*cin[(size_t)m*HS + j] + fsigm(v00)*ftanh(p00);
                    cout[(size_t)m*HS + j] = c2a;
                    hout[(size_t)m*HS + j] = __float2half(fsigm(p01)*ftanh(c2a));
                    float c2b = fsigm(v11)*cin[(size_t)(m+8)*HS + j] + fsigm(v10)*ftanh(p10);
                    cout[(size_t)(m+8)*HS + j] = c2b;
                    hout[(size_t)(m+8)*HS + j] = __float2half(fsigm(p11)*ftanh(c2b));
                }
            } else {
                C16[(size_t)m*ldc + n]       = __float2half(v00);
                C16[(size_t)m*ldc + n+1]     = __float2half(v01);
                C16[(size_t)(m+8)*ldc + n]   = __float2half(v10);
                C16[(size_t)(m+8)*ldc + n+1] = __float2half(v11);
            }
        }
    }
}

// ---------------- fp32 SIMT GEMM (prologue) ----------------------------------
__global__ void gemm_kernel(
    float* __restrict__ C, int ldc,
    const float* __restrict__ A1, int lda1, const float* __restrict__ W1, int ldw1, int K1,
    const float* __restrict__ bias1,
    const float* __restrict__ Cadd, int ldadd,
    int nn, int M, int N)
{
    __shared__ float As[16][68];
    __shared__ float Bs[16][68];
    int m0 = blockIdx.y * 64;
    int n0 = blockIdx.x * 64;
    int tid = threadIdx.x;
    int tx = tid & 15, ty = tid >> 4;

    float acc[4][4];
    #pragma unroll
    for (int i=0;i<4;i++)
        #pragma unroll
        for (int j=0;j<4;j++) acc[i][j]=0.f;

    for (int k0=0; k0<K1; k0+=16){
        #pragma unroll
        for (int i=0;i<4;i++){
            int e = i*256 + tid;
            int m = e >> 4, kk = e & 15;
            int gm = m0 + m, gk = k0 + kk;
            As[kk][m] = (gm < M && gk < K1) ? A1[(size_t)gm*lda1 + gk] : 0.f;
        }
        if (nn){
            #pragma unroll
            for (int i=0;i<4;i++){
                int e = i*256 + tid;
                int kk = e >> 6, n = e & 63;
                int gn = n0 + n, gk = k0 + kk;
                Bs[kk][n] = (gn < N && gk < K1) ? W1[(size_t)gk*ldw1 + gn] : 0.f;
            }
        } else {
            #pragma unroll
            for (int i=0;i<4;i++){
                int e = i*256 + tid;
                int n = e >> 4, kk = e & 15;
                int gn = n0 + n, gk = k0 + kk;
                Bs[kk][n] = (gn < N && gk < K1) ? W1[(size_t)gn*ldw1 + gk] : 0.f;
            }
        }
        __syncthreads();
        #pragma unroll
        for (int kk=0; kk<16; kk++){
            float4 a = *(const float4*)&As[kk][ty*4];
            float4 b = *(const float4*)&Bs[kk][tx*4];
            acc[0][0]+=a.x*b.x; acc[0][1]+=a.x*b.y; acc[0][2]+=a.x*b.z; acc[0][3]+=a.x*b.w;
            acc[1][0]+=a.y*b.x; acc[1][1]+=a.y*b.y; acc[1][2]+=a.y*b.z; acc[1][3]+=a.y*b.w;
            acc[2][0]+=a.z*b.x; acc[2][1]+=a.z*b.y; acc[2][2]+=a.z*b.z; acc[2][3]+=a.z*b.w;
            acc[3][0]+=a.w*b.x; acc[3][1]+=a.w*b.y; acc[3][2]+=a.w*b.z; acc[3][3]+=a.w*b.w;
        }
        __syncthreads();
    }

    #pragma unroll
    for (int i=0;i<4;i++){
        int m = m0 + ty*4 + i;
        if (m >= M) continue;
        #pragma unroll
        for (int j=0;j<4;j++){
            int n = n0 + tx*4 + j;
            if (n >= N) continue;
            float v = acc[i][j];
            if (bias1) v += bias1[n];
            if (Cadd)  v += Cadd[(size_t)m*ldadd + n];
            C[(size_t)m*ldc + n] = v;
        }
    }
}

// ---------------- generator GEMM (fp16 A, fp32 W), remapped output ----------
__global__ void gen_kernel(
    float* __restrict__ C,
    const __half* __restrict__ A1, const float* __restrict__ W1,
    const float* __restrict__ bias1, int M, int N)
{
    __shared__ float As[16][68];
    __shared__ float Bs[16][68];
    int m0 = blockIdx.y * 64;
    int tid = threadIdx.x;
    int tx = tid & 15, ty = tid >> 4;

    float acc[4][4];
    #pragma unroll
    for (int i=0;i<4;i++)
        #pragma unroll
        for (int j=0;j<4;j++) acc[i][j]=0.f;

    for (int k0=0; k0<HS; k0+=16){
        #pragma unroll
        for (int i=0;i<4;i++){
            int e = i*256 + tid;
            int m = e >> 4, kk = e & 15;
            int gm = m0 + m, gk = k0 + kk;
            As[kk][m] = (gm < M) ? __half2float(A1[(size_t)gm*HS + gk]) : 0.f;
        }
        #pragma unroll
        for (int i=0;i<4;i++){
            int e = i*256 + tid;
            int n = e >> 4, kk = e & 15;
            int gk = k0 + kk;
            Bs[kk][n] = (n < N) ? W1[(size_t)n*HS + gk] : 0.f;
        }
        __syncthreads();
        #pragma unroll
        for (int kk=0; kk<16; kk++){
            float4 a = *(const float4*)&As[kk][ty*4];
            float4 b = *(const float4*)&Bs[kk][tx*4];
            acc[0][0]+=a.x*b.x; acc[0][1]+=a.x*b.y; acc[0][2]+=a.x*b.z; acc[0][3]+=a.x*b.w;
            acc[1][0]+=a.y*b.x; acc[1][1]+=a.y*b.y; acc[1][2]+=a.y*b.z; acc[1][3]+=a.y*b.w;
            acc[2][0]+=a.z*b.x; acc[2][1]+=a.z*b.y; acc[2][2]+=a.z*b.z; acc[2][3]+=a.z*b.w;
            acc[3][0]+=a.w*b.x; acc[3][1]+=a.w*b.y; acc[3][2]+=a.w*b.z; acc[3][3]+=a.w*b.w;
        }
        __syncthreads();
    }

    #pragma unroll
    for (int i=0;i<4;i++){
        int m = m0 + ty*4 + i;
        if (m >= M) continue;
        int t = m >> 8, b = m & 255;
        #pragma unroll
        for (int j=0;j<4;j++){
            int n = tx*4 + j;
            if (n >= N) continue;
            C[(size_t)(b*TT + t)*NC + n] = acc[i][j] + bias1[n];
        }
    }
}

// ---------------- mean over T of batch_H ------------------------------------
__global__ void mean_kernel(const float* __restrict__ bH, float* __restrict__ out)
{
    int idx = blockIdx.x*256 + threadIdx.x;
    if (idx >= BB*INSZ) return;
    int b = idx >> 9, k = idx & 511;
    const float* p = bH + (size_t)b*TT*INSZ + k;
    float s = 0.f;
    #pragma unroll
    for (int t=0;t<TT;t++) s += p[t*INSZ];
    out[idx] = s * (1.0f/26.0f);
}

// ---------------- init h0/c0 -------------------------------------------------
__global__ void init_kernel(const float* __restrict__ hh, const float* __restrict__ hc,
                            __half* __restrict__ h1, __half* __restrict__ h2,
                            float* __restrict__ c1, float* __restrict__ c2)
{
    int idx = blockIdx.x*256 + threadIdx.x;
    if (idx >= BB*HS) return;
    float h0 = 0.5f*(hh[idx] + hh[BB*HS + idx]);
    float c0 = 0.5f*(hc[idx] + hc[BB*HS + idx]);
    h1[idx] = __float2half(h0); h2[idx] = __float2half(h0);
    c1[idx]=c0; c2[idx]=c0;
}

// ---------------- attention with fused q-projection --------------------------
// q = qb + h2 @ Wq^T computed in-block (fp32), then e/softmax/context
__global__ void attn_kernel(const __half* __restrict__ fmh, const __half* __restrict__ h2,
                            const __half* __restrict__ Wq16, const float* __restrict__ qb,
                            const float* __restrict__ ws, const float* __restrict__ sb,
                            __half* __restrict__ ctx)
{
    __shared__ float hs[CH];
    __shared__ float qs[CH];
    __shared__ float wss[CH];
    __shared__ float red[256];
    __shared__ float alpha[256];

    int b = blockIdx.x;
    int p = threadIdx.x;
    const __half* f = fmh + (size_t)b * CH * PP;

    hs[p]      = __half2float(h2[b*HS + p]);
    hs[p+256]  = __half2float(h2[b*HS + p + 256]);
    wss[p]     = ws[p];
    wss[p+256] = ws[p+256];
    __syncthreads();

    // q rows p and p+256
    {
        const __half* w0 = Wq16 + (size_t)p*HS;
        const __half* w1 = Wq16 + (size_t)(p+256)*HS;
        float s0 = 0.f, s1 = 0.f;
        #pragma unroll 4
        for (int k=0; k<CH; k+=8){
            uint4 av = *(const uint4*)(w0 + k);
            uint4 bv = *(const uint4*)(w1 + k);
            const __half* ah = (const __half*)&av;
            const __half* bh = (const __half*)&bv;
            #pragma unroll
            for (int i=0;i<8;i++){
                float hv = hs[k+i];
                s0 += __half2float(ah[i]) * hv;
                s1 += __half2float(bh[i]) * hv;
            }
        }
        qs[p]     = qb[b*HS + p]       + s0;
        qs[p+256] = qb[b*HS + p + 256] + s1;
    }
    __syncthreads();

    float a0=0.f, a1=0.f, a2=0.f, a3=0.f;
    #pragma unroll 2
    for (int c=0; c<CH; c+=4){
        float f0 = __half2float(f[(c  )*PP + p]);
        float f1 = __half2float(f[(c+1)*PP + p]);
        float f2 = __half2float(f[(c+2)*PP + p]);
        float f3 = __half2float(f[(c+3)*PP + p]);
        a0 += ftanh_hw(f0 + qs[c  ]) * wss[c  ];
        a1 += ftanh_hw(f1 + qs[c+1]) * wss[c+1];
        a2 += ftanh_hw(f2 + qs[c+2]) * wss[c+2];
        a3 += ftanh_hw(f3 + qs[c+3]) * wss[c+3];
    }
    float e = (a0+a1) + (a2+a3) + sb[0];

    red[p] = e; __syncthreads();
    #pragma unroll
    for (int s=128; s>0; s>>=1){
        if (p < s) red[p] = fmaxf(red[p], red[p+s]);
        __syncthreads();
    }
    float mx = red[0];
    __syncthreads();
    float ex = fexp(e - mx);
    red[p] = ex; __syncthreads();
    #pragma unroll
    for (int s=128; s>0; s>>=1){
        if (p < s) red[p] += red[p+s];
        __syncthreads();
    }
    float sum = red[0];
    __syncthreads();
    alpha[p] = ex * frcp(sum);
    __syncthreads();

    int lane = p & 31, wid = p >> 5;
    for (int c = wid; c < CH; c += 8){
        const __half* fr = f + c*PP;
        float s = 0.f;
        #pragma unroll
        for (int pp = lane; pp < PP; pp += 32) s += alpha[pp] * __half2float(fr[pp]);
        #pragma unroll
        for (int o=16; o>0; o>>=1) s += __shfl_down_sync(0xffffffffu, s, o);
        if (lane == 0) ctx[b*HS + c] = __float2half(s);
    }
}

// ---------------- host orchestration ----------------------------------------
extern "C" void kernel_launch(void* const* d_in, const int* in_sizes, int n_in,
                              void* d_out, int out_size)
{
    const float* feature_map = (const float*)d_in[0];
    const float* batch_H     = (const float*)d_in[1];
    const float* hidden_h    = (const float*)d_in[2];
    const float* hidden_c    = (const float*)d_in[3];
    const int*   text        = (const int*)  d_in[4];
    const float* i2h_w       = (const float*)d_in[5];
    const float* h2h_w       = (const float*)d_in[6];
    const float* h2h_b       = (const float*)d_in[7];
    const float* conv_m2h_w  = (const float*)d_in[8];
    const float* conv_m2h_b  = (const float*)d_in[9];
    const float* conv_h2h_w  = (const float*)d_in[10];
    const float* conv_h2h_b  = (const float*)d_in[11];
    const float* score_w     = (const float*)d_in[12];
    const float* score_b     = (const float*)d_in[13];
    const float* rnn1_w_ih   = (const float*)d_in[14];
    const float* rnn1_w_hh   = (const float*)d_in[15];
    const float* rnn1_b_ih   = (const float*)d_in[16];
    const float* rnn1_b_hh   = (const float*)d_in[17];
    const float* hlin_w      = (const float*)d_in[18];
    const float* hlin_b      = (const float*)d_in[19];
    const float* rnn2_w_ih   = (const float*)d_in[20];
    const float* rnn2_w_hh   = (const float*)d_in[21];
    const float* rnn2_b_ih   = (const float*)d_in[22];
    const float* rnn2_b_hh   = (const float*)d_in[23];
    const float* gen_w       = (const float*)d_in[24];
    const float* gen_b       = (const float*)d_in[25];
    float* out = (float*)d_out;

    __half *ahT,*bhT,*fmh,*Wq16,*hlinT16,*w2ihraw16,*W2pp16;
    __half *w1ih16,*w1hh16,*w2ih16,*w2hh16;
    __half *h1a16,*h1b16,*h2a16,*hist16,*ctx16;
    float *meanH,*bhproj,*Wq,*qb,*badd,*bias1p,*bias2p,*wgp;
    float *c1a,*c1b,*c2a,*c2b;
    cudaGetSymbolAddress((void**)&ahT, g_ahT);
    cudaGetSymbolAddress((void**)&bhT, g_bhT);
    cudaGetSymbolAddress((void**)&fmh, g_fmh);
    cudaGetSymbolAddress((void**)&meanH, g_meanH);
    cudaGetSymbolAddress((void**)&bhproj,g_bhproj);
    cudaGetSymbolAddress((void**)&Wq,    g_Wq);
    cudaGetSymbolAddress((void**)&qb,    g_qb);
    cudaGetSymbolAddress((void**)&badd,  g_badd);
    cudaGetSymbolAddress((void**)&Wq16,  g_Wq16);
    cudaGetSymbolAddress((void**)&hlinT16, g_hlinT16);
    cudaGetSymbolAddress((void**)&w2ihraw16, g_w2ihraw16);
    cudaGetSymbolAddress((void**)&W2pp16, g_W2pp16);
    cudaGetSymbolAddress((void**)&w1ih16,g_w1ih16);
    cudaGetSymbolAddress((void**)&w1hh16,g_w1hh16);
    cudaGetSymbolAddress((void**)&w2ih16,g_w2ih16);
    cudaGetSymbolAddress((void**)&w2hh16,g_w2hh16);
    cudaGetSymbolAddress((void**)&bias1p,g_bias1p);
    cudaGetSymbolAddress((void**)&bias2p,g_bias2p);
    cudaGetSymbolAddress((void**)&wgp,   g_wgp);
    cudaGetSymbolAddress((void**)&h1a16, g_h1a16);
    cudaGetSymbolAddress((void**)&h1b16, g_h1b16);
    cudaGetSymbolAddress((void**)&h2a16, g_h2a16);
    cudaGetSymbolAddress((void**)&c1a, g_c1a); cudaGetSymbolAddress((void**)&c1b, g_c1b);
    cudaGetSymbolAddress((void**)&c2a, g_c2a); cudaGetSymbolAddress((void**)&c2b, g_c2b);
    cudaGetSymbolAddress((void**)&hist16, g_hist16);
    cudaGetSymbolAddress((void**)&ctx16,g_ctx16);

    const int CONV_SMEM = 2 * 4 * 128 * CPITCH * 4;   // 81920
    cudaFuncSetAttribute(conv_fp16_kernel, cudaFuncAttributeMaxDynamicSharedMemorySize, CONV_SMEM);
    const int G16_SMEM = 4 * (GA_WORDS + GB_WORDS) * 4;  // 61440
    cudaFuncSetAttribute(gemm16_kernel, cudaFuncAttributeMaxDynamicSharedMemorySize, G16_SMEM);

    // ---- conv prep + conv ----
    padT_kernel<<<256*10*16, 256>>>(feature_map, ahT);
    wT_kernel<<<(9*CH*CH+255)/256, 256>>>(conv_m2h_w, bhT);
    conv_fp16_kernel<<<dim3(4,2,BB), 256, CONV_SMEM>>>(ahT, bhT, conv_m2h_b, fmh);

    // ---- weight packing ----
    wpack16_kernel<<<(4*HS*512+255)/256,256>>>(rnn1_w_ih, INSZ+NC, w1ih16);
    wpack16_kernel<<<(4*HS*512+255)/256,256>>>(rnn1_w_hh, HS, w1hh16);
    wpack16_kernel<<<(4*HS*512+255)/256,256>>>(rnn2_w_hh, HS, w2hh16);
    bpack_kernel<<<(4*HS+255)/256,256>>>(rnn1_b_ih, rnn1_b_hh, nullptr, bias1p);
    wgpack_kernel<<<(4*HS*NC+255)/256,256>>>(rnn1_w_ih, wgp);
    // fold hlin into rnn2_w_ih via fp16 tensor GEMM:
    //   W2pp = w2ih @ hlin  (= A @ W^T with W = hlin^T)
    cast16_kernel<<<(4*HS*HS+255)/256,256>>>(rnn2_w_ih, w2ihraw16, 4*HS*HS);
    transposeT16_kernel<<<256,256>>>(hlin_w, hlinT16);
    gemm16_kernel<<<dim3(4,32),256,G16_SMEM>>>(W2pp16, HS,
        w2ihraw16, hlinT16, HS, nullptr, nullptr, 0,
        nullptr, nullptr, 0, nullptr, nullptr, 0,
        nullptr, nullptr, nullptr);
    wpack16h_kernel<<<(4*HS*512+255)/256,256>>>(W2pp16, w2ih16);
    badd_kernel<<<(4*HS+255)/256,256>>>(rnn2_w_ih, hlin_b, badd);
    bpack_kernel<<<(4*HS+255)/256,256>>>(rnn2_b_ih, rnn2_b_hh, badd, bias2p);

    // ---- prologue (fp32) ----
    mean_kernel<<<512,256>>>(batch_H, meanH);
    gemm_kernel<<<dim3(8,4),256>>>(bhproj, HS, meanH, INSZ, i2h_w, INSZ, INSZ,
                                   h2h_b, nullptr,0, 0, BB, HS);
    gemm_kernel<<<dim3(8,8),256>>>(Wq, HS, conv_h2h_w, HS, h2h_w, HS, HS,
                                   nullptr, nullptr,0, 1, HS, HS);
    cast16_kernel<<<(HS*HS+255)/256,256>>>(Wq, Wq16, HS*HS);
    gemm_kernel<<<dim3(8,4),256>>>(qb, HS, bhproj, HS, conv_h2h_w, HS, HS,
                                   conv_h2h_b, nullptr,0, 0, BB, HS);
    init_kernel<<<512,256>>>(hidden_h, hidden_c, h1a16, h2a16, c1a, c2a);

    __half *h1c16=h1a16, *h1n16=h1b16, *h2c16=h2a16;
    float *c1c=c1a, *c1n=c1b, *c2c=c2a, *c2n=c2b;

    for (int t=0; t<TT; t++){
        __half* h2n16 = hist16 + (size_t)t*BB*HS;
        // attention with fused q-projection -> ctx (fp16)
        attn_kernel<<<BB,256>>>(fmh, h2c16, Wq16, qb, score_w, score_b, ctx16);
        // gates1 + fused LSTM1
        gemm16_kernel<<<dim3(16,4),256,G16_SMEM>>>(nullptr, 0,
            ctx16, w1ih16, HS, h1c16, w1hh16, HS,
            bias1p, nullptr, 0, wgp, text + t, TT,
            c1c, c1n, h1n16);
        // gates2 + fused LSTM2 (hlin folded into w2ih16)
        gemm16_kernel<<<dim3(16,4),256,G16_SMEM>>>(nullptr, 0,
            h1n16, w2ih16, HS, h2c16, w2hh16, HS,
            bias2p, nullptr, 0, nullptr, nullptr, 0,
            c2c, c2n, h2n16);

        __half* tph;
        tph=h1c16; h1c16=h1n16; h1n16=tph;
        h2c16 = h2n16;
        float* tp;
        tp=c1c; c1c=c1n; c1n=tp;
        tp=c2c; c2c=c2n; c2n=tp;
    }

    // probs: one batched GEMM over all timesteps (fp16 hist), remap [b][t][n]
    gen_kernel<<<dim3(1,104),256>>>(out, hist16, gen_w, gen_b, TT*BB, NC);
}

// round 13
// speedup vs baseline: 1.2008x; 1.2008x over previous
#include <cuda_runtime.h>
#include <cuda_fp16.h>
#include <math.h>
#include <stdint.h>

#define BB 256
#define HS 512
#define INSZ 512
#define NC 38
#define TT 26
#define CH 512
#define PP 256   /* 8*32 */

// ---------------- scratch (device globals; no allocation allowed) ----------
__device__ __align__(16) __half g_ahT[(size_t)3*BB*320*CH];
__device__ __align__(16) __half g_bhT[9*CH*CH];
__device__ __align__(16) __half g_fmh[(size_t)BB*CH*PP];
__device__ float g_meanH[BB*INSZ];
__device__ float g_bhproj[BB*HS];
__device__ float g_Wq[HS*HS];
__device__ float g_qb[BB*HS];
__device__ float g_badd[4*HS];
__device__ __align__(16) __half g_Wq16[HS*HS];
__device__ __align__(16) __half g_hlinT16[HS*HS];
__device__ __align__(16) __half g_w2ihraw16[4*HS*HS];
__device__ __align__(16) __half g_W2pp16[4*HS*HS];
__device__ __align__(16) __half g_w1ih16[4*HS*INSZ];
__device__ __align__(16) __half g_w1hh16[4*HS*HS];
__device__ __align__(16) __half g_w2ih16[4*HS*HS];
__device__ __align__(16) __half g_w2hh16[4*HS*HS];
__device__ float g_bias1p[4*HS], g_bias2p[4*HS];
__device__ float g_wgp[4*HS*NC];
__device__ __align__(16) __half g_h1a16[BB*HS], g_h1b16[BB*HS], g_h2a16[BB*HS];
__device__ float g_c1a[BB*HS], g_c1b[BB*HS], g_c2a[BB*HS], g_c2b[BB*HS];
__device__ __align__(16) __half g_hist16[(size_t)TT*BB*HS];
__device__ __align__(16) __half g_q16[BB*HS];
__device__ __align__(16) __half g_ctx16[BB*HS];

// ---------------- fast math ------------------------------------------------
__device__ __forceinline__ float fexp(float x){
    float y; asm("ex2.approx.f32 %0, %1;" : "=f"(y) : "f"(x*1.4426950408889634f)); return y;
}
__device__ __forceinline__ float frcp(float x){
    float y; asm("rcp.approx.f32 %0, %1;" : "=f"(y) : "f"(x)); return y;
}
__device__ __forceinline__ float ftanh(float x){
    float xc = fminf(fmaxf(x, -15.f), 15.f);
    float t = fexp(2.f*xc);
    return (t - 1.f) * frcp(t + 1.f);
}
__device__ __forceinline__ float ftanh_hw(float x){
    float y; asm("tanh.approx.f32 %0, %1;" : "=f"(y) : "f"(x)); return y;
}
__device__ __forceinline__ float fsigm(float x){
    return frcp(1.f + fexp(-x));
}
__device__ __forceinline__ void mma_fp16(float* d, const uint32_t* a, const uint32_t* b){
    asm volatile(
      "mma.sync.aligned.m16n8k16.row.col.f32.f16.f16.f32 "
      "{%0,%1,%2,%3},{%4,%5,%6,%7},{%8,%9},{%0,%1,%2,%3};"
      : "+f"(d[0]),"+f"(d[1]),"+f"(d[2]),"+f"(d[3])
      : "r"(a[0]),"r"(a[1]),"r"(a[2]),"r"(a[3]), "r"(b[0]),"r"(b[1]));
}

// ---------------- prep kernels ------------------------------------------------
__global__ void padT_kernel(const float* __restrict__ in, __half* __restrict__ oh)
{
    __shared__ float s[32][33];
    int blk = blockIdx.x;
    int icb = blk & 15;
    int rr  = (blk >> 4) % 10;
    int b   = blk >> 4; b /= 10;
    int t = threadIdx.x;
    int r = rr - 1;

    if ((unsigned)r < 8u){
        int c = t & 31, icq = t >> 5;
        #pragma unroll
        for (int j=0;j<4;j++){
            int ic = icq + j*8;
            s[ic][c] = in[((size_t)b*CH + icb*32 + ic)*PP + r*32 + c];
        }
    }
    __syncthreads();

    int icl = t & 31, cq = t >> 5;
    #pragma unroll
    for (int j=0;j<4;j++){
        int c = cq + j*8;
        #pragma unroll
        for (int kw=0; kw<3; kw++){
            int cc = c + kw - 1;
            float v = 0.f;
            if ((unsigned)r < 8u && (unsigned)cc < 32u) v = s[icl][cc];
            size_t off = (((size_t)kw*BB + b)*320 + rr*32 + c)*CH + icb*32 + icl;
            oh[off] = __float2half(v);
        }
    }
}

__global__ void wT_kernel(const float* __restrict__ w, __half* __restrict__ oh)
{
    int idx = blockIdx.x*256 + threadIdx.x;
    if (idx >= 9*CH*CH) return;
    int ic = idx & 511;
    int oc = (idx >> 9) & 511;
    int khw = idx >> 18;
    oh[((size_t)khw*CH + oc)*CH + ic] = __float2half(w[((size_t)oc*CH + ic)*9 + khw]);
}

__global__ void cast16_kernel(const float* __restrict__ in, __half* __restrict__ out, int n)
{
    int idx = blockIdx.x*256 + threadIdx.x;
    if (idx < n) out[idx] = __float2half(in[idx]);
}

// out[k][n] = fp16(in[n][k]), 512x512
__global__ void transposeT16_kernel(const float* __restrict__ in, __half* __restrict__ out)
{
    __shared__ float s[32][33];
    int bx = blockIdx.x & 15, by = blockIdx.x >> 4;
    int tx = threadIdx.x & 31, ty = threadIdx.x >> 5;
    #pragma unroll
    for (int i=0;i<4;i++){
        int n = bx*32 + ty + i*8;
        s[ty+i*8][tx] = in[(size_t)n*HS + by*32 + tx];
    }
    __syncthreads();
    #pragma unroll
    for (int i=0;i<4;i++){
        int k = by*32 + ty + i*8;
        out[(size_t)k*HS + bx*32 + tx] = __float2half(s[tx][ty+i*8]);
    }
}

__global__ void wpack16_kernel(const float* __restrict__ w, int ldw, __half* __restrict__ out)
{
    int idx = blockIdx.x*256 + threadIdx.x;
    if (idx >= 4*HS*512) return;
    int k = idx & 511;
    int row = idx >> 9;
    int j = row >> 2, g = row & 3;
    out[idx] = __float2half(w[(size_t)(g*HS + j)*ldw + k]);
}

__global__ void wpack16h_kernel(const __half* __restrict__ w, __half* __restrict__ out)
{
    int idx = blockIdx.x*256 + threadIdx.x;
    if (idx >= 4*HS*512) return;
    int k = idx & 511;
    int row = idx >> 9;
    int j = row >> 2, g = row & 3;
    out[idx] = w[(size_t)(g*HS + j)*512 + k];
}

__global__ void bpack_kernel(const float* __restrict__ bih, const float* __restrict__ bhh,
                             const float* __restrict__ badd, float* __restrict__ out)
{
    int row = blockIdx.x*256 + threadIdx.x;
    if (row >= 4*HS) return;
    int j = row >> 2, g = row & 3;
    float v = bih[g*HS + j] + bhh[g*HS + j];
    if (badd) v += badd[g*HS + j];
    out[row] = v;
}

__global__ void wgpack_kernel(const float* __restrict__ w, float* __restrict__ out)
{
    int idx = blockIdx.x*256 + threadIdx.x;
    if (idx >= 4*HS*NC) return;
    int c = idx % NC;
    int row = idx / NC;
    int j = row >> 2, g = row & 3;
    out[idx] = w[(size_t)(g*HS + j)*(INSZ+NC) + INSZ + c];
}

__global__ void badd_kernel(const float* __restrict__ w2ih, const float* __restrict__ hlinb,
                            float* __restrict__ out)
{
    int m = blockIdx.x*256 + threadIdx.x;
    if (m >= 4*HS) return;
    const float* wr = w2ih + (size_t)m*HS;
    float s = 0.f;
    #pragma unroll 8
    for (int k=0;k<HS;k++) s += wr[k]*hlinb[k];
    out[m] = s;
}

// ---------------- conv 3x3 SAME via fp16 mma, 4-stage cp.async ---------------
#define CPITCH 20
#define CSTAGE_W (128*CPITCH)

__global__ void __launch_bounds__(256, 2) conv_fp16_kernel(
    const __half* __restrict__ Ag, const __half* __restrict__ Bg,
    const float* __restrict__ bias, __half* __restrict__ out)
{
    extern __shared__ __align__(16) uint32_t sm[];
    uint32_t* Asm = sm;
    uint32_t* Bsm = sm + 4*CSTAGE_W;
    const int b  = blockIdx.z;
    const int m0 = blockIdx.y * 128;
    const int n0 = blockIdx.x * 128;
    const int tid = threadIdx.x;
    const int lane = tid & 31, warp = tid >> 5;
    const int wm = (warp >> 2) * 64;
    const int wn = (warp & 3) * 32;
    const int gid = lane >> 2, tig = lane & 3;

    const int lrow = tid >> 1;
    const int lch  = tid & 1;

    float acc[4][4][4];
    #pragma unroll
    for (int i=0;i<4;i++)
      #pragma unroll
      for (int j=0;j<4;j++)
        #pragma unroll
        for (int k=0;k<4;k++) acc[i][j][k]=0.f;

    uint32_t sAb = (uint32_t)__cvta_generic_to_shared(Asm);
    uint32_t sBb = (uint32_t)__cvta_generic_to_shared(Bsm);

#define CLOAD(s) do { \
        int st_  = (s) & 3; \
        int khw_ = (s) >> 4; \
        int ic0_ = ((s) & 15) << 5; \
        int kh_ = khw_ / 3, kw_ = khw_ - kh_*3; \
        const __half* ap_ = Ag + (((size_t)kw_*BB + b)*320 + m0 + kh_*32 + lrow)*CH + ic0_ + lch*8; \
        const __half* bp_ = Bg + ((size_t)khw_*CH + n0 + lrow)*CH + ic0_ + lch*8; \
        uint32_t da_ = sAb + (uint32_t)(((st_*128 + lrow)*CPITCH + lch*4)*4); \
        uint32_t db_ = sBb + (uint32_t)(((st_*128 + lrow)*CPITCH + lch*4)*4); \
        asm volatile("cp.async.cg.shared.global [%0], [%1], 16;" :: "r"(da_),      "l"(ap_)); \
        asm volatile("cp.async.cg.shared.global [%0], [%1], 16;" :: "r"(da_ + 32), "l"(ap_ + 16)); \
        asm volatile("cp.async.cg.shared.global [%0], [%1], 16;" :: "r"(db_),      "l"(bp_)); \
        asm volatile("cp.async.cg.shared.global [%0], [%1], 16;" :: "r"(db_ + 32), "l"(bp_ + 16)); \
        asm volatile("cp.async.commit_group;"); \
    } while(0)

    CLOAD(0); CLOAD(1); CLOAD(2);

    for (int s = 0; s < 144; ++s){
        asm volatile("cp.async.wait_group 2;");
        __syncthreads();
        if (s + 3 < 144) CLOAD(s + 3);

        const uint32_t* A_ = Asm + (s & 3) * CSTAGE_W;
        const uint32_t* B_ = Bsm + (s & 3) * CSTAGE_W;

        #pragma unroll
        for (int h = 0; h < 2; ++h){
            const int kb = h*8 + tig;
            uint32_t afr[4][4], bfr[4][2];
            #pragma unroll
            for (int mi=0; mi<4; ++mi){
                int rowb = wm + mi*16 + gid;
                afr[mi][0] = A_[rowb*CPITCH + kb];
                afr[mi][1] = A_[(rowb+8)*CPITCH + kb];
                afr[mi][2] = A_[rowb*CPITCH + kb + 4];
                afr[mi][3] = A_[(rowb+8)*CPITCH + kb + 4];
            }
            #pragma unroll
            for (int ni=0; ni<4; ++ni){
                int colb = wn + ni*8 + gid;
                bfr[ni][0] = B_[colb*CPITCH + kb];
                bfr[ni][1] = B_[colb*CPITCH + kb + 4];
            }
            #pragma unroll
            for (int mi=0; mi<4; ++mi)
                #pragma unroll
                for (int ni=0; ni<4; ++ni)
                    mma_fp16(acc[mi][ni], afr[mi], bfr[ni]);
        }
    }
#undef CLOAD

    #pragma unroll
    for (int mi=0; mi<4; ++mi){
        int prow = m0 + wm + mi*16 + gid;
        #pragma unroll
        for (int ni=0; ni<4; ++ni){
            int oc = n0 + wn + ni*8 + tig*2;
            float bz0 = bias[oc], bz1 = bias[oc+1];
            __half* o0 = out + ((size_t)b*CH + oc)*PP;
            o0[prow]          = __float2half(acc[mi][ni][0] + bz0);
            o0[PP + prow]     = __float2half(acc[mi][ni][1] + bz1);
            o0[prow + 8]      = __float2half(acc[mi][ni][2] + bz0);
            o0[PP + prow + 8] = __float2half(acc[mi][ni][3] + bz1);
        }
    }
}

// ---------------- fp16 step GEMM (+optional fused LSTM epilogue) -------------
#define GPITCH 20
#define GA_WORDS (64*GPITCH)
#define GB_WORDS (128*GPITCH)

__global__ void __launch_bounds__(256, 2) gemm16_kernel(
    __half* __restrict__ C16, int ldc,
    const __half* __restrict__ A1, const __half* __restrict__ W1, int K1,
    const __half* __restrict__ A2, const __half* __restrict__ W2, int K2,
    const float* __restrict__ bias, const float* __restrict__ Cadd, int ldadd,
    const float* __restrict__ Wgp, const int* __restrict__ textcol, int textstride,
    const float* __restrict__ cin, float* __restrict__ cout, __half* __restrict__ hout)
{
    extern __shared__ __align__(16) uint32_t sm[];
    uint32_t* Asm = sm;                  // [4][64][20]
    uint32_t* Bsm = sm + 4*GA_WORDS;     // [4][128][20]
    const int m0 = blockIdx.y * 64;
    const int n0 = blockIdx.x * 128;
    const int tid = threadIdx.x;
    const int lane = tid & 31, warp = tid >> 5;
    const int wm = (warp >> 2) * 32;
    const int wn = (warp & 3) * 32;
    const int gid = lane >> 2, tig = lane & 3;

    const int S1 = K1 >> 5;
    const int S2 = (A2 != nullptr) ? (K2 >> 5) : 0;
    const int S  = S1 + S2;

    float acc[2][4][4];
    #pragma unroll
    for (int i=0;i<2;i++)
      #pragma unroll
      for (int j=0;j<4;j++)
        #pragma unroll
        for (int k=0;k<4;k++) acc[i][j][k]=0.f;

    uint32_t sAb = (uint32_t)__cvta_generic_to_shared(Asm);
    uint32_t sBb = (uint32_t)__cvta_generic_to_shared(Bsm);

#define GLOAD(s) do { \
        int st_ = (s) & 3; int s_ = (s); \
        const __half* A_; const __half* W_; int k0_; \
        if (s_ < S1){ A_ = A1; W_ = W1; k0_ = s_ << 5; } \
        else        { A_ = A2; W_ = W2; k0_ = (s_ - S1) << 5; } \
        const __half* ap_ = A_ + (size_t)(m0 + (tid>>2))*512 + k0_ + (tid&3)*8; \
        uint32_t da_ = sAb + (uint32_t)(((st_*64 + (tid>>2))*GPITCH + (tid&3)*4)*4); \
        asm volatile("cp.async.cg.shared.global [%0], [%1], 16;" :: "r"(da_), "l"(ap_)); \
        const __half* bp_ = W_ + (size_t)(n0 + (tid>>1))*512 + k0_ + (tid&1)*16; \
        uint32_t db_ = sBb + (uint32_t)(((st_*128 + (tid>>1))*GPITCH + (tid&1)*8)*4); \
        asm volatile("cp.async.cg.shared.global [%0], [%1], 16;" :: "r"(db_),      "l"(bp_)); \
        asm volatile("cp.async.cg.shared.global [%0], [%1], 16;" :: "r"(db_ + 16), "l"(bp_ + 8)); \
        asm volatile("cp.async.commit_group;"); \
    } while(0)

    GLOAD(0); GLOAD(1); GLOAD(2);

    for (int s = 0; s < S; ++s){
        asm volatile("cp.async.wait_group 2;");
        __syncthreads();
        if (s + 3 < S) GLOAD(s + 3);

        const uint32_t* A_ = Asm + (s & 3) * GA_WORDS;
        const uint32_t* B_ = Bsm + (s & 3) * GB_WORDS;

        #pragma unroll
        for (int h = 0; h < 2; ++h){
            const int kb = h*8 + tig;
            uint32_t afr[2][4], bfr[4][2];
            #pragma unroll
            for (int mi=0; mi<2; ++mi){
                int rowb = wm + mi*16 + gid;
                afr[mi][0] = A_[rowb*GPITCH + kb];
                afr[mi][1] = A_[(rowb+8)*GPITCH + kb];
                afr[mi][2] = A_[rowb*GPITCH + kb + 4];
                afr[mi][3] = A_[(rowb+8)*GPITCH + kb + 4];
            }
            #pragma unroll
            for (int ni=0; ni<4; ++ni){
                int colb = wn + ni*8 + gid;
                bfr[ni][0] = B_[colb*GPITCH + kb];
                bfr[ni][1] = B_[colb*GPITCH + kb + 4];
            }
            #pragma unroll
            for (int mi=0; mi<2; ++mi)
                #pragma unroll
                for (int ni=0; ni<4; ++ni)
                    mma_fp16(acc[mi][ni], afr[mi], bfr[ni]);
        }
    }
#undef GLOAD

    #pragma unroll
    for (int mi=0; mi<2; ++mi){
        int m = m0 + wm + mi*16 + gid;
        int tc0 = 0, tc1 = 0;
        if (Wgp){ tc0 = textcol[m*textstride]; tc1 = textcol[(m+8)*textstride]; }
        #pragma unroll
        for (int ni=0; ni<4; ++ni){
            int n = n0 + wn + ni*8 + tig*2;
            float b0 = 0.f, b1 = 0.f;
            if (bias){ b0 = bias[n]; b1 = bias[n+1]; }
            float v00 = acc[mi][ni][0] + b0;
            float v01 = acc[mi][ni][1] + b1;
            float v10 = acc[mi][ni][2] + b0;
            float v11 = acc[mi][ni][3] + b1;
            if (Cadd){
                v00 += Cadd[(size_t)m*ldadd + n];     v01 += Cadd[(size_t)m*ldadd + n+1];
                v10 += Cadd[(size_t)(m+8)*ldadd + n]; v11 += Cadd[(size_t)(m+8)*ldadd + n+1];
            }
            if (Wgp){
                v00 += Wgp[n*NC + tc0];     v01 += Wgp[(n+1)*NC + tc0];
                v10 += Wgp[n*NC + tc1];     v11 += Wgp[(n+1)*NC + tc1];
            }
            if (cout){
                float p00 = __shfl_xor_sync(0xffffffffu, v00, 1);
                float p01 = __shfl_xor_sync(0xffffffffu, v01, 1);
                float p10 = __shfl_xor_sync(0xffffffffu, v10, 1);
                float p11 = __shfl_xor_sync(0xffffffffu, v11, 1);
                if ((tig & 1) == 0){
                    int j = n >> 2;
                    float c2a = fsigm(v01)*cin[(size_t)m*HS + j] + fsigm(v00)*ftanh(p00);
                    cout[(size_t)m*HS + j] = c2a;
                    hout[(size_t)m*HS + j] = __float2half(fsigm(p01)*ftanh(c2a));
                    float c2b = fsigm(v11)*cin[(size_t)(m+8)*HS + j] + fsigm(v10)*ftanh(p10);
                    cout[(size_t)(m+8)*HS + j] = c2b;
                    hout[(size_t)(m+8)*HS + j] = __float2half(fsigm(p11)*ftanh(c2b));
                }
            } else {
                C16[(size_t)m*ldc + n]       = __float2half(v00);
                C16[(size_t)m*ldc + n+1]     = __float2half(v01);
                C16[(size_t)(m+8)*ldc + n]   = __float2half(v10);
                C16[(size_t)(m+8)*ldc + n+1] = __float2half(v11);
            }
        }
    }
}

// ---------------- fp32 SIMT GEMM (prologue) ----------------------------------
__global__ void gemm_kernel(
    float* __restrict__ C, int ldc,
    const float* __restrict__ A1, int lda1, const float* __restrict__ W1, int ldw1, int K1,
    const float* __restrict__ bias1,
    const float* __restrict__ Cadd, int ldadd,
    int nn, int M, int N)
{
    __shared__ float As[16][68];
    __shared__ float Bs[16][68];
    int m0 = blockIdx.y * 64;
    int n0 = blockIdx.x * 64;
    int tid = threadIdx.x;
    int tx = tid & 15, ty = tid >> 4;

    float acc[4][4];
    #pragma unroll
    for (int i=0;i<4;i++)
        #pragma unroll
        for (int j=0;j<4;j++) acc[i][j]=0.f;

    for (int k0=0; k0<K1; k0+=16){
        #pragma unroll
        for (int i=0;i<4;i++){
            int e = i*256 + tid;
            int m = e >> 4, kk = e & 15;
            int gm = m0 + m, gk = k0 + kk;
            As[kk][m] = (gm < M && gk < K1) ? A1[(size_t)gm*lda1 + gk] : 0.f;
        }
        if (nn){
            #pragma unroll
            for (int i=0;i<4;i++){
                int e = i*256 + tid;
                int kk = e >> 6, n = e & 63;
                int gn = n0 + n, gk = k0 + kk;
                Bs[kk][n] = (gn < N && gk < K1) ? W1[(size_t)gk*ldw1 + gn] : 0.f;
            }
        } else {
            #pragma unroll
            for (int i=0;i<4;i++){
                int e = i*256 + tid;
                int n = e >> 4, kk = e & 15;
                int gn = n0 + n, gk = k0 + kk;
                Bs[kk][n] = (gn < N && gk < K1) ? W1[(size_t)gn*ldw1 + gk] : 0.f;
            }
        }
        __syncthreads();
        #pragma unroll
        for (int kk=0; kk<16; kk++){
            float4 a = *(const float4*)&As[kk][ty*4];
            float4 b = *(const float4*)&Bs[kk][tx*4];
            acc[0][0]+=a.x*b.x; acc[0][1]+=a.x*b.y; acc[0][2]+=a.x*b.z; acc[0][3]+=a.x*b.w;
            acc[1][0]+=a.y*b.x; acc[1][1]+=a.y*b.y; acc[1][2]+=a.y*b.z; acc[1][3]+=a.y*b.w;
            acc[2][0]+=a.z*b.x; acc[2][1]+=a.z*b.y; acc[2][2]+=a.z*b.z; acc[2][3]+=a.z*b.w;
            acc[3][0]+=a.w*b.x; acc[3][1]+=a.w*b.y; acc[3][2]+=a.w*b.z; acc[3][3]+=a.w*b.w;
        }
        __syncthreads();
    }

    #pragma unroll
    for (int i=0;i<4;i++){
        int m = m0 + ty*4 + i;
        if (m >= M) continue;
        #pragma unroll
        for (int j=0;j<4;j++){
            int n = n0 + tx*4 + j;
            if (n >= N) continue;
            float v = acc[i][j];
            if (bias1) v += bias1[n];
            if (Cadd)  v += Cadd[(size_t)m*ldadd + n];
            C[(size_t)m*ldc + n] = v;
        }
    }
}

// ---------------- generator GEMM (fp16 A, fp32 W), remapped output ----------
__global__ void gen_kernel(
    float* __restrict__ C,
    const __half* __restrict__ A1, const float* __restrict__ W1,
    const float* __restrict__ bias1, int M, int N)
{
    __shared__ float As[16][68];
    __shared__ float Bs[16][68];
    int m0 = blockIdx.y * 64;
    int tid = threadIdx.x;
    int tx = tid & 15, ty = tid >> 4;

    float acc[4][4];
    #pragma unroll
    for (int i=0;i<4;i++)
        #pragma unroll
        for (int j=0;j<4;j++) acc[i][j]=0.f;

    for (int k0=0; k0<HS; k0+=16){
        #pragma unroll
        for (int i=0;i<4;i++){
            int e = i*256 + tid;
            int m = e >> 4, kk = e & 15;
            int gm = m0 + m, gk = k0 + kk;
            As[kk][m] = (gm < M) ? __half2float(A1[(size_t)gm*HS + gk]) : 0.f;
        }
        #pragma unroll
        for (int i=0;i<4;i++){
            int e = i*256 + tid;
            int n = e >> 4, kk = e & 15;
            int gk = k0 + kk;
            Bs[kk][n] = (n < N) ? W1[(size_t)n*HS + gk] : 0.f;
        }
        __syncthreads();
        #pragma unroll
        for (int kk=0; kk<16; kk++){
            float4 a = *(const float4*)&As[kk][ty*4];
            float4 b = *(const float4*)&Bs[kk][tx*4];
            acc[0][0]+=a.x*b.x; acc[0][1]+=a.x*b.y; acc[0][2]+=a.x*b.z; acc[0][3]+=a.x*b.w;
            acc[1][0]+=a.y*b.x; acc[1][1]+=a.y*b.y; acc[1][2]+=a.y*b.z; acc[1][3]+=a.y*b.w;
            acc[2][0]+=a.z*b.x; acc[2][1]+=a.z*b.y; acc[2][2]+=a.z*b.z; acc[2][3]+=a.z*b.w;
            acc[3][0]+=a.w*b.x; acc[3][1]+=a.w*b.y; acc[3][2]+=a.w*b.z; acc[3][3]+=a.w*b.w;
        }
        __syncthreads();
    }

    #pragma unroll
    for (int i=0;i<4;i++){
        int m = m0 + ty*4 + i;
        if (m >= M) continue;
        int t = m >> 8, b = m & 255;
        #pragma unroll
        for (int j=0;j<4;j++){
            int n = tx*4 + j;
            if (n >= N) continue;
            C[(size_t)(b*TT + t)*NC + n] = acc[i][j] + bias1[n];
        }
    }
}

// ---------------- mean over T of batch_H ------------------------------------
__global__ void mean_kernel(const float* __restrict__ bH, float* __restrict__ out)
{
    int idx = blockIdx.x*256 + threadIdx.x;
    if (idx >= BB*INSZ) return;
    int b = idx >> 9, k = idx & 511;
    const float* p = bH + (size_t)b*TT*INSZ + k;
    float s = 0.f;
    #pragma unroll
    for (int t=0;t<TT;t++) s += p[t*INSZ];
    out[idx] = s * (1.0f/26.0f);
}

// ---------------- init h0/c0 -------------------------------------------------
__global__ void init_kernel(const float* __restrict__ hh, const float* __restrict__ hc,
                            __half* __restrict__ h1, __half* __restrict__ h2,
                            float* __restrict__ c1, float* __restrict__ c2)
{
    int idx = blockIdx.x*256 + threadIdx.x;
    if (idx >= BB*HS) return;
    float h0 = 0.5f*(hh[idx] + hh[BB*HS + idx]);
    float c0 = 0.5f*(hc[idx] + hc[BB*HS + idx]);
    h1[idx] = __float2half(h0); h2[idx] = __float2half(h0);
    c1[idx]=c0; c2[idx]=c0;
}

// ---------------- attention: 512 threads, 2 threads/position -----------------
__global__ void __launch_bounds__(512) attn_kernel(
    const __half* __restrict__ fmh, const __half* __restrict__ q,
    const float* __restrict__ ws, const float* __restrict__ sb,
    __half* __restrict__ ctx)
{
    __shared__ float qs[CH];
    __shared__ float wss[CH];
    __shared__ float epart[512];
    __shared__ float red[256];
    __shared__ float alpha[256];

    int b = blockIdx.x;
    int tid = threadIdx.x;
    int p = tid & 255;
    int hf = tid >> 8;          // 0 or 1: which channel half
    const __half* f = fmh + (size_t)b * CH * PP;

    qs[tid]  = __half2float(q[b*HS + tid]);
    wss[tid] = ws[tid];
    __syncthreads();

    // e-pass: this thread covers channels [hf*256, hf*256+256)
    {
        int c0 = hf * 256;
        float a0=0.f, a1=0.f, a2=0.f, a3=0.f;
        #pragma unroll 2
        for (int c=c0; c<c0+256; c+=4){
            float f0 = __half2float(f[(c  )*PP + p]);
            float f1 = __half2float(f[(c+1)*PP + p]);
            float f2 = __half2float(f[(c+2)*PP + p]);
            float f3 = __half2float(f[(c+3)*PP + p]);
            a0 += ftanh_hw(f0 + qs[c  ]) * wss[c  ];
            a1 += ftanh_hw(f1 + qs[c+1]) * wss[c+1];
            a2 += ftanh_hw(f2 + qs[c+2]) * wss[c+2];
            a3 += ftanh_hw(f3 + qs[c+3]) * wss[c+3];
        }
        epart[tid] = (a0+a1) + (a2+a3);
    }
    __syncthreads();

    float e = 0.f;
    if (tid < 256){
        e = epart[tid] + epart[tid + 256] + sb[0];
        red[tid] = e;
    }
    __syncthreads();
    #pragma unroll
    for (int s=128; s>0; s>>=1){
        if (tid < s) red[tid] = fmaxf(red[tid], red[tid+s]);
        __syncthreads();
    }
    float mx = red[0];
    __syncthreads();
    float ex = 0.f;
    if (tid < 256){
        ex = fexp(e - mx);
        red[tid] = ex;
    }
    __syncthreads();
    #pragma unroll
    for (int s=128; s>0; s>>=1){
        if (tid < s) red[tid] += red[tid+s];
        __syncthreads();
    }
    float sum = red[0];
    __syncthreads();
    if (tid < 256) alpha[tid] = ex * frcp(sum);
    __syncthreads();

    // context: 16 warps over 512 channels
    int lane = tid & 31, wid = tid >> 5;
    for (int c = wid; c < CH; c += 16){
        const __half* fr = f + c*PP;
        float s = 0.f;
        #pragma unroll
        for (int pp = lane; pp < PP; pp += 32) s += alpha[pp] * __half2float(fr[pp]);
        #pragma unroll
        for (int o=16; o>0; o>>=1) s += __shfl_down_sync(0xffffffffu, s, o);
        if (lane == 0) ctx[b*HS + c] = __float2half(s);
    }
}

// ---------------- host orchestration ----------------------------------------
extern "C" void kernel_launch(void* const* d_in, const int* in_sizes, int n_in,
                              void* d_out, int out_size)
{
    const float* feature_map = (const float*)d_in[0];
    const float* batch_H     = (const float*)d_in[1];
    const float* hidden_h    = (const float*)d_in[2];
    const float* hidden_c    = (const float*)d_in[3];
    const int*   text        = (const int*)  d_in[4];
    const float* i2h_w       = (const float*)d_in[5];
    const float* h2h_w       = (const float*)d_in[6];
    const float* h2h_b       = (const float*)d_in[7];
    const float* conv_m2h_w  = (const float*)d_in[8];
    const float* conv_m2h_b  = (const float*)d_in[9];
    const float* conv_h2h_w  = (const float*)d_in[10];
    const float* conv_h2h_b  = (const float*)d_in[11];
    const float* score_w     = (const float*)d_in[12];
    const float* score_b     = (const float*)d_in[13];
    const float* rnn1_w_ih   = (const float*)d_in[14];
    const float* rnn1_w_hh   = (const float*)d_in[15];
    const float* rnn1_b_ih   = (const float*)d_in[16];
    const float* rnn1_b_hh   = (const float*)d_in[17];
    const float* hlin_w      = (const float*)d_in[18];
    const float* hlin_b      = (const float*)d_in[19];
    const float* rnn2_w_ih   = (const float*)d_in[20];
    const float* rnn2_w_hh   = (const float*)d_in[21];
    const float* rnn2_b_ih   = (const float*)d_in[22];
    const float* rnn2_b_hh   = (const float*)d_in[23];
    const float* gen_w       = (const float*)d_in[24];
    const float* gen_b       = (const float*)d_in[25];
    float* out = (float*)d_out;

    __half *ahT,*bhT,*fmh,*Wq16,*hlinT16,*w2ihraw16,*W2pp16;
    __half *w1ih16,*w1hh16,*w2ih16,*w2hh16;
    __half *h1a16,*h1b16,*h2a16,*hist16,*q16,*ctx16;
    float *meanH,*bhproj,*Wq,*qb,*badd,*bias1p,*bias2p,*wgp;
    float *c1a,*c1b,*c2a,*c2b;
    cudaGetSymbolAddress((void**)&ahT, g_ahT);
    cudaGetSymbolAddress((void**)&bhT, g_bhT);
    cudaGetSymbolAddress((void**)&fmh, g_fmh);
    cudaGetSymbolAddress((void**)&meanH, g_meanH);
    cudaGetSymbolAddress((void**)&bhproj,g_bhproj);
    cudaGetSymbolAddress((void**)&Wq,    g_Wq);
    cudaGetSymbolAddress((void**)&qb,    g_qb);
    cudaGetSymbolAddress((void**)&badd,  g_badd);
    cudaGetSymbolAddress((void**)&Wq16,  g_Wq16);
    cudaGetSymbolAddress((void**)&hlinT16, g_hlinT16);
    cudaGetSymbolAddress((void**)&w2ihraw16, g_w2ihraw16);
    cudaGetSymbolAddress((void**)&W2pp16, g_W2pp16);
    cudaGetSymbolAddress((void**)&w1ih16,g_w1ih16);
    cudaGetSymbolAddress((void**)&w1hh16,g_w1hh16);
    cudaGetSymbolAddress((void**)&w2ih16,g_w2ih16);
    cudaGetSymbolAddress((void**)&w2hh16,g_w2hh16);
    cudaGetSymbolAddress((void**)&bias1p,g_bias1p);
    cudaGetSymbolAddress((void**)&bias2p,g_bias2p);
    cudaGetSymbolAddress((void**)&wgp,   g_wgp);
    cudaGetSymbolAddress((void**)&h1a16, g_h1a16);
    cudaGetSymbolAddress((void**)&h1b16, g_h1b16);
    cudaGetSymbolAddress((void**)&h2a16, g_h2a16);
    cudaGetSymbolAddress((void**)&c1a, g_c1a); cudaGetSymbolAddress((void**)&c1b, g_c1b);
    cudaGetSymbolAddress((void**)&c2a, g_c2a); cudaGetSymbolAddress((void**)&c2b, g_c2b);
    cudaGetSymbolAddress((void**)&hist16, g_hist16);
    cudaGetSymbolAddress((void**)&q16,  g_q16);
    cudaGetSymbolAddress((void**)&ctx16,g_ctx16);

    const int CONV_SMEM = 2 * 4 * 128 * CPITCH * 4;   // 81920
    cudaFuncSetAttribute(conv_fp16_kernel, cudaFuncAttributeMaxDynamicSharedMemorySize, CONV_SMEM);
    const int G16_SMEM = 4 * (GA_WORDS + GB_WORDS) * 4;  // 61440
    cudaFuncSetAttribute(gemm16_kernel, cudaFuncAttributeMaxDynamicSharedMemorySize, G16_SMEM);

    // ---- conv prep + conv ----
    padT_kernel<<<256*10*16, 256>>>(feature_map, ahT);
    wT_kernel<<<(9*CH*CH+255)/256, 256>>>(conv_m2h_w, bhT);
    conv_fp16_kernel<<<dim3(4,2,BB), 256, CONV_SMEM>>>(ahT, bhT, conv_m2h_b, fmh);

    // ---- weight packing ----
    wpack16_kernel<<<(4*HS*512+255)/256,256>>>(rnn1_w_ih, INSZ+NC, w1ih16);
    wpack16_kernel<<<(4*HS*512+255)/256,256>>>(rnn1_w_hh, HS, w1hh16);
    wpack16_kernel<<<(4*HS*512+255)/256,256>>>(rnn2_w_hh, HS, w2hh16);
    bpack_kernel<<<(4*HS+255)/256,256>>>(rnn1_b_ih, rnn1_b_hh, nullptr, bias1p);
    wgpack_kernel<<<(4*HS*NC+255)/256,256>>>(rnn1_w_ih, wgp);
    // fold hlin into rnn2_w_ih via fp16 tensor GEMM: W2pp = w2ih @ hlin
    cast16_kernel<<<(4*HS*HS+255)/256,256>>>(rnn2_w_ih, w2ihraw16, 4*HS*HS);
    transposeT16_kernel<<<256,256>>>(hlin_w, hlinT16);
    gemm16_kernel<<<dim3(4,32),256,G16_SMEM>>>(W2pp16, HS,
        w2ihraw16, hlinT16, HS, nullptr, nullptr, 0,
        nullptr, nullptr, 0, nullptr, nullptr, 0,
        nullptr, nullptr, nullptr);
    wpack16h_kernel<<<(4*HS*512+255)/256,256>>>(W2pp16, w2ih16);
    badd_kernel<<<(4*HS+255)/256,256>>>(rnn2_w_ih, hlin_b, badd);
    bpack_kernel<<<(4*HS+255)/256,256>>>(rnn2_b_ih, rnn2_b_hh, badd, bias2p);

    // ---- prologue (fp32) ----
    mean_kernel<<<512,256>>>(batch_H, meanH);
    gemm_kernel<<<dim3(8,4),256>>>(bhproj, HS, meanH, INSZ, i2h_w, INSZ, INSZ,
                                   h2h_b, nullptr,0, 0, BB, HS);
    gemm_kernel<<<dim3(8,8),256>>>(Wq, HS, conv_h2h_w, HS, h2h_w, HS, HS,
                                   nullptr, nullptr,0, 1, HS, HS);
    cast16_kernel<<<(HS*HS+255)/256,256>>>(Wq, Wq16, HS*HS);
    gemm_kernel<<<dim3(8,4),256>>>(qb, HS, bhproj, HS, conv_h2h_w, HS, HS,
                                   conv_h2h_b, nullptr,0, 0, BB, HS);
    init_kernel<<<512,256>>>(hidden_h, hidden_c, h1a16, h2a16, c1a, c2a);

    __half *h1c16=h1a16, *h1n16=h1b16, *h2c16=h2a16;
    float *c1c=c1a, *c1n=c1b, *c2c=c2a, *c2n=c2b;

    for (int t=0; t<TT; t++){
        __half* h2n16 = hist16 + (size_t)t*BB*HS;
        // q = qb + h2 @ Wq^T  (fp16 out)
        gemm16_kernel<<<dim3(4,4),256,G16_SMEM>>>(q16, HS,
            h2c16, Wq16, HS, nullptr, nullptr, 0,
            nullptr, qb, HS, nullptr, nullptr, 0,
            nullptr, nullptr, nullptr);
        // attention -> ctx (fp16), 512 threads/block
        attn_kernel<<<BB,512>>>(fmh, q16, score_w, score_b, ctx16);
        // gates1 + fused LSTM1
        gemm16_kernel<<<dim3(16,4),256,G16_SMEM>>>(nullptr, 0,
            ctx16, w1ih16, HS, h1c16, w1hh16, HS,
            bias1p, nullptr, 0, wgp, text + t, TT,
            c1c, c1n, h1n16);
        // gates2 + fused LSTM2 (hlin folded into w2ih16)
        gemm16_kernel<<<dim3(16,4),256,G16_SMEM>>>(nullptr, 0,
            h1n16, w2ih16, HS, h2c16, w2hh16, HS,
            bias2p, nullptr, 0, nullptr, nullptr, 0,
            c2c, c2n, h2n16);

        __half* tph;
        tph=h1c16; h1c16=h1n16; h1n16=tph;
        h2c16 = h2n16;
        float* tp;
        tp=c1c; c1c=c1n; c1n=tp;
        tp=c2c; c2c=c2n; c2n=tp;
    }

    // probs: one batched GEMM over all timesteps (fp16 hist), remap [b][t][n]
    gen_kernel<<<dim3(1,104),256>>>(out, hist16, gen_w, gen_b, TT*BB, NC);
}

// round 14
// speedup vs baseline: 1.3071x; 1.0884x over previous
#include <cuda_runtime.h>
#include <cuda_fp16.h>
#include <math.h>
#include <stdint.h>

#define BB 256
#define HS 512
#define INSZ 512
#define NC 38
#define TT 26
#define CH 512
#define PP 256   /* 8*32 */

// ---------------- scratch (device globals; no allocation allowed) ----------
__device__ __align__(16) __half g_ahT[(size_t)3*BB*320*CH];
__device__ __align__(16) __half g_bhT[9*CH*CH];
__device__ __align__(16) __half g_fmh[(size_t)BB*CH*PP];
__device__ float g_meanH[BB*INSZ];
__device__ float g_bhproj[BB*HS];
__device__ float g_Wq[HS*HS];
__device__ float g_qb[BB*HS];
__device__ float g_badd[4*HS];
__device__ __align__(16) __half g_Wq16[HS*HS];
__device__ __align__(16) __half g_hlinT16[HS*HS];
__device__ __align__(16) __half g_w2ihraw16[4*HS*HS];
__device__ __align__(16) __half g_W2pp16[4*HS*HS];
__device__ __align__(16) __half g_w1ih16[4*HS*INSZ];
__device__ __align__(16) __half g_w1hh16[4*HS*HS];
__device__ __align__(16) __half g_w2ih16[4*HS*HS];
__device__ __align__(16) __half g_w2hh16[4*HS*HS];
__device__ float g_bias1p[4*HS], g_bias2p[4*HS];
__device__ float g_wgp[4*HS*NC];
__device__ __align__(16) __half g_h1a16[BB*HS], g_h1b16[BB*HS], g_h2a16[BB*HS];
__device__ float g_c1a[BB*HS], g_c1b[BB*HS], g_c2a[BB*HS], g_c2b[BB*HS];
__device__ __align__(16) __half g_hist16[(size_t)TT*BB*HS];
__device__ __align__(16) __half g_q16[BB*HS];
__device__ __align__(16) __half g_ctx16[BB*HS];

// ---------------- fast math ------------------------------------------------
__device__ __forceinline__ float fexp(float x){
    float y; asm("ex2.approx.f32 %0, %1;" : "=f"(y) : "f"(x*1.4426950408889634f)); return y;
}
__device__ __forceinline__ float frcp(float x){
    float y; asm("rcp.approx.f32 %0, %1;" : "=f"(y) : "f"(x)); return y;
}
__device__ __forceinline__ float ftanh(float x){
    float xc = fminf(fmaxf(x, -15.f), 15.f);
    float t = fexp(2.f*xc);
    return (t - 1.f) * frcp(t + 1.f);
}
__device__ __forceinline__ float ftanh_hw(float x){
    float y; asm("tanh.approx.f32 %0, %1;" : "=f"(y) : "f"(x)); return y;
}
__device__ __forceinline__ float fsigm(float x){
    return frcp(1.f + fexp(-x));
}
__device__ __forceinline__ void mma_fp16(float* d, const uint32_t* a, const uint32_t* b){
    asm volatile(
      "mma.sync.aligned.m16n8k16.row.col.f32.f16.f16.f32 "
      "{%0,%1,%2,%3},{%4,%5,%6,%7},{%8,%9},{%0,%1,%2,%3};"
      : "+f"(d[0]),"+f"(d[1]),"+f"(d[2]),"+f"(d[3])
      : "r"(a[0]),"r"(a[1]),"r"(a[2]),"r"(a[3]), "r"(b[0]),"r"(b[1]));
}
__device__ __forceinline__ void ldsm4(uint32_t* r, uint32_t saddr){
    asm volatile("ldmatrix.sync.aligned.m8n8.x4.shared.b16 {%0,%1,%2,%3}, [%4];"
      : "=r"(r[0]),"=r"(r[1]),"=r"(r[2]),"=r"(r[3]) : "r"(saddr));
}

// ---------------- prep kernels ------------------------------------------------
__global__ void padT_kernel(const float* __restrict__ in, __half* __restrict__ oh)
{
    __shared__ float s[32][33];
    int blk = blockIdx.x;
    int icb = blk & 15;
    int rr  = (blk >> 4) % 10;
    int b   = blk >> 4; b /= 10;
    int t = threadIdx.x;
    int r = rr - 1;

    if ((unsigned)r < 8u){
        int c = t & 31, icq = t >> 5;
        #pragma unroll
        for (int j=0;j<4;j++){
            int ic = icq + j*8;
            s[ic][c] = in[((size_t)b*CH + icb*32 + ic)*PP + r*32 + c];
        }
    }
    __syncthreads();

    int icl = t & 31, cq = t >> 5;
    #pragma unroll
    for (int j=0;j<4;j++){
        int c = cq + j*8;
        #pragma unroll
        for (int kw=0; kw<3; kw++){
            int cc = c + kw - 1;
            float v = 0.f;
            if ((unsigned)r < 8u && (unsigned)cc < 32u) v = s[icl][cc];
            size_t off = (((size_t)kw*BB + b)*320 + rr*32 + c)*CH + icb*32 + icl;
            oh[off] = __float2half(v);
        }
    }
}

__global__ void wT_kernel(const float* __restrict__ w, __half* __restrict__ oh)
{
    int idx = blockIdx.x*256 + threadIdx.x;
    if (idx >= 9*CH*CH) return;
    int ic = idx & 511;
    int oc = (idx >> 9) & 511;
    int khw = idx >> 18;
    oh[((size_t)khw*CH + oc)*CH + ic] = __float2half(w[((size_t)oc*CH + ic)*9 + khw]);
}

__global__ void cast16_kernel(const float* __restrict__ in, __half* __restrict__ out, int n)
{
    int idx = blockIdx.x*256 + threadIdx.x;
    if (idx < n) out[idx] = __float2half(in[idx]);
}

__global__ void transposeT16_kernel(const float* __restrict__ in, __half* __restrict__ out)
{
    __shared__ float s[32][33];
    int bx = blockIdx.x & 15, by = blockIdx.x >> 4;
    int tx = threadIdx.x & 31, ty = threadIdx.x >> 5;
    #pragma unroll
    for (int i=0;i<4;i++){
        int n = bx*32 + ty + i*8;
        s[ty+i*8][tx] = in[(size_t)n*HS + by*32 + tx];
    }
    __syncthreads();
    #pragma unroll
    for (int i=0;i<4;i++){
        int k = by*32 + ty + i*8;
        out[(size_t)k*HS + bx*32 + tx] = __float2half(s[tx][ty+i*8]);
    }
}

__global__ void wpack16_kernel(const float* __restrict__ w, int ldw, __half* __restrict__ out)
{
    int idx = blockIdx.x*256 + threadIdx.x;
    if (idx >= 4*HS*512) return;
    int k = idx & 511;
    int row = idx >> 9;
    int j = row >> 2, g = row & 3;
    out[idx] = __float2half(w[(size_t)(g*HS + j)*ldw + k]);
}

__global__ void wpack16h_kernel(const __half* __restrict__ w, __half* __restrict__ out)
{
    int idx = blockIdx.x*256 + threadIdx.x;
    if (idx >= 4*HS*512) return;
    int k = idx & 511;
    int row = idx >> 9;
    int j = row >> 2, g = row & 3;
    out[idx] = w[(size_t)(g*HS + j)*512 + k];
}

__global__ void bpack_kernel(const float* __restrict__ bih, const float* __restrict__ bhh,
                             const float* __restrict__ badd, float* __restrict__ out)
{
    int row = blockIdx.x*256 + threadIdx.x;
    if (row >= 4*HS) return;
    int j = row >> 2, g = row & 3;
    float v = bih[g*HS + j] + bhh[g*HS + j];
    if (badd) v += badd[g*HS + j];
    out[row] = v;
}

__global__ void wgpack_kernel(const float* __restrict__ w, float* __restrict__ out)
{
    int idx = blockIdx.x*256 + threadIdx.x;
    if (idx >= 4*HS*NC) return;
    int c = idx % NC;
    int row = idx / NC;
    int j = row >> 2, g = row & 3;
    out[idx] = w[(size_t)(g*HS + j)*(INSZ+NC) + INSZ + c];
}

__global__ void badd_kernel(const float* __restrict__ w2ih, const float* __restrict__ hlinb,
                            float* __restrict__ out)
{
    int m = blockIdx.x*256 + threadIdx.x;
    if (m >= 4*HS) return;
    const float* wr = w2ih + (size_t)m*HS;
    float s = 0.f;
    #pragma unroll 8
    for (int k=0;k<HS;k++) s += wr[k]*hlinb[k];
    out[m] = s;
}

// ---------------- conv 3x3 SAME via fp16 mma + ldmatrix ----------------------
#define CPITCH 20
#define CSTAGE_W (128*CPITCH)

__global__ void __launch_bounds__(256, 2) conv_fp16_kernel(
    const __half* __restrict__ Ag, const __half* __restrict__ Bg,
    const float* __restrict__ bias, __half* __restrict__ out)
{
    extern __shared__ __align__(16) uint32_t sm[];
    uint32_t* Asm = sm;
    uint32_t* Bsm = sm + 4*CSTAGE_W;
    const int b  = blockIdx.z;
    const int m0 = blockIdx.y * 128;
    const int n0 = blockIdx.x * 128;
    const int tid = threadIdx.x;
    const int lane = tid & 31, warp = tid >> 5;
    const int wm = (warp >> 2) * 64;
    const int wn = (warp & 3) * 32;
    const int gid = lane >> 2, tig = lane & 3;

    const int lrow = tid >> 1;
    const int lch  = tid & 1;

    // ldmatrix lane-address components
    const int a_row = (lane & 15);
    const int a_kh  = (lane >> 4) * 4;
    const int b_row = (lane & 7) + (lane >> 4) * 8;
    const int b_kh  = ((lane >> 3) & 1) * 4;

    float acc[4][4][4];
    #pragma unroll
    for (int i=0;i<4;i++)
      #pragma unroll
      for (int j=0;j<4;j++)
        #pragma unroll
        for (int k=0;k<4;k++) acc[i][j][k]=0.f;

    uint32_t sAb = (uint32_t)__cvta_generic_to_shared(Asm);
    uint32_t sBb = (uint32_t)__cvta_generic_to_shared(Bsm);

#define CLOAD(s) do { \
        int st_  = (s) & 3; \
        int khw_ = (s) >> 4; \
        int ic0_ = ((s) & 15) << 5; \
        int kh_ = khw_ / 3, kw_ = khw_ - kh_*3; \
        const __half* ap_ = Ag + (((size_t)kw_*BB + b)*320 + m0 + kh_*32 + lrow)*CH + ic0_ + lch*8; \
        const __half* bp_ = Bg + ((size_t)khw_*CH + n0 + lrow)*CH + ic0_ + lch*8; \
        uint32_t da_ = sAb + (uint32_t)(((st_*128 + lrow)*CPITCH + lch*4)*4); \
        uint32_t db_ = sBb + (uint32_t)(((st_*128 + lrow)*CPITCH + lch*4)*4); \
        asm volatile("cp.async.cg.shared.global [%0], [%1], 16;" :: "r"(da_),      "l"(ap_)); \
        asm volatile("cp.async.cg.shared.global [%0], [%1], 16;" :: "r"(da_ + 32), "l"(ap_ + 16)); \
        asm volatile("cp.async.cg.shared.global [%0], [%1], 16;" :: "r"(db_),      "l"(bp_)); \
        asm volatile("cp.async.cg.shared.global [%0], [%1], 16;" :: "r"(db_ + 32), "l"(bp_ + 16)); \
        asm volatile("cp.async.commit_group;"); \
    } while(0)

    CLOAD(0); CLOAD(1); CLOAD(2);

    for (int s = 0; s < 144; ++s){
        asm volatile("cp.async.wait_group 2;");
        __syncthreads();
        if (s + 3 < 144) CLOAD(s + 3);

        const uint32_t stoff = (uint32_t)((s & 3) * CSTAGE_W * 4);
        const uint32_t Aoff = sAb + stoff;
        const uint32_t Boff = sBb + stoff;

        #pragma unroll
        for (int h = 0; h < 2; ++h){
            uint32_t afr[4][4], bfr[4][2];
            #pragma unroll
            for (int mi=0; mi<4; ++mi){
                uint32_t addr = Aoff + (uint32_t)((((wm + mi*16 + a_row)*CPITCH) + h*8 + a_kh)*4);
                ldsm4(afr[mi], addr);
            }
            #pragma unroll
            for (int nj=0; nj<2; ++nj){
                uint32_t r[4];
                uint32_t addr = Boff + (uint32_t)((((wn + nj*16 + b_row)*CPITCH) + h*8 + b_kh)*4);
                ldsm4(r, addr);
                bfr[nj*2  ][0] = r[0]; bfr[nj*2  ][1] = r[1];
                bfr[nj*2+1][0] = r[2]; bfr[nj*2+1][1] = r[3];
            }
            #pragma unroll
            for (int mi=0; mi<4; ++mi)
                #pragma unroll
                for (int ni=0; ni<4; ++ni)
                    mma_fp16(acc[mi][ni], afr[mi], bfr[ni]);
        }
    }
#undef CLOAD

    #pragma unroll
    for (int mi=0; mi<4; ++mi){
        int prow = m0 + wm + mi*16 + gid;
        #pragma unroll
        for (int ni=0; ni<4; ++ni){
            int oc = n0 + wn + ni*8 + tig*2;
            float bz0 = bias[oc], bz1 = bias[oc+1];
            __half* o0 = out + ((size_t)b*CH + oc)*PP;
            o0[prow]          = __float2half(acc[mi][ni][0] + bz0);
            o0[PP + prow]     = __float2half(acc[mi][ni][1] + bz1);
            o0[prow + 8]      = __float2half(acc[mi][ni][2] + bz0);
            o0[PP + prow + 8] = __float2half(acc[mi][ni][3] + bz1);
        }
    }
}

// ---------------- fp16 step GEMM (+optional fused LSTM epilogue) -------------
#define GPITCH 20
#define GA_WORDS (64*GPITCH)
#define GB_WORDS (128*GPITCH)

__global__ void __launch_bounds__(256, 2) gemm16_kernel(
    __half* __restrict__ C16, int ldc,
    const __half* __restrict__ A1, const __half* __restrict__ W1, int K1,
    const __half* __restrict__ A2, const __half* __restrict__ W2, int K2,
    const float* __restrict__ bias, const float* __restrict__ Cadd, int ldadd,
    const float* __restrict__ Wgp, const int* __restrict__ textcol, int textstride,
    const float* __restrict__ cin, float* __restrict__ cout, __half* __restrict__ hout)
{
    extern __shared__ __align__(16) uint32_t sm[];
    uint32_t* Asm = sm;                  // [4][64][20]
    uint32_t* Bsm = sm + 4*GA_WORDS;     // [4][128][20]
    const int m0 = blockIdx.y * 64;
    const int n0 = blockIdx.x * 128;
    const int tid = threadIdx.x;
    const int lane = tid & 31, warp = tid >> 5;
    const int wm = (warp >> 2) * 32;
    const int wn = (warp & 3) * 32;
    const int gid = lane >> 2, tig = lane & 3;

    const int a_row = (lane & 15);
    const int a_kh  = (lane >> 4) * 4;
    const int b_row = (lane & 7) + (lane >> 4) * 8;
    const int b_kh  = ((lane >> 3) & 1) * 4;

    const int S1 = K1 >> 5;
    const int S2 = (A2 != nullptr) ? (K2 >> 5) : 0;
    const int S  = S1 + S2;

    float acc[2][4][4];
    #pragma unroll
    for (int i=0;i<2;i++)
      #pragma unroll
      for (int j=0;j<4;j++)
        #pragma unroll
        for (int k=0;k<4;k++) acc[i][j][k]=0.f;

    uint32_t sAb = (uint32_t)__cvta_generic_to_shared(Asm);
    uint32_t sBb = (uint32_t)__cvta_generic_to_shared(Bsm);

#define GLOAD(s) do { \
        int st_ = (s) & 3; int s_ = (s); \
        const __half* A_; const __half* W_; int k0_; \
        if (s_ < S1){ A_ = A1; W_ = W1; k0_ = s_ << 5; } \
        else        { A_ = A2; W_ = W2; k0_ = (s_ - S1) << 5; } \
        const __half* ap_ = A_ + (size_t)(m0 + (tid>>2))*512 + k0_ + (tid&3)*8; \
        uint32_t da_ = sAb + (uint32_t)(((st_*64 + (tid>>2))*GPITCH + (tid&3)*4)*4); \
        asm volatile("cp.async.cg.shared.global [%0], [%1], 16;" :: "r"(da_), "l"(ap_)); \
        const __half* bp_ = W_ + (size_t)(n0 + (tid>>1))*512 + k0_ + (tid&1)*16; \
        uint32_t db_ = sBb + (uint32_t)(((st_*128 + (tid>>1))*GPITCH + (tid&1)*8)*4); \
        asm volatile("cp.async.cg.shared.global [%0], [%1], 16;" :: "r"(db_),      "l"(bp_)); \
        asm volatile("cp.async.cg.shared.global [%0], [%1], 16;" :: "r"(db_ + 16), "l"(bp_ + 8)); \
        asm volatile("cp.async.commit_group;"); \
    } while(0)

    GLOAD(0); GLOAD(1); GLOAD(2);

    for (int s = 0; s < S; ++s){
        asm volatile("cp.async.wait_group 2;");
        __syncthreads();
        if (s + 3 < S) GLOAD(s + 3);

        const uint32_t Aoff = sAb + (uint32_t)((s & 3) * GA_WORDS * 4);
        const uint32_t Boff = sBb + (uint32_t)((s & 3) * GB_WORDS * 4);

        #pragma unroll
        for (int h = 0; h < 2; ++h){
            uint32_t afr[2][4], bfr[4][2];
            #pragma unroll
            for (int mi=0; mi<2; ++mi){
                uint32_t addr = Aoff + (uint32_t)((((wm + mi*16 + a_row)*GPITCH) + h*8 + a_kh)*4);
                ldsm4(afr[mi], addr);
            }
            #pragma unroll
            for (int nj=0; nj<2; ++nj){
                uint32_t r[4];
                uint32_t addr = Boff + (uint32_t)((((wn + nj*16 + b_row)*GPITCH) + h*8 + b_kh)*4);
                ldsm4(r, addr);
                bfr[nj*2  ][0] = r[0]; bfr[nj*2  ][1] = r[1];
                bfr[nj*2+1][0] = r[2]; bfr[nj*2+1][1] = r[3];
            }
            #pragma unroll
            for (int mi=0; mi<2; ++mi)
                #pragma unroll
                for (int ni=0; ni<4; ++ni)
                    mma_fp16(acc[mi][ni], afr[mi], bfr[ni]);
        }
    }
#undef GLOAD

    #pragma unroll
    for (int mi=0; mi<2; ++mi){
        int m = m0 + wm + mi*16 + gid;
        int tc0 = 0, tc1 = 0;
        if (Wgp){ tc0 = textcol[m*textstride]; tc1 = textcol[(m+8)*textstride]; }
        #pragma unroll
        for (int ni=0; ni<4; ++ni){
            int n = n0 + wn + ni*8 + tig*2;
            float b0 = 0.f, b1 = 0.f;
            if (bias){ b0 = bias[n]; b1 = bias[n+1]; }
            float v00 = acc[mi][ni][0] + b0;
            float v01 = acc[mi][ni][1] + b1;
            float v10 = acc[mi][ni][2] + b0;
            float v11 = acc[mi][ni][3] + b1;
            if (Cadd){
                v00 += Cadd[(size_t)m*ldadd + n];     v01 += Cadd[(size_t)m*ldadd + n+1];
                v10 += Cadd[(size_t)(m+8)*ldadd + n]; v11 += Cadd[(size_t)(m+8)*ldadd + n+1];
            }
            if (Wgp){
                v00 += Wgp[n*NC + tc0];     v01 += Wgp[(n+1)*NC + tc0];
                v10 += Wgp[n*NC + tc1];     v11 += Wgp[(n+1)*NC + tc1];
            }
            if (cout){
                float p00 = __shfl_xor_sync(0xffffffffu, v00, 1);
                float p01 = __shfl_xor_sync(0xffffffffu, v01, 1);
                float p10 = __shfl_xor_sync(0xffffffffu, v10, 1);
                float p11 = __shfl_xor_sync(0xffffffffu, v11, 1);
                if ((tig & 1) == 0){
                    int j = n >> 2;
                    float c2a = fsigm(v01)*cin[(size_t)m*HS + j] + fsigm(v00)*ftanh(p00);
                    cout[(size_t)m*HS + j] = c2a;
                    hout[(size_t)m*HS + j] = __float2half(fsigm(p01)*ftanh(c2a));
                    float c2b = fsigm(v11)*cin[(size_t)(m+8)*HS + j] + fsigm(v10)*ftanh(p10);
                    cout[(size_t)(m+8)*HS + j] = c2b;
                    hout[(size_t)(m+8)*HS + j] = __float2half(fsigm(p11)*ftanh(c2b));
                }
            } else {
                C16[(size_t)m*ldc + n]       = __float2half(v00);
                C16[(size_t)m*ldc + n+1]     = __float2half(v01);
                C16[(size_t)(m+8)*ldc + n]   = __float2half(v10);
                C16[(size_t)(m+8)*ldc + n+1] = __float2half(v11);
            }
        }
    }
}

// ---------------- fp32 SIMT GEMM (prologue) ----------------------------------
__global__ void gemm_kernel(
    float* __restrict__ C, int ldc,
    const float* __restrict__ A1, int lda1, const float* __restrict__ W1, int ldw1, int K1,
    const float* __restrict__ bias1,
    const float* __restrict__ Cadd, int ldadd,
    int nn, int M, int N)
{
    __shared__ float As[16][68];
    __shared__ float Bs[16][68];
    int m0 = blockIdx.y * 64;
    int n0 = blockIdx.x * 64;
    int tid = threadIdx.x;
    int tx = tid & 15, ty = tid >> 4;

    float acc[4][4];
    #pragma unroll
    for (int i=0;i<4;i++)
        #pragma unroll
        for (int j=0;j<4;j++) acc[i][j]=0.f;

    for (int k0=0; k0<K1; k0+=16){
        #pragma unroll
        for (int i=0;i<4;i++){
            int e = i*256 + tid;
            int m = e >> 4, kk = e & 15;
            int gm = m0 + m, gk = k0 + kk;
            As[kk][m] = (gm < M && gk < K1) ? A1[(size_t)gm*lda1 + gk] : 0.f;
        }
        if (nn){
            #pragma unroll
            for (int i=0;i<4;i++){
                int e = i*256 + tid;
                int kk = e >> 6, n = e & 63;
                int gn = n0 + n, gk = k0 + kk;
                Bs[kk][n] = (gn < N && gk < K1) ? W1[(size_t)gk*ldw1 + gn] : 0.f;
            }
        } else {
            #pragma unroll
            for (int i=0;i<4;i++){
                int e = i*256 + tid;
                int n = e >> 4, kk = e & 15;
                int gn = n0 + n, gk = k0 + kk;
                Bs[kk][n] = (gn < N && gk < K1) ? W1[(size_t)gn*ldw1 + gk] : 0.f;
            }
        }
        __syncthreads();
        #pragma unroll
        for (int kk=0; kk<16; kk++){
            float4 a = *(const float4*)&As[kk][ty*4];
            float4 b = *(const float4*)&Bs[kk][tx*4];
            acc[0][0]+=a.x*b.x; acc[0][1]+=a.x*b.y; acc[0][2]+=a.x*b.z; acc[0][3]+=a.x*b.w;
            acc[1][0]+=a.y*b.x; acc[1][1]+=a.y*b.y; acc[1][2]+=a.y*b.z; acc[1][3]+=a.y*b.w;
            acc[2][0]+=a.z*b.x; acc[2][1]+=a.z*b.y; acc[2][2]+=a.z*b.z; acc[2][3]+=a.z*b.w;
            acc[3][0]+=a.w*b.x; acc[3][1]+=a.w*b.y; acc[3][2]+=a.w*b.z; acc[3][3]+=a.w*b.w;
        }
        __syncthreads();
    }

    #pragma unroll
    for (int i=0;i<4;i++){
        int m = m0 + ty*4 + i;
        if (m >= M) continue;
        #pragma unroll
        for (int j=0;j<4;j++){
            int n = n0 + tx*4 + j;
            if (n >= N) continue;
            float v = acc[i][j];
            if (bias1) v += bias1[n];
            if (Cadd)  v += Cadd[(size_t)m*ldadd + n];
            C[(size_t)m*ldc + n] = v;
        }
    }
}

// ---------------- generator GEMM (fp16 A, fp32 W), remapped output ----------
__global__ void gen_kernel(
    float* __restrict__ C,
    const __half* __restrict__ A1, const float* __restrict__ W1,
    const float* __restrict__ bias1, int M, int N)
{
    __shared__ float As[16][68];
    __shared__ float Bs[16][68];
    int m0 = blockIdx.y * 64;
    int tid = threadIdx.x;
    int tx = tid & 15, ty = tid >> 4;

    float acc[4][4];
    #pragma unroll
    for (int i=0;i<4;i++)
        #pragma unroll
        for (int j=0;j<4;j++) acc[i][j]=0.f;

    for (int k0=0; k0<HS; k0+=16){
        #pragma unroll
        for (int i=0;i<4;i++){
            int e = i*256 + tid;
            int m = e >> 4, kk = e & 15;
            int gm = m0 + m, gk = k0 + kk;
            As[kk][m] = (gm < M) ? __half2float(A1[(size_t)gm*HS + gk]) : 0.f;
        }
        #pragma unroll
        for (int i=0;i<4;i++){
            int e = i*256 + tid;
            int n = e >> 4, kk = e & 15;
            int gk = k0 + kk;
            Bs[kk][n] = (n < N) ? W1[(size_t)n*HS + gk] : 0.f;
        }
        __syncthreads();
        #pragma unroll
        for (int kk=0; kk<16; kk++){
            float4 a = *(const float4*)&As[kk][ty*4];
            float4 b = *(const float4*)&Bs[kk][tx*4];
            acc[0][0]+=a.x*b.x; acc[0][1]+=a.x*b.y; acc[0][2]+=a.x*b.z; acc[0][3]+=a.x*b.w;
            acc[1][0]+=a.y*b.x; acc[1][1]+=a.y*b.y; acc[1][2]+=a.y*b.z; acc[1][3]+=a.y*b.w;
            acc[2][0]+=a.z*b.x; acc[2][1]+=a.z*b.y; acc[2][2]+=a.z*b.z; acc[2][3]+=a.z*b.w;
            acc[3][0]+=a.w*b.x; acc[3][1]+=a.w*b.y; acc[3][2]+=a.w*b.z; acc[3][3]+=a.w*b.w;
        }
        __syncthreads();
    }

    #pragma unroll
    for (int i=0;i<4;i++){
        int m = m0 + ty*4 + i;
        if (m >= M) continue;
        int t = m >> 8, b = m & 255;
        #pragma unroll
        for (int j=0;j<4;j++){
            int n = tx*4 + j;
            if (n >= N) continue;
            C[(size_t)(b*TT + t)*NC + n] = acc[i][j] + bias1[n];
        }
    }
}

// ---------------- mean over T of batch_H ------------------------------------
__global__ void mean_kernel(const float* __restrict__ bH, float* __restrict__ out)
{
    int idx = blockIdx.x*256 + threadIdx.x;
    if (idx >= BB*INSZ) return;
    int b = idx >> 9, k = idx & 511;
    const float* p = bH + (size_t)b*TT*INSZ + k;
    float s = 0.f;
    #pragma unroll
    for (int t=0;t<TT;t++) s += p[t*INSZ];
    out[idx] = s * (1.0f/26.0f);
}

// ---------------- init h0/c0 -------------------------------------------------
__global__ void init_kernel(const float* __restrict__ hh, const float* __restrict__ hc,
                            __half* __restrict__ h1, __half* __restrict__ h2,
                            float* __restrict__ c1, float* __restrict__ c2)
{
    int idx = blockIdx.x*256 + threadIdx.x;
    if (idx >= BB*HS) return;
    float h0 = 0.5f*(hh[idx] + hh[BB*HS + idx]);
    float c0 = 0.5f*(hc[idx] + hc[BB*HS + idx]);
    h1[idx] = __float2half(h0); h2[idx] = __float2half(h0);
    c1[idx]=c0; c2[idx]=c0;
}

// ---------------- attention: 512 threads, 2 threads/position -----------------
__global__ void __launch_bounds__(512) attn_kernel(
    const __half* __restrict__ fmh, const __half* __restrict__ q,
    const float* __restrict__ ws, const float* __restrict__ sb,
    __half* __restrict__ ctx)
{
    __shared__ float qs[CH];
    __shared__ float wss[CH];
    __shared__ float epart[512];
    __shared__ float red[256];
    __shared__ float alpha[256];

    int b = blockIdx.x;
    int tid = threadIdx.x;
    int p = tid & 255;
    int hf = tid >> 8;
    const __half* f = fmh + (size_t)b * CH * PP;

    qs[tid]  = __half2float(q[b*HS + tid]);
    wss[tid] = ws[tid];
    __syncthreads();

    {
        int c0 = hf * 256;
        float a0=0.f, a1=0.f, a2=0.f, a3=0.f;
        #pragma unroll 2
        for (int c=c0; c<c0+256; c+=4){
            float f0 = __half2float(f[(c  )*PP + p]);
            float f1 = __half2float(f[(c+1)*PP + p]);
            float f2 = __half2float(f[(c+2)*PP + p]);
            float f3 = __half2float(f[(c+3)*PP + p]);
            a0 += ftanh_hw(f0 + qs[c  ]) * wss[c  ];
            a1 += ftanh_hw(f1 + qs[c+1]) * wss[c+1];
            a2 += ftanh_hw(f2 + qs[c+2]) * wss[c+2];
            a3 += ftanh_hw(f3 + qs[c+3]) * wss[c+3];
        }
        epart[tid] = (a0+a1) + (a2+a3);
    }
    __syncthreads();

    float e = 0.f;
    if (tid < 256){
        e = epart[tid] + epart[tid + 256] + sb[0];
        red[tid] = e;
    }
    __syncthreads();
    #pragma unroll
    for (int s=128; s>0; s>>=1){
        if (tid < s) red[tid] = fmaxf(red[tid], red[tid+s]);
        __syncthreads();
    }
    float mx = red[0];
    __syncthreads();
    float ex = 0.f;
    if (tid < 256){
        ex = fexp(e - mx);
        red[tid] = ex;
    }
    __syncthreads();
    #pragma unroll
    for (int s=128; s>0; s>>=1){
        if (tid < s) red[tid] += red[tid+s];
        __syncthreads();
    }
    float sum = red[0];
    __syncthreads();
    if (tid < 256) alpha[tid] = ex * frcp(sum);
    __syncthreads();

    int lane = tid & 31, wid = tid >> 5;
    for (int c = wid; c < CH; c += 16){
        const __half* fr = f + c*PP;
        float s = 0.f;
        #pragma unroll
        for (int pp = lane; pp < PP; pp += 32) s += alpha[pp] * __half2float(fr[pp]);
        #pragma unroll
        for (int o=16; o>0; o>>=1) s += __shfl_down_sync(0xffffffffu, s, o);
        if (lane == 0) ctx[b*HS + c] = __float2half(s);
    }
}

// ---------------- host orchestration ----------------------------------------
extern "C" void kernel_launch(void* const* d_in, const int* in_sizes, int n_in,
                              void* d_out, int out_size)
{
    const float* feature_map = (const float*)d_in[0];
    const float* batch_H     = (const float*)d_in[1];
    const float* hidden_h    = (const float*)d_in[2];
    const float* hidden_c    = (const float*)d_in[3];
    const int*   text        = (const int*)  d_in[4];
    const float* i2h_w       = (const float*)d_in[5];
    const float* h2h_w       = (const float*)d_in[6];
    const float* h2h_b       = (const float*)d_in[7];
    const float* conv_m2h_w  = (const float*)d_in[8];
    const float* conv_m2h_b  = (const float*)d_in[9];
    const float* conv_h2h_w  = (const float*)d_in[10];
    const float* conv_h2h_b  = (const float*)d_in[11];
    const float* score_w     = (const float*)d_in[12];
    const float* score_b     = (const float*)d_in[13];
    const float* rnn1_w_ih   = (const float*)d_in[14];
    const float* rnn1_w_hh   = (const float*)d_in[15];
    const float* rnn1_b_ih   = (const float*)d_in[16];
    const float* rnn1_b_hh   = (const float*)d_in[17];
    const float* hlin_w      = (const float*)d_in[18];
    const float* hlin_b      = (const float*)d_in[19];
    const float* rnn2_w_ih   = (const float*)d_in[20];
    const float* rnn2_w_hh   = (const float*)d_in[21];
    const float* rnn2_b_ih   = (const float*)d_in[22];
    const float* rnn2_b_hh   = (const float*)d_in[23];
    const float* gen_w       = (const float*)d_in[24];
    const float* gen_b       = (const float*)d_in[25];
    float* out = (float*)d_out;

    __half *ahT,*bhT,*fmh,*Wq16,*hlinT16,*w2ihraw16,*W2pp16;
    __half *w1ih16,*w1hh16,*w2ih16,*w2hh16;
    __half *h1a16,*h1b16,*h2a16,*hist16,*q16,*ctx16;
    float *meanH,*bhproj,*Wq,*qb,*badd,*bias1p,*bias2p,*wgp;
    float *c1a,*c1b,*c2a,*c2b;
    cudaGetSymbolAddress((void**)&ahT, g_ahT);
    cudaGetSymbolAddress((void**)&bhT, g_bhT);
    cudaGetSymbolAddress((void**)&fmh, g_fmh);
    cudaGetSymbolAddress((void**)&meanH, g_meanH);
    cudaGetSymbolAddress((void**)&bhproj,g_bhproj);
    cudaGetSymbolAddress((void**)&Wq,    g_Wq);
    cudaGetSymbolAddress((void**)&qb,    g_qb);
    cudaGetSymbolAddress((void**)&badd,  g_badd);
    cudaGetSymbolAddress((void**)&Wq16,  g_Wq16);
    cudaGetSymbolAddress((void**)&hlinT16, g_hlinT16);
    cudaGetSymbolAddress((void**)&w2ihraw16, g_w2ihraw16);
    cudaGetSymbolAddress((void**)&W2pp16, g_W2pp16);
    cudaGetSymbolAddress((void**)&w1ih16,g_w1ih16);
    cudaGetSymbolAddress((void**)&w1hh16,g_w1hh16);
    cudaGetSymbolAddress((void**)&w2ih16,g_w2ih16);
    cudaGetSymbolAddress((void**)&w2hh16,g_w2hh16);
    cudaGetSymbolAddress((void**)&bias1p,g_bias1p);
    cudaGetSymbolAddress((void**)&bias2p,g_bias2p);
    cudaGetSymbolAddress((void**)&wgp,   g_wgp);
    cudaGetSymbolAddress((void**)&h1a16, g_h1a16);
    cudaGetSymbolAddress((void**)&h1b16, g_h1b16);
    cudaGetSymbolAddress((void**)&h2a16, g_h2a16);
    cudaGetSymbolAddress((void**)&c1a, g_c1a); cudaGetSymbolAddress((void**)&c1b, g_c1b);
    cudaGetSymbolAddress((void**)&c2a, g_c2a); cudaGetSymbolAddress((void**)&c2b, g_c2b);
    cudaGetSymbolAddress((void**)&hist16, g_hist16);
    cudaGetSymbolAddress((void**)&q16,  g_q16);
    cudaGetSymbolAddress((void**)&ctx16,g_ctx16);

    const int CONV_SMEM = 2 * 4 * 128 * CPITCH * 4;   // 81920
    cudaFuncSetAttribute(conv_fp16_kernel, cudaFuncAttributeMaxDynamicSharedMemorySize, CONV_SMEM);
    const int G16_SMEM = 4 * (GA_WORDS + GB_WORDS) * 4;  // 61440
    cudaFuncSetAttribute(gemm16_kernel, cudaFuncAttributeMaxDynamicSharedMemorySize, G16_SMEM);

    // ---- conv prep + conv ----
    padT_kernel<<<256*10*16, 256>>>(feature_map, ahT);
    wT_kernel<<<(9*CH*CH+255)/256, 256>>>(conv_m2h_w, bhT);
    conv_fp16_kernel<<<dim3(4,2,BB), 256, CONV_SMEM>>>(ahT, bhT, conv_m2h_b, fmh);

    // ---- weight packing ----
    wpack16_kernel<<<(4*HS*512+255)/256,256>>>(rnn1_w_ih, INSZ+NC, w1ih16);
    wpack16_kernel<<<(4*HS*512+255)/256,256>>>(rnn1_w_hh, HS, w1hh16);
    wpack16_kernel<<<(4*HS*512+255)/256,256>>>(rnn2_w_hh, HS, w2hh16);
    bpack_kernel<<<(4*HS+255)/256,256>>>(rnn1_b_ih, rnn1_b_hh, nullptr, bias1p);
    wgpack_kernel<<<(4*HS*NC+255)/256,256>>>(rnn1_w_ih, wgp);
    cast16_kernel<<<(4*HS*HS+255)/256,256>>>(rnn2_w_ih, w2ihraw16, 4*HS*HS);
    transposeT16_kernel<<<256,256>>>(hlin_w, hlinT16);
    gemm16_kernel<<<dim3(4,32),256,G16_SMEM>>>(W2pp16, HS,
        w2ihraw16, hlinT16, HS, nullptr, nullptr, 0,
        nullptr, nullptr, 0, nullptr, nullptr, 0,
        nullptr, nullptr, nullptr);
    wpack16h_kernel<<<(4*HS*512+255)/256,256>>>(W2pp16, w2ih16);
    badd_kernel<<<(4*HS+255)/256,256>>>(rnn2_w_ih, hlin_b, badd);
    bpack_kernel<<<(4*HS+255)/256,256>>>(rnn2_b_ih, rnn2_b_hh, badd, bias2p);

    // ---- prologue (fp32) ----
    mean_kernel<<<512,256>>>(batch_H, meanH);
    gemm_kernel<<<dim3(8,4),256>>>(bhproj, HS, meanH, INSZ, i2h_w, INSZ, INSZ,
                                   h2h_b, nullptr,0, 0, BB, HS);
    gemm_kernel<<<dim3(8,8),256>>>(Wq, HS, conv_h2h_w, HS, h2h_w, HS, HS,
                                   nullptr, nullptr,0, 1, HS, HS);
    cast16_kernel<<<(HS*HS+255)/256,256>>>(Wq, Wq16, HS*HS);
    gemm_kernel<<<dim3(8,4),256>>>(qb, HS, bhproj, HS, conv_h2h_w, HS, HS,
                                   conv_h2h_b, nullptr,0, 0, BB, HS);
    init_kernel<<<512,256>>>(hidden_h, hidden_c, h1a16, h2a16, c1a, c2a);

    __half *h1c16=h1a16, *h1n16=h1b16, *h2c16=h2a16;
    float *c1c=c1a, *c1n=c1b, *c2c=c2a, *c2n=c2b;

    for (int t=0; t<TT; t++){
        __half* h2n16 = hist16 + (size_t)t*BB*HS;
        // q = qb + h2 @ Wq^T  (fp16 out)
        gemm16_kernel<<<dim3(4,4),256,G16_SMEM>>>(q16, HS,
            h2c16, Wq16, HS, nullptr, nullptr, 0,
            nullptr, qb, HS, nullptr, nullptr, 0,
            nullptr, nullptr, nullptr);
        // attention -> ctx (fp16), 512 threads/block
        attn_kernel<<<BB,512>>>(fmh, q16, score_w, score_b, ctx16);
        // gates1 + fused LSTM1
        gemm16_kernel<<<dim3(16,4),256,G16_SMEM>>>(nullptr, 0,
            ctx16, w1ih16, HS, h1c16, w1hh16, HS,
            bias1p, nullptr, 0, wgp, text + t, TT,
            c1c, c1n, h1n16);
        // gates2 + fused LSTM2 (hlin folded into w2ih16)
        gemm16_kernel<<<dim3(16,4),256,G16_SMEM>>>(nullptr, 0,
            h1n16, w2ih16, HS, h2c16, w2hh16, HS,
            bias2p, nullptr, 0, nullptr, nullptr, 0,
            c2c, c2n, h2n16);

        __half* tph;
        tph=h1c16; h1c16=h1n16; h1n16=tph;
        h2c16 = h2n16;
        float* tp;
        tp=c1c; c1c=c1n; c1n=tp;
        tp=c2c; c2c=c2n; c2n=tp;
    }

    // probs: one batched GEMM over all timesteps (fp16 hist), remap [b][t][n]
    gen_kernel<<<dim3(1,104),256>>>(out, hist16, gen_w, gen_b, TT*BB, NC);
}

// round 15
// speedup vs baseline: 1.3458x; 1.0296x over previous
#include <cuda_runtime.h>
#include <cuda_fp16.h>
#include <math.h>
#include <stdint.h>

#define BB 256
#define HS 512
#define INSZ 512
#define NC 38
#define TT 26
#define CH 512
#define PP 256   /* 8*32 */

// ---------------- scratch (device globals; no allocation allowed) ----------
__device__ __align__(16) __half g_aP[(size_t)BB*10*34*CH];  // padded input [b][10][34][ic]
__device__ __align__(16) __half g_bhT[9*CH*CH];
__device__ __align__(16) __half g_fmh[(size_t)BB*CH*PP];
__device__ float g_meanH[BB*INSZ];
__device__ float g_bhproj[BB*HS];
__device__ float g_Wq[HS*HS];
__device__ float g_qb[BB*HS];
__device__ float g_badd[4*HS];
__device__ __align__(16) __half g_Wq16[HS*HS];
__device__ __align__(16) __half g_hlinT16[HS*HS];
__device__ __align__(16) __half g_w2ihraw16[4*HS*HS];
__device__ __align__(16) __half g_W2pp16[4*HS*HS];
__device__ __align__(16) __half g_w1ih16[4*HS*INSZ];
__device__ __align__(16) __half g_w1hh16[4*HS*HS];
__device__ __align__(16) __half g_w2ih16[4*HS*HS];
__device__ __align__(16) __half g_w2hh16[4*HS*HS];
__device__ float g_bias1p[4*HS], g_bias2p[4*HS];
__device__ float g_wgp[4*HS*NC];
__device__ __align__(16) __half g_h1a16[BB*HS], g_h1b16[BB*HS], g_h2a16[BB*HS], g_h2b16[BB*HS];
__device__ float g_c1a[BB*HS], g_c1b[BB*HS], g_c2a[BB*HS], g_c2b[BB*HS];
__device__ float g_hist32[(size_t)TT*BB*HS];   // fp32 h2 history for generator
__device__ __align__(16) __half g_q16[BB*HS];
__device__ __align__(16) __half g_ctx16[BB*HS];

// ---------------- fast math ------------------------------------------------
__device__ __forceinline__ float fexp(float x){
    float y; asm("ex2.approx.f32 %0, %1;" : "=f"(y) : "f"(x*1.4426950408889634f)); return y;
}
__device__ __forceinline__ float frcp(float x){
    float y; asm("rcp.approx.f32 %0, %1;" : "=f"(y) : "f"(x)); return y;
}
__device__ __forceinline__ float ftanh(float x){
    float xc = fminf(fmaxf(x, -15.f), 15.f);
    float t = fexp(2.f*xc);
    return (t - 1.f) * frcp(t + 1.f);
}
__device__ __forceinline__ float ftanh_hw(float x){
    float y; asm("tanh.approx.f32 %0, %1;" : "=f"(y) : "f"(x)); return y;
}
__device__ __forceinline__ float fsigm(float x){
    return frcp(1.f + fexp(-x));
}
__device__ __forceinline__ void mma_fp16(float* d, const uint32_t* a, const uint32_t* b){
    asm volatile(
      "mma.sync.aligned.m16n8k16.row.col.f32.f16.f16.f32 "
      "{%0,%1,%2,%3},{%4,%5,%6,%7},{%8,%9},{%0,%1,%2,%3};"
      : "+f"(d[0]),"+f"(d[1]),"+f"(d[2]),"+f"(d[3])
      : "r"(a[0]),"r"(a[1]),"r"(a[2]),"r"(a[3]), "r"(b[0]),"r"(b[1]));
}
__device__ __forceinline__ void ldsm4(uint32_t* r, uint32_t saddr){
    asm volatile("ldmatrix.sync.aligned.m8n8.x4.shared.b16 {%0,%1,%2,%3}, [%4];"
      : "=r"(r[0]),"=r"(r[1]),"=r"(r[2]),"=r"(r[3]) : "r"(saddr));
}

// ---------------- prep kernels ------------------------------------------------
// single padded copy: out[((b*10+rr)*34+cc)*CH + ic] = in[b][ic][(rr-1)*32 + cc-1] or 0
__global__ void padT_kernel(const float* __restrict__ in, __half* __restrict__ oP)
{
    __shared__ float s[32][33];
    int blk = blockIdx.x;             // 256b * 10rr * 16icb
    int icb = blk & 15;
    int rr  = (blk >> 4) % 10;
    int b   = (blk >> 4) / 10;
    int t = threadIdx.x;
    int r = rr - 1;

    if ((unsigned)r < 8u){
        int c = t & 31, icq = t >> 5;
        #pragma unroll
        for (int j=0;j<4;j++){
            int ic = icq + j*8;
            s[ic][c] = in[((size_t)b*CH + icb*32 + ic)*PP + r*32 + c];
        }
    }
    __syncthreads();

    int icl = t & 31, cq = t >> 5;
    #pragma unroll
    for (int j=0;j<5;j++){
        int cc = cq + j*8;
        if (cc >= 34) continue;
        int c = cc - 1;
        float v = 0.f;
        if ((unsigned)r < 8u && (unsigned)c < 32u) v = s[icl][c];
        oP[(((size_t)b*10 + rr)*34 + cc)*CH + icb*32 + icl] = __float2half(v);
    }
}

__global__ void wT_kernel(const float* __restrict__ w, __half* __restrict__ oh)
{
    int idx = blockIdx.x*256 + threadIdx.x;
    if (idx >= 9*CH*CH) return;
    int ic = idx & 511;
    int oc = (idx >> 9) & 511;
    int khw = idx >> 18;
    oh[((size_t)khw*CH + oc)*CH + ic] = __float2half(w[((size_t)oc*CH + ic)*9 + khw]);
}

__global__ void cast16_kernel(const float* __restrict__ in, __half* __restrict__ out, int n)
{
    int idx = blockIdx.x*256 + threadIdx.x;
    if (idx < n) out[idx] = __float2half(in[idx]);
}

__global__ void transposeT16_kernel(const float* __restrict__ in, __half* __restrict__ out)
{
    __shared__ float s[32][33];
    int bx = blockIdx.x & 15, by = blockIdx.x >> 4;
    int tx = threadIdx.x & 31, ty = threadIdx.x >> 5;
    #pragma unroll
    for (int i=0;i<4;i++){
        int n = bx*32 + ty + i*8;
        s[ty+i*8][tx] = in[(size_t)n*HS + by*32 + tx];
    }
    __syncthreads();
    #pragma unroll
    for (int i=0;i<4;i++){
        int k = by*32 + ty + i*8;
        out[(size_t)k*HS + bx*32 + tx] = __float2half(s[tx][ty+i*8]);
    }
}

__global__ void wpack16_kernel(const float* __restrict__ w, int ldw, __half* __restrict__ out)
{
    int idx = blockIdx.x*256 + threadIdx.x;
    if (idx >= 4*HS*512) return;
    int k = idx & 511;
    int row = idx >> 9;
    int j = row >> 2, g = row & 3;
    out[idx] = __float2half(w[(size_t)(g*HS + j)*ldw + k]);
}

__global__ void wpack16h_kernel(const __half* __restrict__ w, __half* __restrict__ out)
{
    int idx = blockIdx.x*256 + threadIdx.x;
    if (idx >= 4*HS*512) return;
    int k = idx & 511;
    int row = idx >> 9;
    int j = row >> 2, g = row & 3;
    out[idx] = w[(size_t)(g*HS + j)*512 + k];
}

__global__ void bpack_kernel(const float* __restrict__ bih, const float* __restrict__ bhh,
                             const float* __restrict__ badd, float* __restrict__ out)
{
    int row = blockIdx.x*256 + threadIdx.x;
    if (row >= 4*HS) return;
    int j = row >> 2, g = row & 3;
    float v = bih[g*HS + j] + bhh[g*HS + j];
    if (badd) v += badd[g*HS + j];
    out[row] = v;
}

__global__ void wgpack_kernel(const float* __restrict__ w, float* __restrict__ out)
{
    int idx = blockIdx.x*256 + threadIdx.x;
    if (idx >= 4*HS*NC) return;
    int c = idx % NC;
    int row = idx / NC;
    int j = row >> 2, g = row & 3;
    out[idx] = w[(size_t)(g*HS + j)*(INSZ+NC) + INSZ + c];
}

__global__ void badd_kernel(const float* __restrict__ w2ih, const float* __restrict__ hlinb,
                            float* __restrict__ out)
{
    int m = blockIdx.x*256 + threadIdx.x;
    if (m >= 4*HS) return;
    const float* wr = w2ih + (size_t)m*HS;
    float s = 0.f;
    #pragma unroll 8
    for (int k=0;k<HS;k++) s += wr[k]*hlinb[k];
    out[m] = s;
}

// ---------------- conv 3x3 SAME via fp16 mma + ldmatrix ----------------------
#define CPITCH 20
#define CSTAGE_W (128*CPITCH)

__global__ void __launch_bounds__(256, 2) conv_fp16_kernel(
    const __half* __restrict__ Ag, const __half* __restrict__ Bg,
    const float* __restrict__ bias, __half* __restrict__ out)
{
    extern __shared__ __align__(16) uint32_t sm[];
    uint32_t* Asm = sm;
    uint32_t* Bsm = sm + 4*CSTAGE_W;
    const int b  = blockIdx.z;
    const int m0 = blockIdx.y * 128;
    const int n0 = blockIdx.x * 128;
    const int tid = threadIdx.x;
    const int lane = tid & 31, warp = tid >> 5;
    const int wm = (warp >> 2) * 64;
    const int wn = (warp & 3) * 32;
    const int gid = lane >> 2, tig = lane & 3;

    const int lrow = tid >> 1;
    const int lch  = tid & 1;
    const int arow = (m0 + lrow) >> 5;     // spatial row 0..7
    const int acol = (m0 + lrow) & 31;     // spatial col 0..31

    const int a_row = (lane & 15);
    const int a_kh  = (lane >> 4) * 4;
    const int b_row = (lane & 7) + (lane >> 4) * 8;
    const int b_kh  = ((lane >> 3) & 1) * 4;

    float acc[4][4][4];
    #pragma unroll
    for (int i=0;i<4;i++)
      #pragma unroll
      for (int j=0;j<4;j++)
        #pragma unroll
        for (int k=0;k<4;k++) acc[i][j][k]=0.f;

    uint32_t sAb = (uint32_t)__cvta_generic_to_shared(Asm);
    uint32_t sBb = (uint32_t)__cvta_generic_to_shared(Bsm);

#define CLOAD(s) do { \
        int st_  = (s) & 3; \
        int khw_ = (s) >> 4; \
        int ic0_ = ((s) & 15) << 5; \
        int kh_ = khw_ / 3, kw_ = khw_ - kh_*3; \
        const __half* ap_ = Ag + ((((size_t)b*10 + arow + kh_)*34) + acol + kw_)*CH + ic0_ + lch*8; \
        const __half* bp_ = Bg + ((size_t)khw_*CH + n0 + lrow)*CH + ic0_ + lch*8; \
        uint32_t da_ = sAb + (uint32_t)(((st_*128 + lrow)*CPITCH + lch*4)*4); \
        uint32_t db_ = sBb + (uint32_t)(((st_*128 + lrow)*CPITCH + lch*4)*4); \
        asm volatile("cp.async.cg.shared.global [%0], [%1], 16;" :: "r"(da_),      "l"(ap_)); \
        asm volatile("cp.async.cg.shared.global [%0], [%1], 16;" :: "r"(da_ + 32), "l"(ap_ + 16)); \
        asm volatile("cp.async.cg.shared.global [%0], [%1], 16;" :: "r"(db_),      "l"(bp_)); \
        asm volatile("cp.async.cg.shared.global [%0], [%1], 16;" :: "r"(db_ + 32), "l"(bp_ + 16)); \
        asm volatile("cp.async.commit_group;"); \
    } while(0)

    CLOAD(0); CLOAD(1); CLOAD(2);

    for (int s = 0; s < 144; ++s){
        asm volatile("cp.async.wait_group 2;");
        __syncthreads();
        if (s + 3 < 144) CLOAD(s + 3);

        const uint32_t stoff = (uint32_t)((s & 3) * CSTAGE_W * 4);
        const uint32_t Aoff = sAb + stoff;
        const uint32_t Boff = sBb + stoff;

        #pragma unroll
        for (int h = 0; h < 2; ++h){
            uint32_t afr[4][4], bfr[4][2];
            #pragma unroll
            for (int mi=0; mi<4; ++mi){
                uint32_t addr = Aoff + (uint32_t)((((wm + mi*16 + a_row)*CPITCH) + h*8 + a_kh)*4);
                ldsm4(afr[mi], addr);
            }
            #pragma unroll
            for (int nj=0; nj<2; ++nj){
                uint32_t r[4];
                uint32_t addr = Boff + (uint32_t)((((wn + nj*16 + b_row)*CPITCH) + h*8 + b_kh)*4);
                ldsm4(r, addr);
                bfr[nj*2  ][0] = r[0]; bfr[nj*2  ][1] = r[1];
                bfr[nj*2+1][0] = r[2]; bfr[nj*2+1][1] = r[3];
            }
            #pragma unroll
            for (int mi=0; mi<4; ++mi)
                #pragma unroll
                for (int ni=0; ni<4; ++ni)
                    mma_fp16(acc[mi][ni], afr[mi], bfr[ni]);
        }
    }
#undef CLOAD

    #pragma unroll
    for (int mi=0; mi<4; ++mi){
        int prow = m0 + wm + mi*16 + gid;
        #pragma unroll
        for (int ni=0; ni<4; ++ni){
            int oc = n0 + wn + ni*8 + tig*2;
            float bz0 = bias[oc], bz1 = bias[oc+1];
            __half* o0 = out + ((size_t)b*CH + oc)*PP;
            o0[prow]          = __float2half(acc[mi][ni][0] + bz0);
            o0[PP + prow]     = __float2half(acc[mi][ni][1] + bz1);
            o0[prow + 8]      = __float2half(acc[mi][ni][2] + bz0);
            o0[PP + prow + 8] = __float2half(acc[mi][ni][3] + bz1);
        }
    }
}

// ---------------- fp16 step GEMM (+optional fused LSTM epilogue) -------------
#define GPITCH 20
#define GA_WORDS (64*GPITCH)
#define GB_WORDS (128*GPITCH)

__global__ void __launch_bounds__(256, 2) gemm16_kernel(
    __half* __restrict__ C16, int ldc,
    const __half* __restrict__ A1, const __half* __restrict__ W1, int K1,
    const __half* __restrict__ A2, const __half* __restrict__ W2, int K2,
    const float* __restrict__ bias, const float* __restrict__ Cadd, int ldadd,
    const float* __restrict__ Wgp, const int* __restrict__ textcol, int textstride,
    const float* __restrict__ cin, float* __restrict__ cout, __half* __restrict__ hout,
    float* __restrict__ houtf)
{
    extern __shared__ __align__(16) uint32_t sm[];
    uint32_t* Asm = sm;                  // [4][64][20]
    uint32_t* Bsm = sm + 4*GA_WORDS;     // [4][128][20]
    const int m0 = blockIdx.y * 64;
    const int n0 = blockIdx.x * 128;
    const int tid = threadIdx.x;
    const int lane = tid & 31, warp = tid >> 5;
    const int wm = (warp >> 2) * 32;
    const int wn = (warp & 3) * 32;
    const int gid = lane >> 2, tig = lane & 3;

    const int a_row = (lane & 15);
    const int a_kh  = (lane >> 4) * 4;
    const int b_row = (lane & 7) + (lane >> 4) * 8;
    const int b_kh  = ((lane >> 3) & 1) * 4;

    const int S1 = K1 >> 5;
    const int S2 = (A2 != nullptr) ? (K2 >> 5) : 0;
    const int S  = S1 + S2;

    float acc[2][4][4];
    #pragma unroll
    for (int i=0;i<2;i++)
      #pragma unroll
      for (int j=0;j<4;j++)
        #pragma unroll
        for (int k=0;k<4;k++) acc[i][j][k]=0.f;

    uint32_t sAb = (uint32_t)__cvta_generic_to_shared(Asm);
    uint32_t sBb = (uint32_t)__cvta_generic_to_shared(Bsm);

#define GLOAD(s) do { \
        int st_ = (s) & 3; int s_ = (s); \
        const __half* A_; const __half* W_; int k0_; \
        if (s_ < S1){ A_ = A1; W_ = W1; k0_ = s_ << 5; } \
        else        { A_ = A2; W_ = W2; k0_ = (s_ - S1) << 5; } \
        const __half* ap_ = A_ + (size_t)(m0 + (tid>>2))*512 + k0_ + (tid&3)*8; \
        uint32_t da_ = sAb + (uint32_t)(((st_*64 + (tid>>2))*GPITCH + (tid&3)*4)*4); \
        asm volatile("cp.async.cg.shared.global [%0], [%1], 16;" :: "r"(da_), "l"(ap_)); \
        const __half* bp_ = W_ + (size_t)(n0 + (tid>>1))*512 + k0_ + (tid&1)*16; \
        uint32_t db_ = sBb + (uint32_t)(((st_*128 + (tid>>1))*GPITCH + (tid&1)*8)*4); \
        asm volatile("cp.async.cg.shared.global [%0], [%1], 16;" :: "r"(db_),      "l"(bp_)); \
        asm volatile("cp.async.cg.shared.global [%0], [%1], 16;" :: "r"(db_ + 16), "l"(bp_ + 8)); \
        asm volatile("cp.async.commit_group;"); \
    } while(0)

    GLOAD(0); GLOAD(1); GLOAD(2);

    for (int s = 0; s < S; ++s){
        asm volatile("cp.async.wait_group 2;");
        __syncthreads();
        if (s + 3 < S) GLOAD(s + 3);

        const uint32_t Aoff = sAb + (uint32_t)((s & 3) * GA_WORDS * 4);
        const uint32_t Boff = sBb + (uint32_t)((s & 3) * GB_WORDS * 4);

        #pragma unroll
        for (int h = 0; h < 2; ++h){
            uint32_t afr[2][4], bfr[4][2];
            #pragma unroll
            for (int mi=0; mi<2; ++mi){
                uint32_t addr = Aoff + (uint32_t)((((wm + mi*16 + a_row)*GPITCH) + h*8 + a_kh)*4);
                ldsm4(afr[mi], addr);
            }
            #pragma unroll
            for (int nj=0; nj<2; ++nj){
                uint32_t r[4];
                uint32_t addr = Boff + (uint32_t)((((wn + nj*16 + b_row)*GPITCH) + h*8 + b_kh)*4);
                ldsm4(r, addr);
                bfr[nj*2  ][0] = r[0]; bfr[nj*2  ][1] = r[1];
                bfr[nj*2+1][0] = r[2]; bfr[nj*2+1][1] = r[3];
            }
            #pragma unroll
            for (int mi=0; mi<2; ++mi)
                #pragma unroll
                for (int ni=0; ni<4; ++ni)
                    mma_fp16(acc[mi][ni], afr[mi], bfr[ni]);
        }
    }
#undef GLOAD

    #pragma unroll
    for (int mi=0; mi<2; ++mi){
        int m = m0 + wm + mi*16 + gid;
        int tc0 = 0, tc1 = 0;
        if (Wgp){ tc0 = textcol[m*textstride]; tc1 = textcol[(m+8)*textstride]; }
        #pragma unroll
        for (int ni=0; ni<4; ++ni){
            int n = n0 + wn + ni*8 + tig*2;
            float b0 = 0.f, b1 = 0.f;
            if (bias){ b0 = bias[n]; b1 = bias[n+1]; }
            float v00 = acc[mi][ni][0] + b0;
            float v01 = acc[mi][ni][1] + b1;
            float v10 = acc[mi][ni][2] + b0;
            float v11 = acc[mi][ni][3] + b1;
            if (Cadd){
                v00 += Cadd[(size_t)m*ldadd + n];     v01 += Cadd[(size_t)m*ldadd + n+1];
                v10 += Cadd[(size_t)(m+8)*ldadd + n]; v11 += Cadd[(size_t)(m+8)*ldadd + n+1];
            }
            if (Wgp){
                v00 += Wgp[n*NC + tc0];     v01 += Wgp[(n+1)*NC + tc0];
                v10 += Wgp[n*NC + tc1];     v11 += Wgp[(n+1)*NC + tc1];
            }
            if (cout){
                float p00 = __shfl_xor_sync(0xffffffffu, v00, 1);
                float p01 = __shfl_xor_sync(0xffffffffu, v01, 1);
                float p10 = __shfl_xor_sync(0xffffffffu, v10, 1);
                float p11 = __shfl_xor_sync(0xffffffffu, v11, 1);
                if ((tig & 1) == 0){
                    int j = n >> 2;
                    float c2a = fsigm(v01)*cin[(size_t)m*HS + j] + fsigm(v00)*ftanh(p00);
                    cout[(size_t)m*HS + j] = c2a;
                    float ha = fsigm(p01)*ftanh(c2a);
                    hout[(size_t)m*HS + j] = __float2half(ha);
                    float c2b = fsigm(v11)*cin[(size_t)(m+8)*HS + j] + fsigm(v10)*ftanh(p10);
                    cout[(size_t)(m+8)*HS + j] = c2b;
                    float hb = fsigm(p11)*ftanh(c2b);
                    hout[(size_t)(m+8)*HS + j] = __float2half(hb);
                    if (houtf){
                        houtf[(size_t)m*HS + j] = ha;
                        houtf[(size_t)(m+8)*HS + j] = hb;
                    }
                }
            } else {
                C16[(size_t)m*ldc + n]       = __float2half(v00);
                C16[(size_t)m*ldc + n+1]     = __float2half(v01);
                C16[(size_t)(m+8)*ldc + n]   = __float2half(v10);
                C16[(size_t)(m+8)*ldc + n+1] = __float2half(v11);
            }
        }
    }
}

// ---------------- fp32 SIMT GEMM (prologue) ----------------------------------
__global__ void gemm_kernel(
    float* __restrict__ C, int ldc,
    const float* __restrict__ A1, int lda1, const float* __restrict__ W1, int ldw1, int K1,
    const float* __restrict__ bias1,
    const float* __restrict__ Cadd, int ldadd,
    int nn, int M, int N)
{
    __shared__ float As[16][68];
    __shared__ float Bs[16][68];
    int m0 = blockIdx.y * 64;
    int n0 = blockIdx.x * 64;
    int tid = threadIdx.x;
    int tx = tid & 15, ty = tid >> 4;

    float acc[4][4];
    #pragma unroll
    for (int i=0;i<4;i++)
        #pragma unroll
        for (int j=0;j<4;j++) acc[i][j]=0.f;

    for (int k0=0; k0<K1; k0+=16){
        #pragma unroll
        for (int i=0;i<4;i++){
            int e = i*256 + tid;
            int m = e >> 4, kk = e & 15;
            int gm = m0 + m, gk = k0 + kk;
            As[kk][m] = (gm < M && gk < K1) ? A1[(size_t)gm*lda1 + gk] : 0.f;
        }
        if (nn){
            #pragma unroll
            for (int i=0;i<4;i++){
                int e = i*256 + tid;
                int kk = e >> 6, n = e & 63;
                int gn = n0 + n, gk = k0 + kk;
                Bs[kk][n] = (gn < N && gk < K1) ? W1[(size_t)gk*ldw1 + gn] : 0.f;
            }
        } else {
            #pragma unroll
            for (int i=0;i<4;i++){
                int e = i*256 + tid;
                int n = e >> 4, kk = e & 15;
                int gn = n0 + n, gk = k0 + kk;
                Bs[kk][n] = (gn < N && gk < K1) ? W1[(size_t)gn*ldw1 + gk] : 0.f;
            }
        }
        __syncthreads();
        #pragma unroll
        for (int kk=0; kk<16; kk++){
            float4 a = *(const float4*)&As[kk][ty*4];
            float4 b = *(const float4*)&Bs[kk][tx*4];
            acc[0][0]+=a.x*b.x; acc[0][1]+=a.x*b.y; acc[0][2]+=a.x*b.z; acc[0][3]+=a.x*b.w;
            acc[1][0]+=a.y*b.x; acc[1][1]+=a.y*b.y; acc[1][2]+=a.y*b.z; acc[1][3]+=a.y*b.w;
            acc[2][0]+=a.z*b.x; acc[2][1]+=a.z*b.y; acc[2][2]+=a.z*b.z; acc[2][3]+=a.z*b.w;
            acc[3][0]+=a.w*b.x; acc[3][1]+=a.w*b.y; acc[3][2]+=a.w*b.z; acc[3][3]+=a.w*b.w;
        }
        __syncthreads();
    }

    #pragma unroll
    for (int i=0;i<4;i++){
        int m = m0 + ty*4 + i;
        if (m >= M) continue;
        #pragma unroll
        for (int j=0;j<4;j++){
            int n = n0 + tx*4 + j;
            if (n >= N) continue;
            float v = acc[i][j];
            if (bias1) v += bias1[n];
            if (Cadd)  v += Cadd[(size_t)m*ldadd + n];
            C[(size_t)m*ldc + n] = v;
        }
    }
}

// ---------------- generator GEMM (fp32 A from hist32), remapped output -------
__global__ void gen_kernel(
    float* __restrict__ C,
    const float* __restrict__ A1, const float* __restrict__ W1,
    const float* __restrict__ bias1, int M, int N)
{
    __shared__ float As[16][68];
    __shared__ float Bs[16][68];
    int m0 = blockIdx.y * 64;
    int tid = threadIdx.x;
    int tx = tid & 15, ty = tid >> 4;

    float acc[4][4];
    #pragma unroll
    for (int i=0;i<4;i++)
        #pragma unroll
        for (int j=0;j<4;j++) acc[i][j]=0.f;

    for (int k0=0; k0<HS; k0+=16){
        #pragma unroll
        for (int i=0;i<4;i++){
            int e = i*256 + tid;
            int m = e >> 4, kk = e & 15;
            int gm = m0 + m, gk = k0 + kk;
            As[kk][m] = (gm < M) ? A1[(size_t)gm*HS + gk] : 0.f;
        }
        #pragma unroll
        for (int i=0;i<4;i++){
            int e = i*256 + tid;
            int n = e >> 4, kk = e & 15;
            int gk = k0 + kk;
            Bs[kk][n] = (n < N) ? W1[(size_t)n*HS + gk] : 0.f;
        }
        __syncthreads();
        #pragma unroll
        for (int kk=0; kk<16; kk++){
            float4 a = *(const float4*)&As[kk][ty*4];
            float4 b = *(const float4*)&Bs[kk][tx*4];
            acc[0][0]+=a.x*b.x; acc[0][1]+=a.x*b.y; acc[0][2]+=a.x*b.z; acc[0][3]+=a.x*b.w;
            acc[1][0]+=a.y*b.x; acc[1][1]+=a.y*b.y; acc[1][2]+=a.y*b.z; acc[1][3]+=a.y*b.w;
            acc[2][0]+=a.z*b.x; acc[2][1]+=a.z*b.y; acc[2][2]+=a.z*b.z; acc[2][3]+=a.z*b.w;
            acc[3][0]+=a.w*b.x; acc[3][1]+=a.w*b.y; acc[3][2]+=a.w*b.z; acc[3][3]+=a.w*b.w;
        }
        __syncthreads();
    }

    #pragma unroll
    for (int i=0;i<4;i++){
        int m = m0 + ty*4 + i;
        if (m >= M) continue;
        int t = m >> 8, b = m & 255;
        #pragma unroll
        for (int j=0;j<4;j++){
            int n = tx*4 + j;
            if (n >= N) continue;
            C[(size_t)(b*TT + t)*NC + n] = acc[i][j] + bias1[n];
        }
    }
}

// ---------------- mean over T of batch_H ------------------------------------
__global__ void mean_kernel(const float* __restrict__ bH, float* __restrict__ out)
{
    int idx = blockIdx.x*256 + threadIdx.x;
    if (idx >= BB*INSZ) return;
    int b = idx >> 9, k = idx & 511;
    const float* p = bH + (size_t)b*TT*INSZ + k;
    float s = 0.f;
    #pragma unroll
    for (int t=0;t<TT;t++) s += p[t*INSZ];
    out[idx] = s * (1.0f/26.0f);
}

// ---------------- init h0/c0 -------------------------------------------------
__global__ void init_kernel(const float* __restrict__ hh, const float* __restrict__ hc,
                            __half* __restrict__ h1, __half* __restrict__ h2,
                            float* __restrict__ c1, float* __restrict__ c2)
{
    int idx = blockIdx.x*256 + threadIdx.x;
    if (idx >= BB*HS) return;
    float h0 = 0.5f*(hh[idx] + hh[BB*HS + idx]);
    float c0 = 0.5f*(hc[idx] + hc[BB*HS + idx]);
    h1[idx] = __float2half(h0); h2[idx] = __float2half(h0);
    c1[idx]=c0; c2[idx]=c0;
}

// ---------------- attention: 512 threads, 2 threads/position -----------------
__global__ void __launch_bounds__(512) attn_kernel(
    const __half* __restrict__ fmh, const __half* __restrict__ q,
    const float* __restrict__ ws, const float* __restrict__ sb,
    __half* __restrict__ ctx)
{
    __shared__ float qs[CH];
    __shared__ float wss[CH];
    __shared__ float epart[512];
    __shared__ float red[256];
    __shared__ float alpha[256];

    int b = blockIdx.x;
    int tid = threadIdx.x;
    int p = tid & 255;
    int hf = tid >> 8;
    const __half* f = fmh + (size_t)b * CH * PP;

    qs[tid]  = __half2float(q[b*HS + tid]);
    wss[tid] = ws[tid];
    __syncthreads();

    {
        int c0 = hf * 256;
        float a0=0.f, a1=0.f, a2=0.f, a3=0.f;
        #pragma unroll 2
        for (int c=c0; c<c0+256; c+=4){
            float f0 = __half2float(f[(c  )*PP + p]);
            float f1 = __half2float(f[(c+1)*PP + p]);
            float f2 = __half2float(f[(c+2)*PP + p]);
            float f3 = __half2float(f[(c+3)*PP + p]);
            a0 += ftanh_hw(f0 + qs[c  ]) * wss[c  ];
            a1 += ftanh_hw(f1 + qs[c+1]) * wss[c+1];
            a2 += ftanh_hw(f2 + qs[c+2]) * wss[c+2];
            a3 += ftanh_hw(f3 + qs[c+3]) * wss[c+3];
        }
        epart[tid] = (a0+a1) + (a2+a3);
    }
    __syncthreads();

    float e = 0.f;
    if (tid < 256){
        e = epart[tid] + epart[tid + 256] + sb[0];
        red[tid] = e;
    }
    __syncthreads();
    #pragma unroll
    for (int s=128; s>0; s>>=1){
        if (tid < s) red[tid] = fmaxf(red[tid], red[tid+s]);
        __syncthreads();
    }
    float mx = red[0];
    __syncthreads();
    float ex = 0.f;
    if (tid < 256){
        ex = fexp(e - mx);
        red[tid] = ex;
    }
    __syncthreads();
    #pragma unroll
    for (int s=128; s>0; s>>=1){
        if (tid < s) red[tid] += red[tid+s];
        __syncthreads();
    }
    float sum = red[0];
    __syncthreads();
    if (tid < 256) alpha[tid] = ex * frcp(sum);
    __syncthreads();

    int lane = tid & 31, wid = tid >> 5;
    for (int c = wid; c < CH; c += 16){
        const __half* fr = f + c*PP;
        float s = 0.f;
        #pragma unroll
        for (int pp = lane; pp < PP; pp += 32) s += alpha[pp] * __half2float(fr[pp]);
        #pragma unroll
        for (int o=16; o>0; o>>=1) s += __shfl_down_sync(0xffffffffu, s, o);
        if (lane == 0) ctx[b*HS + c] = __float2half(s);
    }
}

// ---------------- host orchestration ----------------------------------------
extern "C" void kernel_launch(void* const* d_in, const int* in_sizes, int n_in,
                              void* d_out, int out_size)
{
    const float* feature_map = (const float*)d_in[0];
    const float* batch_H     = (const float*)d_in[1];
    const float* hidden_h    = (const float*)d_in[2];
    const float* hidden_c    = (const float*)d_in[3];
    const int*   text        = (const int*)  d_in[4];
    const float* i2h_w       = (const float*)d_in[5];
    const float* h2h_w       = (const float*)d_in[6];
    const float* h2h_b       = (const float*)d_in[7];
    const float* conv_m2h_w  = (const float*)d_in[8];
    const float* conv_m2h_b  = (const float*)d_in[9];
    const float* conv_h2h_w  = (const float*)d_in[10];
    const float* conv_h2h_b  = (const float*)d_in[11];
    const float* score_w     = (const float*)d_in[12];
    const float* score_b     = (const float*)d_in[13];
    const float* rnn1_w_ih   = (const float*)d_in[14];
    const float* rnn1_w_hh   = (const float*)d_in[15];
    const float* rnn1_b_ih   = (const float*)d_in[16];
    const float* rnn1_b_hh   = (const float*)d_in[17];
    const float* hlin_w      = (const float*)d_in[18];
    const float* hlin_b      = (const float*)d_in[19];
    const float* rnn2_w_ih   = (const float*)d_in[20];
    const float* rnn2_w_hh   = (const float*)d_in[21];
    const float* rnn2_b_ih   = (const float*)d_in[22];
    const float* rnn2_b_hh   = (const float*)d_in[23];
    const float* gen_w       = (const float*)d_in[24];
    const float* gen_b       = (const float*)d_in[25];
    float* out = (float*)d_out;

    __half *aP,*bhT,*fmh,*Wq16,*hlinT16,*w2ihraw16,*W2pp16;
    __half *w1ih16,*w1hh16,*w2ih16,*w2hh16;
    __half *h1a16,*h1b16,*h2a16,*h2b16,*q16,*ctx16;
    float *meanH,*bhproj,*Wq,*qb,*badd,*bias1p,*bias2p,*wgp,*hist32;
    float *c1a,*c1b,*c2a,*c2b;
    cudaGetSymbolAddress((void**)&aP,  g_aP);
    cudaGetSymbolAddress((void**)&bhT, g_bhT);
    cudaGetSymbolAddress((void**)&fmh, g_fmh);
    cudaGetSymbolAddress((void**)&meanH, g_meanH);
    cudaGetSymbolAddress((void**)&bhproj,g_bhproj);
    cudaGetSymbolAddress((void**)&Wq,    g_Wq);
    cudaGetSymbolAddress((void**)&qb,    g_qb);
    cudaGetSymbolAddress((void**)&badd,  g_badd);
    cudaGetSymbolAddress((void**)&Wq16,  g_Wq16);
    cudaGetSymbolAddress((void**)&hlinT16, g_hlinT16);
    cudaGetSymbolAddress((void**)&w2ihraw16, g_w2ihraw16);
    cudaGetSymbolAddress((void**)&W2pp16, g_W2pp16);
    cudaGetSymbolAddress((void**)&w1ih16,g_w1ih16);
    cudaGetSymbolAddress((void**)&w1hh16,g_w1hh16);
    cudaGetSymbolAddress((void**)&w2ih16,g_w2ih16);
    cudaGetSymbolAddress((void**)&w2hh16,g_w2hh16);
    cudaGetSymbolAddress((void**)&bias1p,g_bias1p);
    cudaGetSymbolAddress((void**)&bias2p,g_bias2p);
    cudaGetSymbolAddress((void**)&wgp,   g_wgp);
    cudaGetSymbolAddress((void**)&h1a16, g_h1a16);
    cudaGetSymbolAddress((void**)&h1b16, g_h1b16);
    cudaGetSymbolAddress((void**)&h2a16, g_h2a16);
    cudaGetSymbolAddress((void**)&h2b16, g_h2b16);
    cudaGetSymbolAddress((void**)&c1a, g_c1a); cudaGetSymbolAddress((void**)&c1b, g_c1b);
    cudaGetSymbolAddress((void**)&c2a, g_c2a); cudaGetSymbolAddress((void**)&c2b, g_c2b);
    cudaGetSymbolAddress((void**)&hist32, g_hist32);
    cudaGetSymbolAddress((void**)&q16,  g_q16);
    cudaGetSymbolAddress((void**)&ctx16,g_ctx16);

    const int CONV_SMEM = 2 * 4 * 128 * CPITCH * 4;   // 81920
    cudaFuncSetAttribute(conv_fp16_kernel, cudaFuncAttributeMaxDynamicSharedMemorySize, CONV_SMEM);
    const int G16_SMEM = 4 * (GA_WORDS + GB_WORDS) * 4;  // 61440
    cudaFuncSetAttribute(gemm16_kernel, cudaFuncAttributeMaxDynamicSharedMemorySize, G16_SMEM);

    // ---- conv prep + conv ----
    padT_kernel<<<256*10*16, 256>>>(feature_map, aP);
    wT_kernel<<<(9*CH*CH+255)/256, 256>>>(conv_m2h_w, bhT);
    conv_fp16_kernel<<<dim3(4,2,BB), 256, CONV_SMEM>>>(aP, bhT, conv_m2h_b, fmh);

    // ---- weight packing ----
    wpack16_kernel<<<(4*HS*512+255)/256,256>>>(rnn1_w_ih, INSZ+NC, w1ih16);
    wpack16_kernel<<<(4*HS*512+255)/256,256>>>(rnn1_w_hh, HS, w1hh16);
    wpack16_kernel<<<(4*HS*512+255)/256,256>>>(rnn2_w_hh, HS, w2hh16);
    bpack_kernel<<<(4*HS+255)/256,256>>>(rnn1_b_ih, rnn1_b_hh, nullptr, bias1p);
    wgpack_kernel<<<(4*HS*NC+255)/256,256>>>(rnn1_w_ih, wgp);
    cast16_kernel<<<(4*HS*HS+255)/256,256>>>(rnn2_w_ih, w2ihraw16, 4*HS*HS);
    transposeT16_kernel<<<256,256>>>(hlin_w, hlinT16);
    gemm16_kernel<<<dim3(4,32),256,G16_SMEM>>>(W2pp16, HS,
        w2ihraw16, hlinT16, HS, nullptr, nullptr, 0,
        nullptr, nullptr, 0, nullptr, nullptr, 0,
        nullptr, nullptr, nullptr, nullptr);
    wpack16h_kernel<<<(4*HS*512+255)/256,256>>>(W2pp16, w2ih16);
    badd_kernel<<<(4*HS+255)/256,256>>>(rnn2_w_ih, hlin_b, badd);
    bpack_kernel<<<(4*HS+255)/256,256>>>(rnn2_b_ih, rnn2_b_hh, badd, bias2p);

    // ---- prologue (fp32) ----
    mean_kernel<<<512,256>>>(batch_H, meanH);
    gemm_kernel<<<dim3(8,4),256>>>(bhproj, HS, meanH, INSZ, i2h_w, INSZ, INSZ,
                                   h2h_b, nullptr,0, 0, BB, HS);
    gemm_kernel<<<dim3(8,8),256>>>(Wq, HS, conv_h2h_w, HS, h2h_w, HS, HS,
                                   nullptr, nullptr,0, 1, HS, HS);
    cast16_kernel<<<(HS*HS+255)/256,256>>>(Wq, Wq16, HS*HS);
    gemm_kernel<<<dim3(8,4),256>>>(qb, HS, bhproj, HS, conv_h2h_w, HS, HS,
                                   conv_h2h_b, nullptr,0, 0, BB, HS);
    init_kernel<<<512,256>>>(hidden_h, hidden_c, h1a16, h2a16, c1a, c2a);

    __half *h1c16=h1a16, *h1n16=h1b16, *h2c16=h2a16, *h2n16=h2b16;
    float *c1c=c1a, *c1n=c1b, *c2c=c2a, *c2n=c2b;

    for (int t=0; t<TT; t++){
        // q = qb + h2 @ Wq^T  (fp16 out)
        gemm16_kernel<<<dim3(4,4),256,G16_SMEM>>>(q16, HS,
            h2c16, Wq16, HS, nullptr, nullptr, 0,
            nullptr, qb, HS, nullptr, nullptr, 0,
            nullptr, nullptr, nullptr, nullptr);
        // attention -> ctx (fp16), 512 threads/block
        attn_kernel<<<BB,512>>>(fmh, q16, score_w, score_b, ctx16);
        // gates1 + fused LSTM1
        gemm16_kernel<<<dim3(16,4),256,G16_SMEM>>>(nullptr, 0,
            ctx16, w1ih16, HS, h1c16, w1hh16, HS,
            bias1p, nullptr, 0, wgp, text + t, TT,
            c1c, c1n, h1n16, nullptr);
        // gates2 + fused LSTM2 (hlin folded); h2 -> fp16 state + fp32 hist
        gemm16_kernel<<<dim3(16,4),256,G16_SMEM>>>(nullptr, 0,
            h1n16, w2ih16, HS, h2c16, w2hh16, HS,
            bias2p, nullptr, 0, nullptr, nullptr, 0,
            c2c, c2n, h2n16, hist32 + (size_t)t*BB*HS);

        __half* tph;
        tph=h1c16; h1c16=h1n16; h1n16=tph;
        tph=h2c16; h2c16=h2n16; h2n16=tph;
        float* tp;
        tp=c1c; c1c=c1n; c1n=tp;
        tp=c2c; c2c=c2n; c2n=tp;
    }

    // probs: one batched GEMM over all timesteps (fp32 hist), remap [b][t][n]
    gen_kernel<<<dim3(1,104),256>>>(out, hist32, gen_w, gen_b, TT*BB, NC);
}

// round 17
// speedup vs baseline: 1.3793x; 1.0249x over previous
#include <cuda_runtime.h>
#include <cuda_fp16.h>
#include <math.h>
#include <stdint.h>

#define BB 256
#define HS 512
#define INSZ 512
#define NC 38
#define TT 26
#define CH 512
#define PP 256   /* 8*32 */

// ---------------- scratch (device globals; no allocation allowed) ----------
__device__ __align__(16) __half g_aP[(size_t)BB*10*34*CH];  // padded input [b][10][34][ic]
__device__ __align__(16) __half g_bhT[9*CH*CH];
__device__ __align__(16) __half g_fmh[(size_t)BB*CH*PP];
__device__ float g_meanH[BB*INSZ];
__device__ float g_bhproj[BB*HS];
__device__ float g_Wq[HS*HS];
__device__ float g_qb[BB*HS];
__device__ float g_badd[4*HS];
__device__ __align__(16) __half g_Wq16[HS*HS];
__device__ __align__(16) __half g_hlinT16[HS*HS];
__device__ __align__(16) __half g_w2ihraw16[4*HS*HS];
__device__ __align__(16) __half g_W2pp16[4*HS*HS];
__device__ __align__(16) __half g_w1ih16[4*HS*INSZ];
__device__ __align__(16) __half g_w1hh16[4*HS*HS];
__device__ __align__(16) __half g_w2ih16[4*HS*HS];
__device__ __align__(16) __half g_w2hh16[4*HS*HS];
__device__ float g_bias1p[4*HS], g_bias2p[4*HS];
__device__ float g_wgp[4*HS*NC];
__device__ __align__(16) __half g_h1a16[BB*HS], g_h1b16[BB*HS], g_h2a16[BB*HS], g_h2b16[BB*HS];
__device__ float g_c1a[BB*HS], g_c1b[BB*HS], g_c2a[BB*HS], g_c2b[BB*HS];
__device__ float g_hist32[(size_t)TT*BB*HS];   // fp32 h2 history for generator
__device__ __align__(16) __half g_q16[BB*HS];
__device__ __align__(16) __half g_ctx16[BB*HS];

// ---------------- fast math ------------------------------------------------
__device__ __forceinline__ float fexp(float x){
    float y; asm("ex2.approx.f32 %0, %1;" : "=f"(y) : "f"(x*1.4426950408889634f)); return y;
}
__device__ __forceinline__ float frcp(float x){
    float y; asm("rcp.approx.f32 %0, %1;" : "=f"(y) : "f"(x)); return y;
}
__device__ __forceinline__ float ftanh(float x){
    float xc = fminf(fmaxf(x, -15.f), 15.f);
    float t = fexp(2.f*xc);
    return (t - 1.f) * frcp(t + 1.f);
}
__device__ __forceinline__ float ftanh_hw(float x){
    float y; asm("tanh.approx.f32 %0, %1;" : "=f"(y) : "f"(x)); return y;
}
__device__ __forceinline__ float fsigm(float x){
    return frcp(1.f + fexp(-x));
}
__device__ __forceinline__ void mma_fp16(float* d, const uint32_t* a, const uint32_t* b){
    asm volatile(
      "mma.sync.aligned.m16n8k16.row.col.f32.f16.f16.f32 "
      "{%0,%1,%2,%3},{%4,%5,%6,%7},{%8,%9},{%0,%1,%2,%3};"
      : "+f"(d[0]),"+f"(d[1]),"+f"(d[2]),"+f"(d[3])
      : "r"(a[0]),"r"(a[1]),"r"(a[2]),"r"(a[3]), "r"(b[0]),"r"(b[1]));
}
__device__ __forceinline__ void ldsm4(uint32_t* r, uint32_t saddr){
    asm volatile("ldmatrix.sync.aligned.m8n8.x4.shared.b16 {%0,%1,%2,%3}, [%4];"
      : "=r"(r[0]),"=r"(r[1]),"=r"(r[2]),"=r"(r[3]) : "r"(saddr));
}

// ---------------- prep kernels ------------------------------------------------
__global__ void padT_kernel(const float* __restrict__ in, __half* __restrict__ oP)
{
    __shared__ float s[32][33];
    int blk = blockIdx.x;
    int icb = blk & 15;
    int rr  = (blk >> 4) % 10;
    int b   = (blk >> 4) / 10;
    int t = threadIdx.x;
    int r = rr - 1;

    if ((unsigned)r < 8u){
        int c = t & 31, icq = t >> 5;
        #pragma unroll
        for (int j=0;j<4;j++){
            int ic = icq + j*8;
            s[ic][c] = in[((size_t)b*CH + icb*32 + ic)*PP + r*32 + c];
        }
    }
    __syncthreads();

    int icl = t & 31, cq = t >> 5;
    #pragma unroll
    for (int j=0;j<5;j++){
        int cc = cq + j*8;
        if (cc >= 34) continue;
        int c = cc - 1;
        float v = 0.f;
        if ((unsigned)r < 8u && (unsigned)c < 32u) v = s[icl][c];
        oP[(((size_t)b*10 + rr)*34 + cc)*CH + icb*32 + icl] = __float2half(v);
    }
}

__global__ void wT_kernel(const float* __restrict__ w, __half* __restrict__ oh)
{
    int idx = blockIdx.x*256 + threadIdx.x;
    if (idx >= 9*CH*CH) return;
    int ic = idx & 511;
    int oc = (idx >> 9) & 511;
    int khw = idx >> 18;
    oh[((size_t)khw*CH + oc)*CH + ic] = __float2half(w[((size_t)oc*CH + ic)*9 + khw]);
}

__global__ void cast16_kernel(const float* __restrict__ in, __half* __restrict__ out, int n)
{
    int idx = blockIdx.x*256 + threadIdx.x;
    if (idx < n) out[idx] = __float2half(in[idx]);
}

__global__ void transposeT16_kernel(const float* __restrict__ in, __half* __restrict__ out)
{
    __shared__ float s[32][33];
    int bx = blockIdx.x & 15, by = blockIdx.x >> 4;
    int tx = threadIdx.x & 31, ty = threadIdx.x >> 5;
    #pragma unroll
    for (int i=0;i<4;i++){
        int n = bx*32 + ty + i*8;
        s[ty+i*8][tx] = in[(size_t)n*HS + by*32 + tx];
    }
    __syncthreads();
    #pragma unroll
    for (int i=0;i<4;i++){
        int k = by*32 + ty + i*8;
        out[(size_t)k*HS + bx*32 + tx] = __float2half(s[tx][ty+i*8]);
    }
}

__global__ void wpack16_kernel(const float* __restrict__ w, int ldw, __half* __restrict__ out)
{
    int idx = blockIdx.x*256 + threadIdx.x;
    if (idx >= 4*HS*512) return;
    int k = idx & 511;
    int row = idx >> 9;
    int j = row >> 2, g = row & 3;
    out[idx] = __float2half(w[(size_t)(g*HS + j)*ldw + k]);
}

__global__ void wpack16h_kernel(const __half* __restrict__ w, __half* __restrict__ out)
{
    int idx = blockIdx.x*256 + threadIdx.x;
    if (idx >= 4*HS*512) return;
    int k = idx & 511;
    int row = idx >> 9;
    int j = row >> 2, g = row & 3;
    out[idx] = w[(size_t)(g*HS + j)*512 + k];
}

__global__ void bpack_kernel(const float* __restrict__ bih, const float* __restrict__ bhh,
                             const float* __restrict__ badd, float* __restrict__ out)
{
    int row = blockIdx.x*256 + threadIdx.x;
    if (row >= 4*HS) return;
    int j = row >> 2, g = row & 3;
    float v = bih[g*HS + j] + bhh[g*HS + j];
    if (badd) v += badd[g*HS + j];
    out[row] = v;
}

__global__ void wgpack_kernel(const float* __restrict__ w, float* __restrict__ out)
{
    int idx = blockIdx.x*256 + threadIdx.x;
    if (idx >= 4*HS*NC) return;
    int c = idx % NC;
    int row = idx / NC;
    int j = row >> 2, g = row & 3;
    out[idx] = w[(size_t)(g*HS + j)*(INSZ+NC) + INSZ + c];
}

__global__ void badd_kernel(const float* __restrict__ w2ih, const float* __restrict__ hlinb,
                            float* __restrict__ out)
{
    int m = blockIdx.x*256 + threadIdx.x;
    if (m >= 4*HS) return;
    const float* wr = w2ih + (size_t)m*HS;
    float s = 0.f;
    #pragma unroll 8
    for (int k=0;k<HS;k++) s += wr[k]*hlinb[k];
    out[m] = s;
}

// ---------------- conv 3x3 SAME via fp16 mma + ldmatrix ----------------------
#define CPITCH 20
#define CSTAGE_W (128*CPITCH)

__global__ void __launch_bounds__(256, 2) conv_fp16_kernel(
    const __half* __restrict__ Ag, const __half* __restrict__ Bg,
    const float* __restrict__ bias, __half* __restrict__ out)
{
    extern __shared__ __align__(16) uint32_t sm[];
    uint32_t* Asm = sm;
    uint32_t* Bsm = sm + 4*CSTAGE_W;
    const int b  = blockIdx.z;
    const int m0 = blockIdx.y * 128;
    const int n0 = blockIdx.x * 128;
    const int tid = threadIdx.x;
    const int lane = tid & 31, warp = tid >> 5;
    const int wm = (warp >> 2) * 64;
    const int wn = (warp & 3) * 32;
    const int gid = lane >> 2, tig = lane & 3;

    const int lrow = tid >> 1;
    const int lch  = tid & 1;
    const int arow = (m0 + lrow) >> 5;
    const int acol = (m0 + lrow) & 31;

    const int a_row = (lane & 15);
    const int a_kh  = (lane >> 4) * 4;
    const int b_row = (lane & 7) + (lane >> 4) * 8;
    const int b_kh  = ((lane >> 3) & 1) * 4;

    float acc[4][4][4];
    #pragma unroll
    for (int i=0;i<4;i++)
      #pragma unroll
      for (int j=0;j<4;j++)
        #pragma unroll
        for (int k=0;k<4;k++) acc[i][j][k]=0.f;

    uint32_t sAb = (uint32_t)__cvta_generic_to_shared(Asm);
    uint32_t sBb = (uint32_t)__cvta_generic_to_shared(Bsm);

#define CLOAD(s) do { \
        int st_  = (s) & 3; \
        int khw_ = (s) >> 4; \
        int ic0_ = ((s) & 15) << 5; \
        int kh_ = khw_ / 3, kw_ = khw_ - kh_*3; \
        const __half* ap_ = Ag + ((((size_t)b*10 + arow + kh_)*34) + acol + kw_)*CH + ic0_ + lch*8; \
        const __half* bp_ = Bg + ((size_t)khw_*CH + n0 + lrow)*CH + ic0_ + lch*8; \
        uint32_t da_ = sAb + (uint32_t)(((st_*128 + lrow)*CPITCH + lch*4)*4); \
        uint32_t db_ = sBb + (uint32_t)(((st_*128 + lrow)*CPITCH + lch*4)*4); \
        asm volatile("cp.async.cg.shared.global [%0], [%1], 16;" :: "r"(da_),      "l"(ap_)); \
        asm volatile("cp.async.cg.shared.global [%0], [%1], 16;" :: "r"(da_ + 32), "l"(ap_ + 16)); \
        asm volatile("cp.async.cg.shared.global [%0], [%1], 16;" :: "r"(db_),      "l"(bp_)); \
        asm volatile("cp.async.cg.shared.global [%0], [%1], 16;" :: "r"(db_ + 32), "l"(bp_ + 16)); \
        asm volatile("cp.async.commit_group;"); \
    } while(0)

    CLOAD(0); CLOAD(1); CLOAD(2);

    for (int s = 0; s < 144; ++s){
        asm volatile("cp.async.wait_group 2;");
        __syncthreads();
        if (s + 3 < 144) CLOAD(s + 3);

        const uint32_t stoff = (uint32_t)((s & 3) * CSTAGE_W * 4);
        const uint32_t Aoff = sAb + stoff;
        const uint32_t Boff = sBb + stoff;

        #pragma unroll
        for (int h = 0; h < 2; ++h){
            uint32_t afr[4][4], bfr[4][2];
            #pragma unroll
            for (int mi=0; mi<4; ++mi){
                uint32_t addr = Aoff + (uint32_t)((((wm + mi*16 + a_row)*CPITCH) + h*8 + a_kh)*4);
                ldsm4(afr[mi], addr);
            }
            #pragma unroll
            for (int nj=0; nj<2; ++nj){
                uint32_t r[4];
                uint32_t addr = Boff + (uint32_t)((((wn + nj*16 + b_row)*CPITCH) + h*8 + b_kh)*4);
                ldsm4(r, addr);
                bfr[nj*2  ][0] = r[0]; bfr[nj*2  ][1] = r[1];
                bfr[nj*2+1][0] = r[2]; bfr[nj*2+1][1] = r[3];
            }
            #pragma unroll
            for (int mi=0; mi<4; ++mi)
                #pragma unroll
                for (int ni=0; ni<4; ++ni)
                    mma_fp16(acc[mi][ni], afr[mi], bfr[ni]);
        }
    }
#undef CLOAD

    #pragma unroll
    for (int mi=0; mi<4; ++mi){
        int prow = m0 + wm + mi*16 + gid;
        #pragma unroll
        for (int ni=0; ni<4; ++ni){
            int oc = n0 + wn + ni*8 + tig*2;
            float bz0 = bias[oc], bz1 = bias[oc+1];
            __half* o0 = out + ((size_t)b*CH + oc)*PP;
            o0[prow]          = __float2half(acc[mi][ni][0] + bz0);
            o0[PP + prow]     = __float2half(acc[mi][ni][1] + bz1);
            o0[prow + 8]      = __float2half(acc[mi][ni][2] + bz0);
            o0[PP + prow + 8] = __float2half(acc[mi][ni][3] + bz1);
        }
    }
}

// ---------------- fp16 step GEMM (+optional fused LSTM epilogue) -------------
#define GPITCH 20
#define GA_WORDS (64*GPITCH)
#define GB_WORDS (128*GPITCH)

__global__ void __launch_bounds__(256, 2) gemm16_kernel(
    __half* __restrict__ C16, int ldc,
    const __half* __restrict__ A1, const __half* __restrict__ W1, int K1,
    const __half* __restrict__ A2, const __half* __restrict__ W2, int K2,
    const float* __restrict__ bias, const float* __restrict__ Cadd, int ldadd,
    const float* __restrict__ Wgp, const int* __restrict__ textcol, int textstride,
    const float* __restrict__ cin, float* __restrict__ cout, __half* __restrict__ hout,
    float* __restrict__ houtf)
{
    extern __shared__ __align__(16) uint32_t sm[];
    uint32_t* Asm = sm;                  // [4][64][20]
    uint32_t* Bsm = sm + 4*GA_WORDS;     // [4][128][20]
    const int m0 = blockIdx.y * 64;
    const int n0 = blockIdx.x * 128;
    const int tid = threadIdx.x;
    const int lane = tid & 31, warp = tid >> 5;
    const int wm = (warp >> 2) * 32;
    const int wn = (warp & 3) * 32;
    const int gid = lane >> 2, tig = lane & 3;

    const int a_row = (lane & 15);
    const int a_kh  = (lane >> 4) * 4;
    const int b_row = (lane & 7) + (lane >> 4) * 8;
    const int b_kh  = ((lane >> 3) & 1) * 4;

    const int S1 = K1 >> 5;
    const int S2 = (A2 != nullptr) ? (K2 >> 5) : 0;
    const int S  = S1 + S2;

    float acc[2][4][4];
    #pragma unroll
    for (int i=0;i<2;i++)
      #pragma unroll
      for (int j=0;j<4;j++)
        #pragma unroll
        for (int k=0;k<4;k++) acc[i][j][k]=0.f;

    uint32_t sAb = (uint32_t)__cvta_generic_to_shared(Asm);
    uint32_t sBb = (uint32_t)__cvta_generic_to_shared(Bsm);

#define GLOAD(s) do { \
        int st_ = (s) & 3; int s_ = (s); \
        const __half* A_; const __half* W_; int k0_; \
        if (s_ < S1){ A_ = A1; W_ = W1; k0_ = s_ << 5; } \
        else        { A_ = A2; W_ = W2; k0_ = (s_ - S1) << 5; } \
        const __half* ap_ = A_ + (size_t)(m0 + (tid>>2))*512 + k0_ + (tid&3)*8; \
        uint32_t da_ = sAb + (uint32_t)(((st_*64 + (tid>>2))*GPITCH + (tid&3)*4)*4); \
        asm volatile("cp.async.cg.shared.global [%0], [%1], 16;" :: "r"(da_), "l"(ap_)); \
        const __half* bp_ = W_ + (size_t)(n0 + (tid>>1))*512 + k0_ + (tid&1)*16; \
        uint32_t db_ = sBb + (uint32_t)(((st_*128 + (tid>>1))*GPITCH + (tid&1)*8)*4); \
        asm volatile("cp.async.cg.shared.global [%0], [%1], 16;" :: "r"(db_),      "l"(bp_)); \
        asm volatile("cp.async.cg.shared.global [%0], [%1], 16;" :: "r"(db_ + 16), "l"(bp_ + 8)); \
        asm volatile("cp.async.commit_group;"); \
    } while(0)

    GLOAD(0); GLOAD(1); GLOAD(2);

    for (int s = 0; s < S; ++s){
        asm volatile("cp.async.wait_group 2;");
        __syncthreads();
        if (s + 3 < S) GLOAD(s + 3);

        const uint32_t Aoff = sAb + (uint32_t)((s & 3) * GA_WORDS * 4);
        const uint32_t Boff = sBb + (uint32_t)((s & 3) * GB_WORDS * 4);

        #pragma unroll
        for (int h = 0; h < 2; ++h){
            uint32_t afr[2][4], bfr[4][2];
            #pragma unroll
            for (int mi=0; mi<2; ++mi){
                uint32_t addr = Aoff + (uint32_t)((((wm + mi*16 + a_row)*GPITCH) + h*8 + a_kh)*4);
                ldsm4(afr[mi], addr);
            }
            #pragma unroll
            for (int nj=0; nj<2; ++nj){
                uint32_t r[4];
                uint32_t addr = Boff + (uint32_t)((((wn + nj*16 + b_row)*GPITCH) + h*8 + b_kh)*4);
                ldsm4(r, addr);
                bfr[nj*2  ][0] = r[0]; bfr[nj*2  ][1] = r[1];
                bfr[nj*2+1][0] = r[2]; bfr[nj*2+1][1] = r[3];
            }
            #pragma unroll
            for (int mi=0; mi<2; ++mi)
                #pragma unroll
                for (int ni=0; ni<4; ++ni)
                    mma_fp16(acc[mi][ni], afr[mi], bfr[ni]);
        }
    }
#undef GLOAD

    #pragma unroll
    for (int mi=0; mi<2; ++mi){
        int m = m0 + wm + mi*16 + gid;
        int tc0 = 0, tc1 = 0;
        if (Wgp){ tc0 = textcol[m*textstride]; tc1 = textcol[(m+8)*textstride]; }
        #pragma unroll
        for (int ni=0; ni<4; ++ni){
            int n = n0 + wn + ni*8 + tig*2;
            float b0 = 0.f, b1 = 0.f;
            if (bias){ b0 = bias[n]; b1 = bias[n+1]; }
            float v00 = acc[mi][ni][0] + b0;
            float v01 = acc[mi][ni][1] + b1;
            float v10 = acc[mi][ni][2] + b0;
            float v11 = acc[mi][ni][3] + b1;
            if (Cadd){
                v00 += Cadd[(size_t)m*ldadd + n];     v01 += Cadd[(size_t)m*ldadd + n+1];
                v10 += Cadd[(size_t)(m+8)*ldadd + n]; v11 += Cadd[(size_t)(m+8)*ldadd + n+1];
            }
            if (Wgp){
                v00 += Wgp[n*NC + tc0];     v01 += Wgp[(n+1)*NC + tc0];
                v10 += Wgp[n*NC + tc1];     v11 += Wgp[(n+1)*NC + tc1];
            }
            if (cout){
                float p00 = __shfl_xor_sync(0xffffffffu, v00, 1);
                float p01 = __shfl_xor_sync(0xffffffffu, v01, 1);
                float p10 = __shfl_xor_sync(0xffffffffu, v10, 1);
                float p11 = __shfl_xor_sync(0xffffffffu, v11, 1);
                if ((tig & 1) == 0){
                    int j = n >> 2;
                    float c2a = fsigm(v01)*cin[(size_t)m*HS + j] + fsigm(v00)*ftanh(p00);
                    cout[(size_t)m*HS + j] = c2a;
                    float ha = fsigm(p01)*ftanh(c2a);
                    hout[(size_t)m*HS + j] = __float2half(ha);
                    float c2b = fsigm(v11)*cin[(size_t)(m+8)*HS + j] + fsigm(v10)*ftanh(p10);
                    cout[(size_t)(m+8)*HS + j] = c2b;
                    float hb = fsigm(p11)*ftanh(c2b);
                    hout[(size_t)(m+8)*HS + j] = __float2half(hb);
                    if (houtf){
                        houtf[(size_t)m*HS + j] = ha;
                        houtf[(size_t)(m+8)*HS + j] = hb;
                    }
                }
            } else {
                C16[(size_t)m*ldc + n]       = __float2half(v00);
                C16[(size_t)m*ldc + n+1]     = __float2half(v01);
                C16[(size_t)(m+8)*ldc + n]   = __float2half(v10);
                C16[(size_t)(m+8)*ldc + n+1] = __float2half(v11);
            }
        }
    }
}

// ---------------- fp32 SIMT GEMM (prologue) ----------------------------------
__global__ void gemm_kernel(
    float* __restrict__ C, int ldc,
    const float* __restrict__ A1, int lda1, const float* __restrict__ W1, int ldw1, int K1,
    const float* __restrict__ bias1,
    const float* __restrict__ Cadd, int ldadd,
    int nn, int M, int N)
{
    __shared__ float As[16][68];
    __shared__ float Bs[16][68];
    int m0 = blockIdx.y * 64;
    int n0 = blockIdx.x * 64;
    int tid = threadIdx.x;
    int tx = tid & 15, ty = tid >> 4;

    float acc[4][4];
    #pragma unroll
    for (int i=0;i<4;i++)
        #pragma unroll
        for (int j=0;j<4;j++) acc[i][j]=0.f;

    for (int k0=0; k0<K1; k0+=16){
        #pragma unroll
        for (int i=0;i<4;i++){
            int e = i*256 + tid;
            int m = e >> 4, kk = e & 15;
            int gm = m0 + m, gk = k0 + kk;
            As[kk][m] = (gm < M && gk < K1) ? A1[(size_t)gm*lda1 + gk] : 0.f;
        }
        if (nn){
            #pragma unroll
            for (int i=0;i<4;i++){
                int e = i*256 + tid;
                int kk = e >> 6, n = e & 63;
                int gn = n0 + n, gk = k0 + kk;
                Bs[kk][n] = (gn < N && gk < K1) ? W1[(size_t)gk*ldw1 + gn] : 0.f;
            }
        } else {
            #pragma unroll
            for (int i=0;i<4;i++){
                int e = i*256 + tid;
                int n = e >> 4, kk = e & 15;
                int gn = n0 + n, gk = k0 + kk;
                Bs[kk][n] = (gn < N && gk < K1) ? W1[(size_t)gn*ldw1 + gk] : 0.f;
            }
        }
        __syncthreads();
        #pragma unroll
        for (int kk=0; kk<16; kk++){
            float4 a = *(const float4*)&As[kk][ty*4];
            float4 b = *(const float4*)&Bs[kk][tx*4];
            acc[0][0]+=a.x*b.x; acc[0][1]+=a.x*b.y; acc[0][2]+=a.x*b.z; acc[0][3]+=a.x*b.w;
            acc[1][0]+=a.y*b.x; acc[1][1]+=a.y*b.y; acc[1][2]+=a.y*b.z; acc[1][3]+=a.y*b.w;
            acc[2][0]+=a.z*b.x; acc[2][1]+=a.z*b.y; acc[2][2]+=a.z*b.z; acc[2][3]+=a.z*b.w;
            acc[3][0]+=a.w*b.x; acc[3][1]+=a.w*b.y; acc[3][2]+=a.w*b.z; acc[3][3]+=a.w*b.w;
        }
        __syncthreads();
    }

    #pragma unroll
    for (int i=0;i<4;i++){
        int m = m0 + ty*4 + i;
        if (m >= M) continue;
        #pragma unroll
        for (int j=0;j<4;j++){
            int n = n0 + tx*4 + j;
            if (n >= N) continue;
            float v = acc[i][j];
            if (bias1) v += bias1[n];
            if (Cadd)  v += Cadd[(size_t)m*ldadd + n];
            C[(size_t)m*ldc + n] = v;
        }
    }
}

// ---------------- generator GEMM (fp32 A from hist32), remapped output -------
__global__ void gen_kernel(
    float* __restrict__ C,
    const float* __restrict__ A1, const float* __restrict__ W1,
    const float* __restrict__ bias1, int M, int N)
{
    __shared__ float As[16][68];
    __shared__ float Bs[16][68];
    int m0 = blockIdx.y * 64;
    int tid = threadIdx.x;
    int tx = tid & 15, ty = tid >> 4;

    float acc[4][4];
    #pragma unroll
    for (int i=0;i<4;i++)
        #pragma unroll
        for (int j=0;j<4;j++) acc[i][j]=0.f;

    for (int k0=0; k0<HS; k0+=16){
        #pragma unroll
        for (int i=0;i<4;i++){
            int e = i*256 + tid;
            int m = e >> 4, kk = e & 15;
            int gm = m0 + m, gk = k0 + kk;
            As[kk][m] = (gm < M) ? A1[(size_t)gm*HS + gk] : 0.f;
        }
        #pragma unroll
        for (int i=0;i<4;i++){
            int e = i*256 + tid;
            int n = e >> 4, kk = e & 15;
            int gk = k0 + kk;
            Bs[kk][n] = (n < N) ? W1[(size_t)n*HS + gk] : 0.f;
        }
        __syncthreads();
        #pragma unroll
        for (int kk=0; kk<16; kk++){
            float4 a = *(const float4*)&As[kk][ty*4];
            float4 b = *(const float4*)&Bs[kk][tx*4];
            acc[0][0]+=a.x*b.x; acc[0][1]+=a.x*b.y; acc[0][2]+=a.x*b.z; acc[0][3]+=a.x*b.w;
            acc[1][0]+=a.y*b.x; acc[1][1]+=a.y*b.y; acc[1][2]+=a.y*b.z; acc[1][3]+=a.y*b.w;
            acc[2][0]+=a.z*b.x; acc[2][1]+=a.z*b.y; acc[2][2]+=a.z*b.z; acc[2][3]+=a.z*b.w;
            acc[3][0]+=a.w*b.x; acc[3][1]+=a.w*b.y; acc[3][2]+=a.w*b.z; acc[3][3]+=a.w*b.w;
        }
        __syncthreads();
    }

    #pragma unroll
    for (int i=0;i<4;i++){
        int m = m0 + ty*4 + i;
        if (m >= M) continue;
        int t = m >> 8, b = m & 255;
        #pragma unroll
        for (int j=0;j<4;j++){
            int n = tx*4 + j;
            if (n >= N) continue;
            C[(size_t)(b*TT + t)*NC + n] = acc[i][j] + bias1[n];
        }
    }
}

// ---------------- mean over T of batch_H ------------------------------------
__global__ void mean_kernel(const float* __restrict__ bH, float* __restrict__ out)
{
    int idx = blockIdx.x*256 + threadIdx.x;
    if (idx >= BB*INSZ) return;
    int b = idx >> 9, k = idx & 511;
    const float* p = bH + (size_t)b*TT*INSZ + k;
    float s = 0.f;
    #pragma unroll
    for (int t=0;t<TT;t++) s += p[t*INSZ];
    out[idx] = s * (1.0f/26.0f);
}

// ---------------- init h0/c0 -------------------------------------------------
__global__ void init_kernel(const float* __restrict__ hh, const float* __restrict__ hc,
                            __half* __restrict__ h1, __half* __restrict__ h2,
                            float* __restrict__ c1, float* __restrict__ c2)
{
    int idx = blockIdx.x*256 + threadIdx.x;
    if (idx >= BB*HS) return;
    float h0 = 0.5f*(hh[idx] + hh[BB*HS + idx]);
    float c0 = 0.5f*(hc[idx] + hc[BB*HS + idx]);
    h1[idx] = __float2half(h0); h2[idx] = __float2half(h0);
    c1[idx]=c0; c2[idx]=c0;
}

// ---------------- attention: 1024 threads, 4 threads/position ----------------
__global__ void __launch_bounds__(1024) attn_kernel(
    const __half* __restrict__ fmh, const __half* __restrict__ q,
    const float* __restrict__ ws, const float* __restrict__ sb,
    __half* __restrict__ ctx)
{
    __shared__ float qs[CH];
    __shared__ float wss[CH];
    __shared__ float epart[1024];
    __shared__ float red[256];
    __shared__ float alpha[256];

    int b = blockIdx.x;
    int tid = threadIdx.x;
    int p = tid & 255;
    int q4 = tid >> 8;          // 0..3: channel quarter
    const __half* f = fmh + (size_t)b * CH * PP;

    if (tid < 512){
        qs[tid]  = __half2float(q[b*HS + tid]);
        wss[tid] = ws[tid];
    }
    __syncthreads();

    {
        int c0 = q4 * 128;
        float a0=0.f, a1=0.f, a2=0.f, a3=0.f;
        #pragma unroll 2
        for (int c=c0; c<c0+128; c+=4){
            float f0 = __half2float(f[(c  )*PP + p]);
            float f1 = __half2float(f[(c+1)*PP + p]);
            float f2 = __half2float(f[(c+2)*PP + p]);
            float f3 = __half2float(f[(c+3)*PP + p]);
            a0 += ftanh_hw(f0 + qs[c  ]) * wss[c  ];
            a1 += ftanh_hw(f1 + qs[c+1]) * wss[c+1];
            a2 += ftanh_hw(f2 + qs[c+2]) * wss[c+2];
            a3 += ftanh_hw(f3 + qs[c+3]) * wss[c+3];
        }
        epart[tid] = (a0+a1) + (a2+a3);
    }
    __syncthreads();

    float e = 0.f;
    if (tid < 256){
        e = (epart[tid] + epart[tid + 256]) + (epart[tid + 512] + epart[tid + 768]) + sb[0];
        red[tid] = e;
    }
    __syncthreads();
    #pragma unroll
    for (int s=128; s>0; s>>=1){
        if (tid < s) red[tid] = fmaxf(red[tid], red[tid+s]);
        __syncthreads();
    }
    float mx = red[0];
    __syncthreads();
    float ex = 0.f;
    if (tid < 256){
        ex = fexp(e - mx);
        red[tid] = ex;
    }
    __syncthreads();
    #pragma unroll
    for (int s=128; s>0; s>>=1){
        if (tid < s) red[tid] += red[tid+s];
        __syncthreads();
    }
    float sum = red[0];
    __syncthreads();
    if (tid < 256) alpha[tid] = ex * frcp(sum);
    __syncthreads();

    int lane = tid & 31, wid = tid >> 5;     // 32 warps
    for (int c = wid; c < CH; c += 32){
        const __half* fr = f + c*PP;
        float s = 0.f;
        #pragma unroll
        for (int pp = lane; pp < PP; pp += 32) s += alpha[pp] * __half2float(fr[pp]);
        #pragma unroll
        for (int o=16; o>0; o>>=1) s += __shfl_down_sync(0xffffffffu, s, o);
        if (lane == 0) ctx[b*HS + c] = __float2half(s);
    }
}

// ---------------- host orchestration ----------------------------------------
extern "C" void kernel_launch(void* const* d_in, const int* in_sizes, int n_in,
                              void* d_out, int out_size)
{
    const float* feature_map = (const float*)d_in[0];
    const float* batch_H     = (const float*)d_in[1];
    const float* hidden_h    = (const float*)d_in[2];
    const float* hidden_c    = (const float*)d_in[3];
    const int*   text        = (const int*)  d_in[4];
    const float* i2h_w       = (const float*)d_in[5];
    const float* h2h_w       = (const float*)d_in[6];
    const float* h2h_b       = (const float*)d_in[7];
    const float* conv_m2h_w  = (const float*)d_in[8];
    const float* conv_m2h_b  = (const float*)d_in[9];
    const float* conv_h2h_w  = (const float*)d_in[10];
    const float* conv_h2h_b  = (const float*)d_in[11];
    const float* score_w     = (const float*)d_in[12];
    const float* score_b     = (const float*)d_in[13];
    const float* rnn1_w_ih   = (const float*)d_in[14];
    const float* rnn1_w_hh   = (const float*)d_in[15];
    const float* rnn1_b_ih   = (const float*)d_in[16];
    const float* rnn1_b_hh   = (const float*)d_in[17];
    const float* hlin_w      = (const float*)d_in[18];
    const float* hlin_b      = (const float*)d_in[19];
    const float* rnn2_w_ih   = (const float*)d_in[20];
    const float* rnn2_w_hh   = (const float*)d_in[21];
    const float* rnn2_b_ih   = (const float*)d_in[22];
    const float* rnn2_b_hh   = (const float*)d_in[23];
    const float* gen_w       = (const float*)d_in[24];
    const float* gen_b       = (const float*)d_in[25];
    float* out = (float*)d_out;

    __half *aP,*bhT,*fmh,*Wq16,*hlinT16,*w2ihraw16,*W2pp16;
    __half *w1ih16,*w1hh16,*w2ih16,*w2hh16;
    __half *h1a16,*h1b16,*h2a16,*h2b16,*q16,*ctx16;
    float *meanH,*bhproj,*Wq,*qb,*badd,*bias1p,*bias2p,*wgp,*hist32;
    float *c1a,*c1b,*c2a,*c2b;
    cudaGetSymbolAddress((void**)&aP,  g_aP);
    cudaGetSymbolAddress((void**)&bhT, g_bhT);
    cudaGetSymbolAddress((void**)&fmh, g_fmh);
    cudaGetSymbolAddress((void**)&meanH, g_meanH);
    cudaGetSymbolAddress((void**)&bhproj,g_bhproj);
    cudaGetSymbolAddress((void**)&Wq,    g_Wq);
    cudaGetSymbolAddress((void**)&qb,    g_qb);
    cudaGetSymbolAddress((void**)&badd,  g_badd);
    cudaGetSymbolAddress((void**)&Wq16,  g_Wq16);
    cudaGetSymbolAddress((void**)&hlinT16, g_hlinT16);
    cudaGetSymbolAddress((void**)&w2ihraw16, g_w2ihraw16);
    cudaGetSymbolAddress((void**)&W2pp16, g_W2pp16);
    cudaGetSymbolAddress((void**)&w1ih16,g_w1ih16);
    cudaGetSymbolAddress((void**)&w1hh16,g_w1hh16);
    cudaGetSymbolAddress((void**)&w2ih16,g_w2ih16);
    cudaGetSymbolAddress((void**)&w2hh16,g_w2hh16);
    cudaGetSymbolAddress((void**)&bias1p,g_bias1p);
    cudaGetSymbolAddress((void**)&bias2p,g_bias2p);
    cudaGetSymbolAddress((void**)&wgp,   g_wgp);
    cudaGetSymbolAddress((void**)&h1a16, g_h1a16);
    cudaGetSymbolAddress((void**)&h1b16, g_h1b16);
    cudaGetSymbolAddress((void**)&h2a16, g_h2a16);
    cudaGetSymbolAddress((void**)&h2b16, g_h2b16);
    cudaGetSymbolAddress((void**)&c1a, g_c1a); cudaGetSymbolAddress((void**)&c1b, g_c1b);
    cudaGetSymbolAddress((void**)&c2a, g_c2a); cudaGetSymbolAddress((void**)&c2b, g_c2b);
    cudaGetSymbolAddress((void**)&hist32, g_hist32);
    cudaGetSymbolAddress((void**)&q16,  g_q16);
    cudaGetSymbolAddress((void**)&ctx16,g_ctx16);

    const int CONV_SMEM = 2 * 4 * 128 * CPITCH * 4;   // 81920
    cudaFuncSetAttribute(conv_fp16_kernel, cudaFuncAttributeMaxDynamicSharedMemorySize, CONV_SMEM);
    const int G16_SMEM = 4 * (GA_WORDS + GB_WORDS) * 4;  // 61440
    cudaFuncSetAttribute(gemm16_kernel, cudaFuncAttributeMaxDynamicSharedMemorySize, G16_SMEM);

    // ---- conv prep + conv ----
    padT_kernel<<<256*10*16, 256>>>(feature_map, aP);
    wT_kernel<<<(9*CH*CH+255)/256, 256>>>(conv_m2h_w, bhT);
    conv_fp16_kernel<<<dim3(4,2,BB), 256, CONV_SMEM>>>(aP, bhT, conv_m2h_b, fmh);

    // ---- weight packing ----
    wpack16_kernel<<<(4*HS*512+255)/256,256>>>(rnn1_w_ih, INSZ+NC, w1ih16);
    wpack16_kernel<<<(4*HS*512+255)/256,256>>>(rnn1_w_hh, HS, w1hh16);
    wpack16_kernel<<<(4*HS*512+255)/256,256>>>(rnn2_w_hh, HS, w2hh16);
    bpack_kernel<<<(4*HS+255)/256,256>>>(rnn1_b_ih, rnn1_b_hh, nullptr, bias1p);
    wgpack_kernel<<<(4*HS*NC+255)/256,256>>>(rnn1_w_ih, wgp);
    cast16_kernel<<<(4*HS*HS+255)/256,256>>>(rnn2_w_ih, w2ihraw16, 4*HS*HS);
    transposeT16_kernel<<<256,256>>>(hlin_w, hlinT16);
    gemm16_kernel<<<dim3(4,32),256,G16_SMEM>>>(W2pp16, HS,
        w2ihraw16, hlinT16, HS, nullptr, nullptr, 0,
        nullptr, nullptr, 0, nullptr, nullptr, 0,
        nullptr, nullptr, nullptr, nullptr);
    wpack16h_kernel<<<(4*HS*512+255)/256,256>>>(W2pp16, w2ih16);
    badd_kernel<<<(4*HS+255)/256,256>>>(rnn2_w_ih, hlin_b, badd);
    bpack_kernel<<<(4*HS+255)/256,256>>>(rnn2_b_ih, rnn2_b_hh, badd, bias2p);

    // ---- prologue (fp32) ----
    mean_kernel<<<512,256>>>(batch_H, meanH);
    gemm_kernel<<<dim3(8,4),256>>>(bhproj, HS, meanH, INSZ, i2h_w, INSZ, INSZ,
                                   h2h_b, nullptr,0, 0, BB, HS);
    gemm_kernel<<<dim3(8,8),256>>>(Wq, HS, conv_h2h_w, HS, h2h_w, HS, HS,
                                   nullptr, nullptr,0, 1, HS, HS);
    cast16_kernel<<<(HS*HS+255)/256,256>>>(Wq, Wq16, HS*HS);
    gemm_kernel<<<dim3(8,4),256>>>(qb, HS, bhproj, HS, conv_h2h_w, HS, HS,
                                   conv_h2h_b, nullptr,0, 0, BB, HS);
    init_kernel<<<512,256>>>(hidden_h, hidden_c, h1a16, h2a16, c1a, c2a);

    __half *h1c16=h1a16, *h1n16=h1b16, *h2c16=h2a16, *h2n16=h2b16;
    float *c1c=c1a, *c1n=c1b, *c2c=c2a, *c2n=c2b;

    for (int t=0; t<TT; t++){
        // q = qb + h2 @ Wq^T  (fp16 out)
        gemm16_kernel<<<dim3(4,4),256,G16_SMEM>>>(q16, HS,
            h2c16, Wq16, HS, nullptr, nullptr, 0,
            nullptr, qb, HS, nullptr, nullptr, 0,
            nullptr, nullptr, nullptr, nullptr);
        // attention -> ctx (fp16), 1024 threads/block
        attn_kernel<<<BB,1024>>>(fmh, q16, score_w, score_b, ctx16);
        // gates1 + fused LSTM1
        gemm16_kernel<<<dim3(16,4),256,G16_SMEM>>>(nullptr, 0,
            ctx16, w1ih16, HS, h1c16, w1hh16, HS,
            bias1p, nullptr, 0, wgp, text + t, TT,
            c1c, c1n, h1n16, nullptr);
        // gates2 + fused LSTM2 (hlin folded); h2 -> fp16 state + fp32 hist
        gemm16_kernel<<<dim3(16,4),256,G16_SMEM>>>(nullptr, 0,
            h1n16, w2ih16, HS, h2c16, w2hh16, HS,
            bias2p, nullptr, 0, nullptr, nullptr, 0,
            c2c, c2n, h2n16, hist32 + (size_t)t*BB*HS);

        __half* tph;
        tph=h1c16; h1c16=h1n16; h1n16=tph;
        tph=h2c16; h2c16=h2n16; h2n16=tph;
        float* tp;
        tp=c1c; c1c=c1n; c1n=tp;
        tp=c2c; c2c=c2n; c2n=tp;
    }

    // probs: one batched GEMM over all timesteps (fp32 hist), remap [b][t][n]
    gen_kernel<<<dim3(1,104),256>>>(out, hist32, gen_w, gen_b, TT*BB, NC);
}